// round 1
// baseline (speedup 1.0000x reference)
#include <cuda_runtime.h>

// Problem: SJCSNN spiking CNN forward, T=8, B=32, out [32,7] f32.
// Inputs (all f32, metadata order):
//  0 x[32,1,48,48] 1 conv1_w[128,1,3,3] 2 conv1_b[128] 3-6 bn1 g/b/m/v[128]
//  7 conv2_w[128,128,3,3] 8 conv2_b[128] 9-12 bn2 g/b/m/v[128]
//  13 fc1_w[1152,18432] 14 fc1_b[1152] 15 fc2_w[128,1152] 16 fc2_b[128]
//  17 fc3_w[7,128] 18 fc3_b[7]

#define NTB 256  // T*B

// ---- scratch (device globals; no allocations) ----
__device__ float g_h[32 * 128 * 48 * 48];        // conv1+bn1 output
__device__ float g_p1[NTB * 128 * 26 * 26];      // IF1+pool spikes, PADDED 26x26
__device__ float g_c2[NTB * 128 * 24 * 24];      // conv2+bn2 output
__device__ float g_f[NTB * 18432];               // IF2+pool spikes, flattened
__device__ float g_y1p[4 * NTB * 1152];          // fc1 split-K partials
__device__ float g_l1[NTB * 1152];               // LIF1 spikes
__device__ float g_y2[NTB * 128];                // fc2 output
__device__ float g_l2[NTB * 128];                // LIF2 spikes

// ---------------- K1: conv1 (1->128, 3x3 SAME) + BN1 ----------------
// one block per (b, c); x plane cached in smem (padded 50x50)
__global__ __launch_bounds__(256) void k1_conv1bn(
    const float* __restrict__ x, const float* __restrict__ w,
    const float* __restrict__ cb, const float* __restrict__ bg,
    const float* __restrict__ bb, const float* __restrict__ bm,
    const float* __restrict__ bv)
{
    __shared__ float s[2500];  // 50*50 padded
    int b = blockIdx.x >> 7, c = blockIdx.x & 127;
    int tid = threadIdx.x;
    for (int i = tid; i < 2500; i += 256) s[i] = 0.0f;
    __syncthreads();
    const float* xp = x + b * 2304;
    for (int i = tid; i < 2304; i += 256) {
        int r = i / 48, q = i - r * 48;
        s[(r + 1) * 50 + q + 1] = xp[i];
    }
    __syncthreads();
    float wr[9];
#pragma unroll
    for (int k = 0; k < 9; k++) wr[k] = w[c * 9 + k];
    float sc = bg[c] * rsqrtf(bv[c] + 1e-5f);
    float sh = (cb[c] - bm[c]) * sc + bb[c];
    float* hp = g_h + (b * 128 + c) * 2304;
    for (int p = tid; p < 2304; p += 256) {
        int y = p / 48, xx = p - y * 48;
        const float* sp = s + y * 50 + xx;
        float a = sp[0] * wr[0] + sp[1] * wr[1] + sp[2] * wr[2]
                + sp[50] * wr[3] + sp[51] * wr[4] + sp[52] * wr[5]
                + sp[100] * wr[6] + sp[101] * wr[7] + sp[102] * wr[8];
        hp[p] = a * sc + sh;
    }
}

// ---------------- K2: IF1 (constant input per t) + 2x2 maxpool ----------------
// thread per (b,c,oy,ox) of the 24x24 pooled grid; writes padded p1 for all T
__global__ __launch_bounds__(256) void k2_if_pool()
{
    int idx = blockIdx.x * 256 + threadIdx.x;  // 2,359,296 exact
    int ox = idx % 24;
    int t1 = idx / 24;
    int oy = t1 % 24;
    int t2 = t1 / 24;
    int c = t2 & 127;
    int b = t2 >> 7;
    const float* hp = g_h + (b * 128 + c) * 2304 + (2 * oy) * 48 + 2 * ox;
    float h0 = hp[0], h1 = hp[1], h2 = hp[48], h3 = hp[49];
    float v0 = 0.f, v1 = 0.f, v2 = 0.f, v3 = 0.f;
    int pin = c * 676 + (oy + 1) * 26 + ox + 1;
#pragma unroll
    for (int t = 0; t < 8; t++) {
        v0 += h0; v1 += h1; v2 += h2; v3 += h3;
        float s0 = v0 >= 1.f ? 1.f : 0.f; v0 = v0 >= 1.f ? 0.f : v0;
        float s1 = v1 >= 1.f ? 1.f : 0.f; v1 = v1 >= 1.f ? 0.f : v1;
        float s2 = v2 >= 1.f ? 1.f : 0.f; v2 = v2 >= 1.f ? 0.f : v2;
        float s3 = v3 >= 1.f ? 1.f : 0.f; v3 = v3 >= 1.f ? 0.f : v3;
        float mx = fmaxf(fmaxf(s0, s1), fmaxf(s2, s3));
        g_p1[(t * 32 + b) * 128 * 676 + pin] = mx;
    }
}

// ---------------- K3: conv2 (128->128, 3x3 SAME on 24x24) + BN2 ----------------
// block = (image n, group of 8 couts); weights for 8 couts (9216 f) in smem,
// one input-channel padded plane (676 f) staged per cin iteration.
__global__ __launch_bounds__(192) void k3_conv2bn(
    const float* __restrict__ w2, const float* __restrict__ cb,
    const float* __restrict__ bg, const float* __restrict__ bb,
    const float* __restrict__ bm, const float* __restrict__ bv)
{
    __shared__ float ws[9216];    // 8 couts x 128 cin x 9
    __shared__ float plane[676];  // 26x26 padded input plane
    int n = blockIdx.x >> 4;
    int gi = blockIdx.x & 15;
    int cob = gi * 8;
    int tid = threadIdx.x;  // 192 threads, 3 pixels each (576 total)
    for (int i = tid; i < 9216; i += 192) ws[i] = w2[cob * 1152 + i];
    int p0 = tid, p1i = tid + 192, p2i = tid + 384;
    int o0 = (p0 / 24) * 26 + (p0 % 24);
    int o1 = (p1i / 24) * 26 + (p1i % 24);
    int o2 = (p2i / 24) * 26 + (p2i % 24);
    float acc[24];
#pragma unroll
    for (int i = 0; i < 24; i++) acc[i] = 0.f;
    const float* base = g_p1 + n * 128 * 676;
    for (int ci = 0; ci < 128; ci++) {
        __syncthreads();
        const float* src = base + ci * 676;
        for (int i = tid; i < 676; i += 192) plane[i] = src[i];
        __syncthreads();
        float in0[9], in1[9], in2[9];
#pragma unroll
        for (int ky = 0; ky < 3; ky++)
#pragma unroll
            for (int kx = 0; kx < 3; kx++) {
                int off = ky * 26 + kx, k = ky * 3 + kx;
                in0[k] = plane[o0 + off];
                in1[k] = plane[o1 + off];
                in2[k] = plane[o2 + off];
            }
        const float* wc = ws + ci * 9;
#pragma unroll
        for (int co = 0; co < 8; co++) {
            const float* wp = wc + co * 1152;
            float a0 = acc[co * 3], a1 = acc[co * 3 + 1], a2 = acc[co * 3 + 2];
#pragma unroll
            for (int k = 0; k < 9; k++) {
                float wv = wp[k];
                a0 += in0[k] * wv;
                a1 += in1[k] * wv;
                a2 += in2[k] * wv;
            }
            acc[co * 3] = a0; acc[co * 3 + 1] = a1; acc[co * 3 + 2] = a2;
        }
    }
#pragma unroll
    for (int co = 0; co < 8; co++) {
        int oc = cob + co;
        float sc = bg[oc] * rsqrtf(bv[oc] + 1e-5f);
        float sh = (cb[oc] - bm[oc]) * sc + bb[oc];
        float* op = g_c2 + (n * 128 + oc) * 576;
        op[p0] = acc[co * 3] * sc + sh;
        op[p1i] = acc[co * 3 + 1] * sc + sh;
        op[p2i] = acc[co * 3 + 2] * sc + sh;
    }
}

// ---------------- K4: IF2 + 2x2 maxpool + flatten ----------------
__global__ __launch_bounds__(256) void k4_if2_pool()
{
    int idx = blockIdx.x * 256 + threadIdx.x;  // 589,824 exact
    int ox = idx % 12;
    int t1 = idx / 12;
    int oy = t1 % 12;
    int t2 = t1 / 12;
    int c = t2 & 127;
    int b = t2 >> 7;
    float v0 = 0.f, v1 = 0.f, v2 = 0.f, v3 = 0.f;
    int fo = c * 144 + oy * 12 + ox;
#pragma unroll
    for (int t = 0; t < 8; t++) {
        const float* cp = g_c2 + ((t * 32 + b) * 128 + c) * 576 + (2 * oy) * 24 + 2 * ox;
        v0 += cp[0]; v1 += cp[1]; v2 += cp[24]; v3 += cp[25];
        float s0 = v0 >= 1.f ? 1.f : 0.f; v0 = v0 >= 1.f ? 0.f : v0;
        float s1 = v1 >= 1.f ? 1.f : 0.f; v1 = v1 >= 1.f ? 0.f : v1;
        float s2 = v2 >= 1.f ? 1.f : 0.f; v2 = v2 >= 1.f ? 0.f : v2;
        float s3 = v3 >= 1.f ? 1.f : 0.f; v3 = v3 >= 1.f ? 0.f : v3;
        g_f[(t * 32 + b) * 18432 + fo] = fmaxf(fmaxf(s0, s1), fmaxf(s2, s3));
    }
}

// ---------------- K5: fc1 GEMM, split-K=4 ----------------
// C[256,1152] = F[256,18432] * W1[1152,18432]^T ; BM=BN=64, BK=16, 4x4 microtile
__global__ __launch_bounds__(256) void k5_fc1(const float* __restrict__ w1)
{
    __shared__ float As[16][65];
    __shared__ float Bs[16][65];
    int tid = threadIdx.x;
    int tx = tid & 15, ty = tid >> 4;
    int m0 = blockIdx.y * 64, n0 = blockIdx.x * 64;
    int kbase = blockIdx.z * 4608;
    float acc[4][4] = {};
    int lrow = tid >> 2;
    int lk = (tid & 3) * 4;
    const float* aptr = g_f + (m0 + lrow) * 18432 + kbase + lk;
    const float* bptr = w1 + (n0 + lrow) * 18432 + kbase + lk;
    for (int kt = 0; kt < 288; kt++) {
        float4 av = *(const float4*)aptr;
        float4 bv = *(const float4*)bptr;
        __syncthreads();
        As[lk + 0][lrow] = av.x; As[lk + 1][lrow] = av.y;
        As[lk + 2][lrow] = av.z; As[lk + 3][lrow] = av.w;
        Bs[lk + 0][lrow] = bv.x; Bs[lk + 1][lrow] = bv.y;
        Bs[lk + 2][lrow] = bv.z; Bs[lk + 3][lrow] = bv.w;
        __syncthreads();
#pragma unroll
        for (int kk = 0; kk < 16; kk++) {
            float ar[4], br[4];
#pragma unroll
            for (int i = 0; i < 4; i++) ar[i] = As[kk][ty + 16 * i];
#pragma unroll
            for (int j = 0; j < 4; j++) br[j] = Bs[kk][tx + 16 * j];
#pragma unroll
            for (int i = 0; i < 4; i++)
#pragma unroll
                for (int j = 0; j < 4; j++) acc[i][j] += ar[i] * br[j];
        }
        aptr += 16; bptr += 16;
    }
    float* op = g_y1p + blockIdx.z * 294912;
#pragma unroll
    for (int i = 0; i < 4; i++)
#pragma unroll
        for (int j = 0; j < 4; j++)
            op[(m0 + ty + 16 * i) * 1152 + n0 + tx + 16 * j] = acc[i][j];
}

// ---------------- K6: reduce split-K + bias + LIF1 ----------------
__global__ __launch_bounds__(256) void k6_lif1(const float* __restrict__ bias)
{
    int idx = blockIdx.x * 256 + threadIdx.x;  // 36,864 exact
    int o = idx % 1152, b = idx / 1152;
    float bi = bias[o];
    float v = 0.f;
#pragma unroll
    for (int t = 0; t < 8; t++) {
        int row = (t * 32 + b) * 1152 + o;
        float xx = g_y1p[row] + g_y1p[294912 + row] + g_y1p[2 * 294912 + row]
                 + g_y1p[3 * 294912 + row] + bi;
        v += (xx - v) * 0.5f;
        float s = v >= 1.f ? 1.f : 0.f;
        g_l1[row] = s;
        v = v >= 1.f ? 0.f : v;
    }
}

// ---------------- K7: fc2 (row-per-block matvec) ----------------
__global__ __launch_bounds__(128) void k7_fc2(const float* __restrict__ w,
                                              const float* __restrict__ bias)
{
    __shared__ float row[1152];
    int r = blockIdx.x, o = threadIdx.x;
    for (int i = o; i < 1152; i += 128) row[i] = g_l1[r * 1152 + i];
    __syncthreads();
    const float4* wp = (const float4*)(w + o * 1152);
    float acc = 0.f;
#pragma unroll 4
    for (int k = 0; k < 288; k++) {
        float4 wv = wp[k];
        acc += row[4 * k] * wv.x + row[4 * k + 1] * wv.y
             + row[4 * k + 2] * wv.z + row[4 * k + 3] * wv.w;
    }
    g_y2[r * 128 + o] = acc + bias[o];
}

// ---------------- K8: LIF2 ----------------
__global__ __launch_bounds__(256) void k8_lif2()
{
    int idx = blockIdx.x * 256 + threadIdx.x;  // 4096 exact
    int o = idx & 127, b = idx >> 7;
    float v = 0.f;
#pragma unroll
    for (int t = 0; t < 8; t++) {
        int row = (t * 32 + b) * 128 + o;
        float xx = g_y2[row];
        v += (xx - v) * 0.5f;
        float s = v >= 1.f ? 1.f : 0.f;
        g_l2[row] = s;
        v = v >= 1.f ? 0.f : v;
    }
}

// ---------------- K9: fc3 + LIF3 + mean over T ----------------
__global__ __launch_bounds__(256) void k9_fc3(const float* __restrict__ w,
                                              const float* __restrict__ bias,
                                              float* __restrict__ out)
{
    int idx = threadIdx.x;
    if (idx >= 224) return;
    int o = idx % 7, b = idx / 7;
    const float4* wp = (const float4*)(w + o * 128);
    float v = 0.f, accm = 0.f;
    float bi = bias[o];
    for (int t = 0; t < 8; t++) {
        const float4* lp = (const float4*)(g_l2 + (t * 32 + b) * 128);
        float y = 0.f;
#pragma unroll
        for (int k = 0; k < 32; k++) {
            float4 a = lp[k], ww = wp[k];
            y += a.x * ww.x + a.y * ww.y + a.z * ww.z + a.w * ww.w;
        }
        y += bi;
        v += (y - v) * 0.5f;
        float s = v >= 1.f ? 1.f : 0.f;
        accm += s;
        v = v >= 1.f ? 0.f : v;
    }
    out[b * 7 + o] = accm * 0.125f;
}

// ---------------- launch ----------------
extern "C" void kernel_launch(void* const* d_in, const int* in_sizes, int n_in,
                              void* d_out, int out_size)
{
    const float* x       = (const float*)d_in[0];
    const float* conv1_w = (const float*)d_in[1];
    const float* conv1_b = (const float*)d_in[2];
    const float* bn1_g   = (const float*)d_in[3];
    const float* bn1_b   = (const float*)d_in[4];
    const float* bn1_m   = (const float*)d_in[5];
    const float* bn1_v   = (const float*)d_in[6];
    const float* conv2_w = (const float*)d_in[7];
    const float* conv2_b = (const float*)d_in[8];
    const float* bn2_g   = (const float*)d_in[9];
    const float* bn2_b   = (const float*)d_in[10];
    const float* bn2_m   = (const float*)d_in[11];
    const float* bn2_v   = (const float*)d_in[12];
    const float* fc1_w   = (const float*)d_in[13];
    const float* fc1_b   = (const float*)d_in[14];
    const float* fc2_w   = (const float*)d_in[15];
    const float* fc2_b   = (const float*)d_in[16];
    const float* fc3_w   = (const float*)d_in[17];
    const float* fc3_b   = (const float*)d_in[18];

    // zero padded p1 borders (interior overwritten by K2)
    void* p1ptr = nullptr;
    cudaGetSymbolAddress(&p1ptr, g_p1);
    cudaMemsetAsync(p1ptr, 0, sizeof(g_p1));

    k1_conv1bn<<<32 * 128, 256>>>(x, conv1_w, conv1_b, bn1_g, bn1_b, bn1_m, bn1_v);
    k2_if_pool<<<9216, 256>>>();
    k3_conv2bn<<<NTB * 16, 192>>>(conv2_w, conv2_b, bn2_g, bn2_b, bn2_m, bn2_v);
    k4_if2_pool<<<2304, 256>>>();
    dim3 g5(18, 4, 4);
    k5_fc1<<<g5, 256>>>(fc1_w);
    k6_lif1<<<144, 256>>>(fc1_b);
    k7_fc2<<<NTB, 128>>>(fc2_w, fc2_b);
    k8_lif2<<<16, 256>>>();
    k9_fc3<<<1, 256>>>(fc3_w, fc3_b, (float*)d_out);
}

// round 2
// speedup vs baseline: 1.5774x; 1.5774x over previous
#include <cuda_runtime.h>
#include <cstdint>

// Problem: SJCSNN spiking CNN forward, T=8, B=32, out [32,7] f32.
// conv2 now runs on the tensor pipe: tf32 mma.sync with 2-term weight split
// (activations are binary spikes -> exact in tf32; weight residual ~2^-21).

#define NTB 256  // T*B

// ---- scratch (device globals; no allocations) ----
__device__ float g_h[32 * 128 * 48 * 48];        // conv1+bn1 output
__device__ float g_p1[NTB * 128 * 26 * 26];      // IF1+pool spikes, PADDED 26x26
__device__ float g_c2[NTB * 128 * 24 * 24];      // conv2+bn2 output
__device__ float g_f[NTB * 18432];               // IF2+pool spikes, flattened
__device__ float g_y1p[4 * NTB * 1152];          // fc1 split-K partials
__device__ float g_l1[NTB * 1152];               // LIF1 spikes
__device__ float g_y2[NTB * 128];                // fc2 output
__device__ float g_l2[NTB * 128];                // LIF2 spikes

// ---------------- tf32 mma helpers ----------------
__device__ __forceinline__ uint32_t f2tf32(float f) {
    uint32_t r;
    asm("cvt.rna.tf32.f32 %0, %1;" : "=r"(r) : "f"(f));
    return r;
}
__device__ __forceinline__ void mma_tf32(float c[4], const uint32_t a[4],
                                         uint32_t b0, uint32_t b1) {
    asm volatile(
        "mma.sync.aligned.m16n8k8.row.col.f32.tf32.tf32.f32 "
        "{%0,%1,%2,%3}, {%4,%5,%6,%7}, {%8,%9}, {%0,%1,%2,%3};"
        : "+f"(c[0]), "+f"(c[1]), "+f"(c[2]), "+f"(c[3])
        : "r"(a[0]), "r"(a[1]), "r"(a[2]), "r"(a[3]), "r"(b0), "r"(b1));
}

// ---------------- K1: conv1 (1->128, 3x3 SAME) + BN1 ----------------
__global__ __launch_bounds__(256) void k1_conv1bn(
    const float* __restrict__ x, const float* __restrict__ w,
    const float* __restrict__ cb, const float* __restrict__ bg,
    const float* __restrict__ bb, const float* __restrict__ bm,
    const float* __restrict__ bv)
{
    __shared__ float s[2500];  // 50*50 padded
    int b = blockIdx.x >> 7, c = blockIdx.x & 127;
    int tid = threadIdx.x;
    for (int i = tid; i < 2500; i += 256) s[i] = 0.0f;
    __syncthreads();
    const float* xp = x + b * 2304;
    for (int i = tid; i < 2304; i += 256) {
        int r = i / 48, q = i - r * 48;
        s[(r + 1) * 50 + q + 1] = xp[i];
    }
    __syncthreads();
    float wr[9];
#pragma unroll
    for (int k = 0; k < 9; k++) wr[k] = w[c * 9 + k];
    float sc = bg[c] * rsqrtf(bv[c] + 1e-5f);
    float sh = (cb[c] - bm[c]) * sc + bb[c];
    float* hp = g_h + (b * 128 + c) * 2304;
    for (int p = tid; p < 2304; p += 256) {
        int y = p / 48, xx = p - y * 48;
        const float* sp = s + y * 50 + xx;
        float a = sp[0] * wr[0] + sp[1] * wr[1] + sp[2] * wr[2]
                + sp[50] * wr[3] + sp[51] * wr[4] + sp[52] * wr[5]
                + sp[100] * wr[6] + sp[101] * wr[7] + sp[102] * wr[8];
        hp[p] = a * sc + sh;
    }
}

// ---------------- K2: IF1 + 2x2 maxpool ----------------
__global__ __launch_bounds__(256) void k2_if_pool()
{
    int idx = blockIdx.x * 256 + threadIdx.x;  // 2,359,296 exact
    int ox = idx % 24;
    int t1 = idx / 24;
    int oy = t1 % 24;
    int t2 = t1 / 24;
    int c = t2 & 127;
    int b = t2 >> 7;
    const float* hp = g_h + (b * 128 + c) * 2304 + (2 * oy) * 48 + 2 * ox;
    float h0 = hp[0], h1 = hp[1], h2 = hp[48], h3 = hp[49];
    float v0 = 0.f, v1 = 0.f, v2 = 0.f, v3 = 0.f;
    int pin = c * 676 + (oy + 1) * 26 + ox + 1;
#pragma unroll
    for (int t = 0; t < 8; t++) {
        v0 += h0; v1 += h1; v2 += h2; v3 += h3;
        float s0 = v0 >= 1.f ? 1.f : 0.f; v0 = v0 >= 1.f ? 0.f : v0;
        float s1 = v1 >= 1.f ? 1.f : 0.f; v1 = v1 >= 1.f ? 0.f : v1;
        float s2 = v2 >= 1.f ? 1.f : 0.f; v2 = v2 >= 1.f ? 0.f : v2;
        float s3 = v3 >= 1.f ? 1.f : 0.f; v3 = v3 >= 1.f ? 0.f : v3;
        float mx = fmaxf(fmaxf(s0, s1), fmaxf(s2, s3));
        g_p1[(t * 32 + b) * 128 * 676 + pin] = mx;
    }
}

// ---------------- K3: conv2 (128->128, 3x3 on 24x24) + BN2, tf32 tensor ----------------
// Block: image n, 8 output rows (192 px), 64 couts. K = 16 chunks x (8 cin x 9 taps).
// 8 warps, 4(M) x 2(N); warp tile m48 x n32; mma m16n8k8, 2-split tf32 weights.
__global__ __launch_bounds__(256) void k3_conv2_mma(
    const float* __restrict__ w2, const float* __restrict__ cb,
    const float* __restrict__ bg, const float* __restrict__ bb,
    const float* __restrict__ bm, const float* __restrict__ bv)
{
    __shared__ float sA[8 * 260];        // 8 cins x 10 rows x 26 cols (padded plane slab)
    __shared__ float sBh[9 * 8 * 65];    // [tap][cin8][cout64] hi, pad 65
    __shared__ float sBl[9 * 8 * 65];    // lo
    __shared__ float sSc[64], sSh[64];

    int n = blockIdx.x;
    int y0g = blockIdx.y;              // 0..2  -> rows y0g*8 .. +7
    int coutbase = blockIdx.z * 64;    // 0 or 64
    int tid = threadIdx.x;
    int lane = tid & 31, warp = tid >> 5;
    int wm = warp & 3, wn = warp >> 2; // 4 x 2 warp grid
    int qr = lane >> 2, qc = lane & 3;

    if (tid < 64) {
        int oc = coutbase + tid;
        float sc = bg[oc] * rsqrtf(bv[oc] + 1e-5f);
        sSc[tid] = sc;
        sSh[tid] = (cb[oc] - bm[oc]) * sc + bb[oc];
    }

    // per-thread pixel->plane offsets for the 3 m-fragments (rows r and r+8)
    int offr[3], offr8[3];
#pragma unroll
    for (int mf = 0; mf < 3; mf++) {
        int p = wm * 48 + mf * 16 + qr;
        offr[mf] = (p / 24) * 26 + (p % 24);
        int p8 = p + 8;
        offr8[mf] = (p8 / 24) * 26 + (p8 % 24);
    }

    float acc[3][4][4];
#pragma unroll
    for (int mf = 0; mf < 3; mf++)
#pragma unroll
        for (int nf = 0; nf < 4; nf++)
#pragma unroll
            for (int i = 0; i < 4; i++) acc[mf][nf][i] = 0.f;

    int y0 = y0g * 8;
    const float* pbase = g_p1 + n * 128 * 676 + y0 * 26;

    for (int cb8 = 0; cb8 < 128; cb8 += 8) {
        __syncthreads();
        // stage A: 8 planes, 10 rows x 26 cols each
        for (int i = tid; i < 2080; i += 256) {
            int ci = i / 260, r = i - ci * 260;
            sA[i] = pbase[(cb8 + ci) * 676 + r];
        }
        // stage B: 64 couts x 8 cins x 9 taps, split hi/lo
        for (int i = tid; i < 4608; i += 256) {
            int co = i / 72;
            int rem = i - co * 72;
            int ci = rem / 9, tap = rem - ci * 9;
            float w = w2[(coutbase + co) * 1152 + (cb8 + ci) * 9 + tap];
            uint32_t hb = f2tf32(w);
            float hf = __uint_as_float(hb);
            uint32_t lb = f2tf32(w - hf);
            sBh[(tap * 8 + ci) * 65 + co] = hf;
            sBl[(tap * 8 + ci) * 65 + co] = __uint_as_float(lb);
        }
        __syncthreads();
#pragma unroll
        for (int tap = 0; tap < 9; tap++) {
            int toff = (tap / 3) * 26 + (tap % 3);
            uint32_t a[3][4];
#pragma unroll
            for (int mf = 0; mf < 3; mf++) {
                a[mf][0] = __float_as_uint(sA[qc * 260 + offr[mf] + toff]);
                a[mf][1] = __float_as_uint(sA[qc * 260 + offr8[mf] + toff]);
                a[mf][2] = __float_as_uint(sA[(qc + 4) * 260 + offr[mf] + toff]);
                a[mf][3] = __float_as_uint(sA[(qc + 4) * 260 + offr8[mf] + toff]);
            }
#pragma unroll
            for (int nf = 0; nf < 4; nf++) {
                int ncol = wn * 32 + nf * 8 + qr;
                uint32_t bh0 = __float_as_uint(sBh[(tap * 8 + qc) * 65 + ncol]);
                uint32_t bh1 = __float_as_uint(sBh[(tap * 8 + qc + 4) * 65 + ncol]);
                uint32_t bl0 = __float_as_uint(sBl[(tap * 8 + qc) * 65 + ncol]);
                uint32_t bl1 = __float_as_uint(sBl[(tap * 8 + qc + 4) * 65 + ncol]);
#pragma unroll
                for (int mf = 0; mf < 3; mf++) {
                    mma_tf32(acc[mf][nf], a[mf], bh0, bh1);
                    mma_tf32(acc[mf][nf], a[mf], bl0, bl1);
                }
            }
        }
    }

    // epilogue: BN + scatter to g_c2 [n][cout][576]
    float* op = g_c2 + (n * 128 + coutbase) * 576 + y0g * 192;
#pragma unroll
    for (int mf = 0; mf < 3; mf++) {
        int p = wm * 48 + mf * 16 + qr;
#pragma unroll
        for (int nf = 0; nf < 4; nf++) {
            int L = wn * 32 + nf * 8 + qc * 2;
            float sc0 = sSc[L], sh0 = sSh[L];
            float sc1 = sSc[L + 1], sh1 = sSh[L + 1];
            op[L * 576 + p]           = acc[mf][nf][0] * sc0 + sh0;
            op[(L + 1) * 576 + p]     = acc[mf][nf][1] * sc1 + sh1;
            op[L * 576 + p + 8]       = acc[mf][nf][2] * sc0 + sh0;
            op[(L + 1) * 576 + p + 8] = acc[mf][nf][3] * sc1 + sh1;
        }
    }
}

// ---------------- K4: IF2 + 2x2 maxpool + flatten ----------------
__global__ __launch_bounds__(256) void k4_if2_pool()
{
    int idx = blockIdx.x * 256 + threadIdx.x;  // 589,824 exact
    int ox = idx % 12;
    int t1 = idx / 12;
    int oy = t1 % 12;
    int t2 = t1 / 12;
    int c = t2 & 127;
    int b = t2 >> 7;
    float v0 = 0.f, v1 = 0.f, v2 = 0.f, v3 = 0.f;
    int fo = c * 144 + oy * 12 + ox;
#pragma unroll
    for (int t = 0; t < 8; t++) {
        const float* cp = g_c2 + ((t * 32 + b) * 128 + c) * 576 + (2 * oy) * 24 + 2 * ox;
        v0 += cp[0]; v1 += cp[1]; v2 += cp[24]; v3 += cp[25];
        float s0 = v0 >= 1.f ? 1.f : 0.f; v0 = v0 >= 1.f ? 0.f : v0;
        float s1 = v1 >= 1.f ? 1.f : 0.f; v1 = v1 >= 1.f ? 0.f : v1;
        float s2 = v2 >= 1.f ? 1.f : 0.f; v2 = v2 >= 1.f ? 0.f : v2;
        float s3 = v3 >= 1.f ? 1.f : 0.f; v3 = v3 >= 1.f ? 0.f : v3;
        g_f[(t * 32 + b) * 18432 + fo] = fmaxf(fmaxf(s0, s1), fmaxf(s2, s3));
    }
}

// ---------------- K5: fc1 GEMM, split-K=4 (fp32) ----------------
__global__ __launch_bounds__(256) void k5_fc1(const float* __restrict__ w1)
{
    __shared__ float As[16][65];
    __shared__ float Bs[16][65];
    int tid = threadIdx.x;
    int tx = tid & 15, ty = tid >> 4;
    int m0 = blockIdx.y * 64, n0 = blockIdx.x * 64;
    int kbase = blockIdx.z * 4608;
    float acc[4][4] = {};
    int lrow = tid >> 2;
    int lk = (tid & 3) * 4;
    const float* aptr = g_f + (m0 + lrow) * 18432 + kbase + lk;
    const float* bptr = w1 + (n0 + lrow) * 18432 + kbase + lk;
    for (int kt = 0; kt < 288; kt++) {
        float4 av = *(const float4*)aptr;
        float4 bv = *(const float4*)bptr;
        __syncthreads();
        As[lk + 0][lrow] = av.x; As[lk + 1][lrow] = av.y;
        As[lk + 2][lrow] = av.z; As[lk + 3][lrow] = av.w;
        Bs[lk + 0][lrow] = bv.x; Bs[lk + 1][lrow] = bv.y;
        Bs[lk + 2][lrow] = bv.z; Bs[lk + 3][lrow] = bv.w;
        __syncthreads();
#pragma unroll
        for (int kk = 0; kk < 16; kk++) {
            float ar[4], br[4];
#pragma unroll
            for (int i = 0; i < 4; i++) ar[i] = As[kk][ty + 16 * i];
#pragma unroll
            for (int j = 0; j < 4; j++) br[j] = Bs[kk][tx + 16 * j];
#pragma unroll
            for (int i = 0; i < 4; i++)
#pragma unroll
                for (int j = 0; j < 4; j++) acc[i][j] += ar[i] * br[j];
        }
        aptr += 16; bptr += 16;
    }
    float* op = g_y1p + blockIdx.z * 294912;
#pragma unroll
    for (int i = 0; i < 4; i++)
#pragma unroll
        for (int j = 0; j < 4; j++)
            op[(m0 + ty + 16 * i) * 1152 + n0 + tx + 16 * j] = acc[i][j];
}

// ---------------- K6: reduce split-K + bias + LIF1 ----------------
__global__ __launch_bounds__(256) void k6_lif1(const float* __restrict__ bias)
{
    int idx = blockIdx.x * 256 + threadIdx.x;  // 36,864 exact
    int o = idx % 1152, b = idx / 1152;
    float bi = bias[o];
    float v = 0.f;
#pragma unroll
    for (int t = 0; t < 8; t++) {
        int row = (t * 32 + b) * 1152 + o;
        float xx = g_y1p[row] + g_y1p[294912 + row] + g_y1p[2 * 294912 + row]
                 + g_y1p[3 * 294912 + row] + bi;
        v += (xx - v) * 0.5f;
        float s = v >= 1.f ? 1.f : 0.f;
        g_l1[row] = s;
        v = v >= 1.f ? 0.f : v;
    }
}

// ---------------- K7: fc2 ----------------
__global__ __launch_bounds__(128) void k7_fc2(const float* __restrict__ w,
                                              const float* __restrict__ bias)
{
    __shared__ float row[1152];
    int r = blockIdx.x, o = threadIdx.x;
    for (int i = o; i < 1152; i += 128) row[i] = g_l1[r * 1152 + i];
    __syncthreads();
    const float4* wp = (const float4*)(w + o * 1152);
    float acc = 0.f;
#pragma unroll 4
    for (int k = 0; k < 288; k++) {
        float4 wv = wp[k];
        acc += row[4 * k] * wv.x + row[4 * k + 1] * wv.y
             + row[4 * k + 2] * wv.z + row[4 * k + 3] * wv.w;
    }
    g_y2[r * 128 + o] = acc + bias[o];
}

// ---------------- K8: LIF2 ----------------
__global__ __launch_bounds__(256) void k8_lif2()
{
    int idx = blockIdx.x * 256 + threadIdx.x;  // 4096 exact
    int o = idx & 127, b = idx >> 7;
    float v = 0.f;
#pragma unroll
    for (int t = 0; t < 8; t++) {
        int row = (t * 32 + b) * 128 + o;
        float xx = g_y2[row];
        v += (xx - v) * 0.5f;
        float s = v >= 1.f ? 1.f : 0.f;
        g_l2[row] = s;
        v = v >= 1.f ? 0.f : v;
    }
}

// ---------------- K9: fc3 + LIF3 + mean over T ----------------
__global__ __launch_bounds__(256) void k9_fc3(const float* __restrict__ w,
                                              const float* __restrict__ bias,
                                              float* __restrict__ out)
{
    int idx = threadIdx.x;
    if (idx >= 224) return;
    int o = idx % 7, b = idx / 7;
    const float4* wp = (const float4*)(w + o * 128);
    float v = 0.f, accm = 0.f;
    float bi = bias[o];
    for (int t = 0; t < 8; t++) {
        const float4* lp = (const float4*)(g_l2 + (t * 32 + b) * 128);
        float y = 0.f;
#pragma unroll
        for (int k = 0; k < 32; k++) {
            float4 a = lp[k], ww = wp[k];
            y += a.x * ww.x + a.y * ww.y + a.z * ww.z + a.w * ww.w;
        }
        y += bi;
        v += (y - v) * 0.5f;
        float s = v >= 1.f ? 1.f : 0.f;
        accm += s;
        v = v >= 1.f ? 0.f : v;
    }
    out[b * 7 + o] = accm * 0.125f;
}

// ---------------- launch ----------------
extern "C" void kernel_launch(void* const* d_in, const int* in_sizes, int n_in,
                              void* d_out, int out_size)
{
    const float* x       = (const float*)d_in[0];
    const float* conv1_w = (const float*)d_in[1];
    const float* conv1_b = (const float*)d_in[2];
    const float* bn1_g   = (const float*)d_in[3];
    const float* bn1_b   = (const float*)d_in[4];
    const float* bn1_m   = (const float*)d_in[5];
    const float* bn1_v   = (const float*)d_in[6];
    const float* conv2_w = (const float*)d_in[7];
    const float* conv2_b = (const float*)d_in[8];
    const float* bn2_g   = (const float*)d_in[9];
    const float* bn2_b   = (const float*)d_in[10];
    const float* bn2_m   = (const float*)d_in[11];
    const float* bn2_v   = (const float*)d_in[12];
    const float* fc1_w   = (const float*)d_in[13];
    const float* fc1_b   = (const float*)d_in[14];
    const float* fc2_w   = (const float*)d_in[15];
    const float* fc2_b   = (const float*)d_in[16];
    const float* fc3_w   = (const float*)d_in[17];
    const float* fc3_b   = (const float*)d_in[18];

    // zero padded p1 borders (interior overwritten by K2)
    void* p1ptr = nullptr;
    cudaGetSymbolAddress(&p1ptr, g_p1);
    cudaMemsetAsync(p1ptr, 0, sizeof(g_p1));

    k1_conv1bn<<<32 * 128, 256>>>(x, conv1_w, conv1_b, bn1_g, bn1_b, bn1_m, bn1_v);
    k2_if_pool<<<9216, 256>>>();
    dim3 g3(NTB, 3, 2);
    k3_conv2_mma<<<g3, 256>>>(conv2_w, conv2_b, bn2_g, bn2_b, bn2_m, bn2_v);
    k4_if2_pool<<<2304, 256>>>();
    dim3 g5(18, 4, 4);
    k5_fc1<<<g5, 256>>>(fc1_w);
    k6_lif1<<<144, 256>>>(fc1_b);
    k7_fc2<<<NTB, 128>>>(fc2_w, fc2_b);
    k8_lif2<<<16, 256>>>();
    k9_fc3<<<1, 256>>>(fc3_w, fc3_b, (float*)d_out);
}

// round 3
// speedup vs baseline: 1.6016x; 1.0153x over previous
#include <cuda_runtime.h>
#include <cstdint>

// SJCSNN spiking CNN forward, T=8, B=32, out [32,7] f32.
// conv2 AND fc1 on tensor pipe: tf32 mma.sync, 2-term weight split
// (spike activations are {0,1} -> exact in tf32; weight residual ~2^-21).

#define NTB 256  // T*B

// ---- scratch (device globals; no allocations) ----
__device__ float g_h[32 * 128 * 48 * 48];        // conv1+bn1 output
__device__ float g_p1[NTB * 128 * 26 * 26];      // IF1+pool spikes, PADDED 26x26
__device__ float g_c2[NTB * 128 * 24 * 24];      // conv2+bn2 output
__device__ float g_f[NTB * 18432];               // IF2+pool spikes, flattened
__device__ float g_y1p[8 * NTB * 1152];          // fc1 split-K partials (8)
__device__ float g_l1[NTB * 1152];               // LIF1 spikes
__device__ float g_y2[NTB * 128];                // fc2 output
__device__ float g_l2[NTB * 128];                // LIF2 spikes
__device__ float g_w2h[9 * 128 * 128];           // conv2 W hi, [tap][cin][cout]
__device__ float g_w2l[9 * 128 * 128];           // conv2 W lo

// ---------------- tf32 mma helpers ----------------
__device__ __forceinline__ uint32_t f2tf32(float f) {
    uint32_t r;
    asm("cvt.rna.tf32.f32 %0, %1;" : "=r"(r) : "f"(f));
    return r;
}
__device__ __forceinline__ void mma_tf32(float c[4], const uint32_t a[4],
                                         uint32_t b0, uint32_t b1) {
    asm volatile(
        "mma.sync.aligned.m16n8k8.row.col.f32.tf32.tf32.f32 "
        "{%0,%1,%2,%3}, {%4,%5,%6,%7}, {%8,%9}, {%0,%1,%2,%3};"
        : "+f"(c[0]), "+f"(c[1]), "+f"(c[2]), "+f"(c[3])
        : "r"(a[0]), "r"(a[1]), "r"(a[2]), "r"(a[3]), "r"(b0), "r"(b1));
}

// ---------------- K0: precompute conv2 weight split ----------------
__global__ __launch_bounds__(256) void k0_split_w2(const float* __restrict__ w2)
{
    int i = blockIdx.x * 256 + threadIdx.x;  // 147456 exact
    int co = i / 1152;
    int rem = i - co * 1152;
    int ci = rem / 9, tap = rem - ci * 9;
    float w = w2[i];
    uint32_t hb = f2tf32(w);
    float hf = __uint_as_float(hb);
    uint32_t lb = f2tf32(w - hf);
    int o = (tap * 128 + ci) * 128 + co;
    g_w2h[o] = hf;
    g_w2l[o] = __uint_as_float(lb);
}

// ---------------- K1: conv1 (1->128, 3x3 SAME) + BN1 ----------------
__global__ __launch_bounds__(256) void k1_conv1bn(
    const float* __restrict__ x, const float* __restrict__ w,
    const float* __restrict__ cb, const float* __restrict__ bg,
    const float* __restrict__ bb, const float* __restrict__ bm,
    const float* __restrict__ bv)
{
    __shared__ float s[2500];  // 50*50 padded
    int b = blockIdx.x >> 7, c = blockIdx.x & 127;
    int tid = threadIdx.x;
    for (int i = tid; i < 2500; i += 256) s[i] = 0.0f;
    __syncthreads();
    const float* xp = x + b * 2304;
    for (int i = tid; i < 2304; i += 256) {
        int r = i / 48, q = i - r * 48;
        s[(r + 1) * 50 + q + 1] = xp[i];
    }
    __syncthreads();
    float wr[9];
#pragma unroll
    for (int k = 0; k < 9; k++) wr[k] = w[c * 9 + k];
    float sc = bg[c] * rsqrtf(bv[c] + 1e-5f);
    float sh = (cb[c] - bm[c]) * sc + bb[c];
    float* hp = g_h + (b * 128 + c) * 2304;
    for (int p = tid; p < 2304; p += 256) {
        int y = p / 48, xx = p - y * 48;
        const float* sp = s + y * 50 + xx;
        float a = sp[0] * wr[0] + sp[1] * wr[1] + sp[2] * wr[2]
                + sp[50] * wr[3] + sp[51] * wr[4] + sp[52] * wr[5]
                + sp[100] * wr[6] + sp[101] * wr[7] + sp[102] * wr[8];
        hp[p] = a * sc + sh;
    }
}

// ---------------- K2: IF1 + 2x2 maxpool ----------------
__global__ __launch_bounds__(256) void k2_if_pool()
{
    int idx = blockIdx.x * 256 + threadIdx.x;  // 2,359,296 exact
    int ox = idx % 24;
    int t1 = idx / 24;
    int oy = t1 % 24;
    int t2 = t1 / 24;
    int c = t2 & 127;
    int b = t2 >> 7;
    const float* hp = g_h + (b * 128 + c) * 2304 + (2 * oy) * 48 + 2 * ox;
    float h0 = hp[0], h1 = hp[1], h2 = hp[48], h3 = hp[49];
    float v0 = 0.f, v1 = 0.f, v2 = 0.f, v3 = 0.f;
    int pin = c * 676 + (oy + 1) * 26 + ox + 1;
#pragma unroll
    for (int t = 0; t < 8; t++) {
        v0 += h0; v1 += h1; v2 += h2; v3 += h3;
        float s0 = v0 >= 1.f ? 1.f : 0.f; v0 = v0 >= 1.f ? 0.f : v0;
        float s1 = v1 >= 1.f ? 1.f : 0.f; v1 = v1 >= 1.f ? 0.f : v1;
        float s2 = v2 >= 1.f ? 1.f : 0.f; v2 = v2 >= 1.f ? 0.f : v2;
        float s3 = v3 >= 1.f ? 1.f : 0.f; v3 = v3 >= 1.f ? 0.f : v3;
        float mx = fmaxf(fmaxf(s0, s1), fmaxf(s2, s3));
        g_p1[(t * 32 + b) * 128 * 676 + pin] = mx;
    }
}

// ---------------- K3: conv2 (128->128, 3x3 on 24x24) + BN2, tf32 tensor ----------------
// Block: image n, 8 output rows (192 px), 64 couts. K = 16 chunks x (8 cin x 9 taps).
// 8 warps, 4(M) x 2(N); warp tile m48 x n32; mma m16n8k8, pre-split tf32 weights.
__global__ __launch_bounds__(256) void k3_conv2_mma(
    const float* __restrict__ cb, const float* __restrict__ bg,
    const float* __restrict__ bb, const float* __restrict__ bm,
    const float* __restrict__ bv)
{
    __shared__ float sA[8 * 260];        // 8 cins x 10 rows x 26 cols
    __shared__ float sBh[9 * 8 * 65];    // [tap][cin8][cout64] hi, pad 65
    __shared__ float sBl[9 * 8 * 65];    // lo
    __shared__ float sSc[64], sSh[64];

    int n = blockIdx.x;
    int y0g = blockIdx.y;              // 0..2  -> rows y0g*8 .. +7
    int coutbase = blockIdx.z * 64;    // 0 or 64
    int tid = threadIdx.x;
    int lane = tid & 31, warp = tid >> 5;
    int wm = warp & 3, wn = warp >> 2; // 4 x 2 warp grid
    int qr = lane >> 2, qc = lane & 3;

    if (tid < 64) {
        int oc = coutbase + tid;
        float sc = bg[oc] * rsqrtf(bv[oc] + 1e-5f);
        sSc[tid] = sc;
        sSh[tid] = (cb[oc] - bm[oc]) * sc + bb[oc];
    }

    int offr[3], offr8[3];
#pragma unroll
    for (int mf = 0; mf < 3; mf++) {
        int p = wm * 48 + mf * 16 + qr;
        offr[mf] = (p / 24) * 26 + (p % 24);
        int p8 = p + 8;
        offr8[mf] = (p8 / 24) * 26 + (p8 % 24);
    }

    float acc[3][4][4];
#pragma unroll
    for (int mf = 0; mf < 3; mf++)
#pragma unroll
        for (int nf = 0; nf < 4; nf++)
#pragma unroll
            for (int i = 0; i < 4; i++) acc[mf][nf][i] = 0.f;

    int y0 = y0g * 8;
    const float* pbase = g_p1 + n * 128 * 676 + y0 * 26;

    for (int cb8 = 0; cb8 < 128; cb8 += 8) {
        __syncthreads();
        // stage A: 8 planes, 10 rows x 26 cols each
        for (int i = tid; i < 2080; i += 256) {
            int ci = i / 260, r = i - ci * 260;
            sA[i] = pbase[(cb8 + ci) * 676 + r];
        }
        // stage B: copy pre-split weights (coalesced along cout)
        for (int i = tid; i < 4608; i += 256) {
            int co = i & 63;
            int r = i >> 6;
            int ci = r & 7, tap = r >> 3;
            int src = (tap * 128 + cb8 + ci) * 128 + coutbase + co;
            int dst = (tap * 8 + ci) * 65 + co;
            sBh[dst] = g_w2h[src];
            sBl[dst] = g_w2l[src];
        }
        __syncthreads();
#pragma unroll
        for (int tap = 0; tap < 9; tap++) {
            int toff = (tap / 3) * 26 + (tap % 3);
            uint32_t a[3][4];
#pragma unroll
            for (int mf = 0; mf < 3; mf++) {
                a[mf][0] = __float_as_uint(sA[qc * 260 + offr[mf] + toff]);
                a[mf][1] = __float_as_uint(sA[qc * 260 + offr8[mf] + toff]);
                a[mf][2] = __float_as_uint(sA[(qc + 4) * 260 + offr[mf] + toff]);
                a[mf][3] = __float_as_uint(sA[(qc + 4) * 260 + offr8[mf] + toff]);
            }
#pragma unroll
            for (int nf = 0; nf < 4; nf++) {
                int ncol = wn * 32 + nf * 8 + qr;
                uint32_t bh0 = __float_as_uint(sBh[(tap * 8 + qc) * 65 + ncol]);
                uint32_t bh1 = __float_as_uint(sBh[(tap * 8 + qc + 4) * 65 + ncol]);
                uint32_t bl0 = __float_as_uint(sBl[(tap * 8 + qc) * 65 + ncol]);
                uint32_t bl1 = __float_as_uint(sBl[(tap * 8 + qc + 4) * 65 + ncol]);
#pragma unroll
                for (int mf = 0; mf < 3; mf++) {
                    mma_tf32(acc[mf][nf], a[mf], bh0, bh1);
                    mma_tf32(acc[mf][nf], a[mf], bl0, bl1);
                }
            }
        }
    }

    // epilogue: BN + scatter to g_c2 [n][cout][576]
    float* op = g_c2 + (n * 128 + coutbase) * 576 + y0g * 192;
#pragma unroll
    for (int mf = 0; mf < 3; mf++) {
        int p = wm * 48 + mf * 16 + qr;
#pragma unroll
        for (int nf = 0; nf < 4; nf++) {
            int L = wn * 32 + nf * 8 + qc * 2;
            float sc0 = sSc[L], sh0 = sSh[L];
            float sc1 = sSc[L + 1], sh1 = sSh[L + 1];
            op[L * 576 + p]           = acc[mf][nf][0] * sc0 + sh0;
            op[(L + 1) * 576 + p]     = acc[mf][nf][1] * sc1 + sh1;
            op[L * 576 + p + 8]       = acc[mf][nf][2] * sc0 + sh0;
            op[(L + 1) * 576 + p + 8] = acc[mf][nf][3] * sc1 + sh1;
        }
    }
}

// ---------------- K4: IF2 + 2x2 maxpool + flatten ----------------
__global__ __launch_bounds__(256) void k4_if2_pool()
{
    int idx = blockIdx.x * 256 + threadIdx.x;  // 589,824 exact
    int ox = idx % 12;
    int t1 = idx / 12;
    int oy = t1 % 12;
    int t2 = t1 / 12;
    int c = t2 & 127;
    int b = t2 >> 7;
    float v0 = 0.f, v1 = 0.f, v2 = 0.f, v3 = 0.f;
    int fo = c * 144 + oy * 12 + ox;
#pragma unroll
    for (int t = 0; t < 8; t++) {
        const float* cp = g_c2 + ((t * 32 + b) * 128 + c) * 576 + (2 * oy) * 24 + 2 * ox;
        v0 += cp[0]; v1 += cp[1]; v2 += cp[24]; v3 += cp[25];
        float s0 = v0 >= 1.f ? 1.f : 0.f; v0 = v0 >= 1.f ? 0.f : v0;
        float s1 = v1 >= 1.f ? 1.f : 0.f; v1 = v1 >= 1.f ? 0.f : v1;
        float s2 = v2 >= 1.f ? 1.f : 0.f; v2 = v2 >= 1.f ? 0.f : v2;
        float s3 = v3 >= 1.f ? 1.f : 0.f; v3 = v3 >= 1.f ? 0.f : v3;
        g_f[(t * 32 + b) * 18432 + fo] = fmaxf(fmaxf(s0, s1), fmaxf(s2, s3));
    }
}

// ---------------- K5: fc1 GEMM, tf32 mma, split-K=8 ----------------
// C[256,1152] = F[256,18432] * W1[1152,18432]^T. BM=256, BN=64, BK=16.
// 8 warps 4(M)x2(N); warp tile m64 x n32. A = spikes (exact tf32), B split hi/lo.
__global__ __launch_bounds__(256) void k5_fc1_mma(const float* __restrict__ w1)
{
    __shared__ float sA[16 * 264];   // [k][m], pad 264 (conflict-free)
    __shared__ float sBh[16 * 72];   // [k][n], pad 72 (conflict-free)
    __shared__ float sBl[16 * 72];
    int n0 = blockIdx.x * 64;
    int z = blockIdx.y;
    int tid = threadIdx.x;
    int lane = tid & 31, warp = tid >> 5;
    int wm = warp & 3, wn = warp >> 2;
    int qr = lane >> 2, qc = lane & 3;

    float acc[4][4][4];
#pragma unroll
    for (int mf = 0; mf < 4; mf++)
#pragma unroll
        for (int nf = 0; nf < 4; nf++)
#pragma unroll
            for (int i = 0; i < 4; i++) acc[mf][nf][i] = 0.f;

    int kbase = z * 2304;
    for (int kc = 0; kc < 144; kc++) {
        int k0 = kbase + kc * 16;
        __syncthreads();
        // stage A: 256 rows x 16 k (1024 float4)
        for (int v = tid; v < 1024; v += 256) {
            int m = v >> 2;
            int kq = (v & 3) * 4;
            float4 a = *(const float4*)(g_f + m * 18432 + k0 + kq);
            sA[(kq + 0) * 264 + m] = a.x;
            sA[(kq + 1) * 264 + m] = a.y;
            sA[(kq + 2) * 264 + m] = a.z;
            sA[(kq + 3) * 264 + m] = a.w;
        }
        // stage B: 64 rows x 16 k (256 float4), split hi/lo
        {
            int nr = tid >> 2;
            int kq = (tid & 3) * 4;
            float4 b = *(const float4*)(w1 + (n0 + nr) * 18432 + k0 + kq);
            float bx[4] = {b.x, b.y, b.z, b.w};
#pragma unroll
            for (int i = 0; i < 4; i++) {
                uint32_t hb = f2tf32(bx[i]);
                float hf = __uint_as_float(hb);
                sBh[(kq + i) * 72 + nr] = hf;
                sBl[(kq + i) * 72 + nr] = __uint_as_float(f2tf32(bx[i] - hf));
            }
        }
        __syncthreads();
#pragma unroll
        for (int ks = 0; ks < 2; ks++) {
            uint32_t a[4][4];
#pragma unroll
            for (int mf = 0; mf < 4; mf++) {
                int m = wm * 64 + mf * 16 + qr;
                a[mf][0] = __float_as_uint(sA[(ks * 8 + qc) * 264 + m]);
                a[mf][1] = __float_as_uint(sA[(ks * 8 + qc) * 264 + m + 8]);
                a[mf][2] = __float_as_uint(sA[(ks * 8 + qc + 4) * 264 + m]);
                a[mf][3] = __float_as_uint(sA[(ks * 8 + qc + 4) * 264 + m + 8]);
            }
#pragma unroll
            for (int nf = 0; nf < 4; nf++) {
                int nn = wn * 32 + nf * 8 + qr;
                uint32_t bh0 = __float_as_uint(sBh[(ks * 8 + qc) * 72 + nn]);
                uint32_t bh1 = __float_as_uint(sBh[(ks * 8 + qc + 4) * 72 + nn]);
                uint32_t bl0 = __float_as_uint(sBl[(ks * 8 + qc) * 72 + nn]);
                uint32_t bl1 = __float_as_uint(sBl[(ks * 8 + qc + 4) * 72 + nn]);
#pragma unroll
                for (int mf = 0; mf < 4; mf++) {
                    mma_tf32(acc[mf][nf], a[mf], bh0, bh1);
                    mma_tf32(acc[mf][nf], a[mf], bl0, bl1);
                }
            }
        }
    }

    float* op = g_y1p + z * 294912;
#pragma unroll
    for (int mf = 0; mf < 4; mf++) {
        int m = wm * 64 + mf * 16 + qr;
#pragma unroll
        for (int nf = 0; nf < 4; nf++) {
            int nn = n0 + wn * 32 + nf * 8 + qc * 2;
            op[m * 1152 + nn]           = acc[mf][nf][0];
            op[m * 1152 + nn + 1]       = acc[mf][nf][1];
            op[(m + 8) * 1152 + nn]     = acc[mf][nf][2];
            op[(m + 8) * 1152 + nn + 1] = acc[mf][nf][3];
        }
    }
}

// ---------------- K6: reduce split-K(8) + bias + LIF1 ----------------
__global__ __launch_bounds__(256) void k6_lif1(const float* __restrict__ bias)
{
    int idx = blockIdx.x * 256 + threadIdx.x;  // 36,864 exact
    int o = idx % 1152, b = idx / 1152;
    float bi = bias[o];
    float v = 0.f;
#pragma unroll
    for (int t = 0; t < 8; t++) {
        int row = (t * 32 + b) * 1152 + o;
        float xx = bi;
#pragma unroll
        for (int z = 0; z < 8; z++) xx += g_y1p[z * 294912 + row];
        v += (xx - v) * 0.5f;
        float s = v >= 1.f ? 1.f : 0.f;
        g_l1[row] = s;
        v = v >= 1.f ? 0.f : v;
    }
}

// ---------------- K7: fc2 ----------------
__global__ __launch_bounds__(128) void k7_fc2(const float* __restrict__ w,
                                              const float* __restrict__ bias)
{
    __shared__ float row[1152];
    int r = blockIdx.x, o = threadIdx.x;
    for (int i = o; i < 1152; i += 128) row[i] = g_l1[r * 1152 + i];
    __syncthreads();
    const float4* wp = (const float4*)(w + o * 1152);
    float acc = 0.f;
#pragma unroll 4
    for (int k = 0; k < 288; k++) {
        float4 wv = wp[k];
        acc += row[4 * k] * wv.x + row[4 * k + 1] * wv.y
             + row[4 * k + 2] * wv.z + row[4 * k + 3] * wv.w;
    }
    g_y2[r * 128 + o] = acc + bias[o];
}

// ---------------- K8: LIF2 ----------------
__global__ __launch_bounds__(256) void k8_lif2()
{
    int idx = blockIdx.x * 256 + threadIdx.x;  // 4096 exact
    int o = idx & 127, b = idx >> 7;
    float v = 0.f;
#pragma unroll
    for (int t = 0; t < 8; t++) {
        int row = (t * 32 + b) * 128 + o;
        float xx = g_y2[row];
        v += (xx - v) * 0.5f;
        float s = v >= 1.f ? 1.f : 0.f;
        g_l2[row] = s;
        v = v >= 1.f ? 0.f : v;
    }
}

// ---------------- K9: fc3 + LIF3 + mean over T ----------------
__global__ __launch_bounds__(256) void k9_fc3(const float* __restrict__ w,
                                              const float* __restrict__ bias,
                                              float* __restrict__ out)
{
    int idx = threadIdx.x;
    if (idx >= 224) return;
    int o = idx % 7, b = idx / 7;
    const float4* wp = (const float4*)(w + o * 128);
    float v = 0.f, accm = 0.f;
    float bi = bias[o];
    for (int t = 0; t < 8; t++) {
        const float4* lp = (const float4*)(g_l2 + (t * 32 + b) * 128);
        float y = 0.f;
#pragma unroll
        for (int k = 0; k < 32; k++) {
            float4 a = lp[k], ww = wp[k];
            y += a.x * ww.x + a.y * ww.y + a.z * ww.z + a.w * ww.w;
        }
        y += bi;
        v += (y - v) * 0.5f;
        float s = v >= 1.f ? 1.f : 0.f;
        accm += s;
        v = v >= 1.f ? 0.f : v;
    }
    out[b * 7 + o] = accm * 0.125f;
}

// ---------------- launch ----------------
extern "C" void kernel_launch(void* const* d_in, const int* in_sizes, int n_in,
                              void* d_out, int out_size)
{
    const float* x       = (const float*)d_in[0];
    const float* conv1_w = (const float*)d_in[1];
    const float* conv1_b = (const float*)d_in[2];
    const float* bn1_g   = (const float*)d_in[3];
    const float* bn1_b   = (const float*)d_in[4];
    const float* bn1_m   = (const float*)d_in[5];
    const float* bn1_v   = (const float*)d_in[6];
    const float* conv2_w = (const float*)d_in[7];
    const float* conv2_b = (const float*)d_in[8];
    const float* bn2_g   = (const float*)d_in[9];
    const float* bn2_b   = (const float*)d_in[10];
    const float* bn2_m   = (const float*)d_in[11];
    const float* bn2_v   = (const float*)d_in[12];
    const float* fc1_w   = (const float*)d_in[13];
    const float* fc1_b   = (const float*)d_in[14];
    const float* fc2_w   = (const float*)d_in[15];
    const float* fc2_b   = (const float*)d_in[16];
    const float* fc3_w   = (const float*)d_in[17];
    const float* fc3_b   = (const float*)d_in[18];

    // zero padded p1 borders (interior overwritten by K2)
    void* p1ptr = nullptr;
    cudaGetSymbolAddress(&p1ptr, g_p1);
    cudaMemsetAsync(p1ptr, 0, sizeof(g_p1));

    k0_split_w2<<<576, 256>>>(conv2_w);
    k1_conv1bn<<<32 * 128, 256>>>(x, conv1_w, conv1_b, bn1_g, bn1_b, bn1_m, bn1_v);
    k2_if_pool<<<9216, 256>>>();
    dim3 g3(NTB, 3, 2);
    k3_conv2_mma<<<g3, 256>>>(conv2_b, bn2_g, bn2_b, bn2_m, bn2_v);
    k4_if2_pool<<<2304, 256>>>();
    dim3 g5(18, 8);
    k5_fc1_mma<<<g5, 256>>>(fc1_w);
    k6_lif1<<<144, 256>>>(fc1_b);
    k7_fc2<<<NTB, 128>>>(fc2_w, fc2_b);
    k8_lif2<<<16, 256>>>();
    k9_fc3<<<1, 256>>>(fc3_w, fc3_b, (float*)d_out);
}

// round 4
// speedup vs baseline: 1.8252x; 1.1396x over previous
#include <cuda_runtime.h>
#include <cstdint>

// SJCSNN spiking CNN forward, T=8, B=32, out [32,7] f32.
// conv2 AND fc1 on tensor pipe: tf32 mma.sync, 2-term weight split
// (spike activations are {0,1} -> exact in tf32; weight residual ~2^-21).

#define NTB 256  // T*B

// ---- scratch (device globals; no allocations) ----
__device__ float g_h[32 * 128 * 48 * 48];        // conv1+bn1 output
__device__ float g_p1[NTB * 128 * 26 * 26];      // IF1+pool spikes, PADDED 26x26
__device__ float g_c2[NTB * 128 * 24 * 24];      // conv2+bn2 output
__device__ float g_f[NTB * 18432];               // IF2+pool spikes, flattened
__device__ float g_y1p[8 * NTB * 1152];          // fc1 split-K partials (8)
__device__ float g_l1[NTB * 1152];               // LIF1 spikes
__device__ float g_y2[NTB * 128];                // fc2 output
__device__ float g_l2[NTB * 128];                // LIF2 spikes
__device__ float2 g_w2hl[9 * 128 * 128];         // conv2 W (hi,lo), [tap][cin][cout]

// ---------------- tf32 mma helpers ----------------
__device__ __forceinline__ uint32_t f2tf32(float f) {
    uint32_t r;
    asm("cvt.rna.tf32.f32 %0, %1;" : "=r"(r) : "f"(f));
    return r;
}
__device__ __forceinline__ void mma_tf32(float c[4], const uint32_t a[4],
                                         uint32_t b0, uint32_t b1) {
    asm volatile(
        "mma.sync.aligned.m16n8k8.row.col.f32.tf32.tf32.f32 "
        "{%0,%1,%2,%3}, {%4,%5,%6,%7}, {%8,%9}, {%0,%1,%2,%3};"
        : "+f"(c[0]), "+f"(c[1]), "+f"(c[2]), "+f"(c[3])
        : "r"(a[0]), "r"(a[1]), "r"(a[2]), "r"(a[3]), "r"(b0), "r"(b1));
}

// ---------------- K0: precompute conv2 weight split (interleaved) ----------------
__global__ __launch_bounds__(256) void k0_split_w2(const float* __restrict__ w2)
{
    int i = blockIdx.x * 256 + threadIdx.x;  // 147456 exact
    int co = i / 1152;
    int rem = i - co * 1152;
    int ci = rem / 9, tap = rem - ci * 9;
    float w = w2[i];
    uint32_t hb = f2tf32(w);
    float hf = __uint_as_float(hb);
    uint32_t lb = f2tf32(w - hf);
    g_w2hl[(tap * 128 + ci) * 128 + co] = make_float2(hf, __uint_as_float(lb));
}

// ---------------- K1: conv1 (1->128, 3x3 SAME) + BN1 ----------------
__global__ __launch_bounds__(256) void k1_conv1bn(
    const float* __restrict__ x, const float* __restrict__ w,
    const float* __restrict__ cb, const float* __restrict__ bg,
    const float* __restrict__ bb, const float* __restrict__ bm,
    const float* __restrict__ bv)
{
    __shared__ float s[2500];  // 50*50 padded
    int b = blockIdx.x >> 7, c = blockIdx.x & 127;
    int tid = threadIdx.x;
    for (int i = tid; i < 2500; i += 256) s[i] = 0.0f;
    __syncthreads();
    const float* xp = x + b * 2304;
    for (int i = tid; i < 2304; i += 256) {
        int r = i / 48, q = i - r * 48;
        s[(r + 1) * 50 + q + 1] = xp[i];
    }
    __syncthreads();
    float wr[9];
#pragma unroll
    for (int k = 0; k < 9; k++) wr[k] = w[c * 9 + k];
    float sc = bg[c] * rsqrtf(bv[c] + 1e-5f);
    float sh = (cb[c] - bm[c]) * sc + bb[c];
    float* hp = g_h + (b * 128 + c) * 2304;
    for (int p = tid; p < 2304; p += 256) {
        int y = p / 48, xx = p - y * 48;
        const float* sp = s + y * 50 + xx;
        float a = sp[0] * wr[0] + sp[1] * wr[1] + sp[2] * wr[2]
                + sp[50] * wr[3] + sp[51] * wr[4] + sp[52] * wr[5]
                + sp[100] * wr[6] + sp[101] * wr[7] + sp[102] * wr[8];
        hp[p] = a * sc + sh;
    }
}

// ---------------- K2: IF1 + 2x2 maxpool ----------------
__global__ __launch_bounds__(256) void k2_if_pool()
{
    int idx = blockIdx.x * 256 + threadIdx.x;  // 2,359,296 exact
    int ox = idx % 24;
    int t1 = idx / 24;
    int oy = t1 % 24;
    int t2 = t1 / 24;
    int c = t2 & 127;
    int b = t2 >> 7;
    const float* hp = g_h + (b * 128 + c) * 2304 + (2 * oy) * 48 + 2 * ox;
    float h0 = hp[0], h1 = hp[1], h2 = hp[48], h3 = hp[49];
    float v0 = 0.f, v1 = 0.f, v2 = 0.f, v3 = 0.f;
    int pin = c * 676 + (oy + 1) * 26 + ox + 1;
#pragma unroll
    for (int t = 0; t < 8; t++) {
        v0 += h0; v1 += h1; v2 += h2; v3 += h3;
        float s0 = v0 >= 1.f ? 1.f : 0.f; v0 = v0 >= 1.f ? 0.f : v0;
        float s1 = v1 >= 1.f ? 1.f : 0.f; v1 = v1 >= 1.f ? 0.f : v1;
        float s2 = v2 >= 1.f ? 1.f : 0.f; v2 = v2 >= 1.f ? 0.f : v2;
        float s3 = v3 >= 1.f ? 1.f : 0.f; v3 = v3 >= 1.f ? 0.f : v3;
        float mx = fmaxf(fmaxf(s0, s1), fmaxf(s2, s3));
        g_p1[(t * 32 + b) * 128 * 676 + pin] = mx;
    }
}

// ---------------- K3: conv2 (128->128, 3x3 on 24x24) + BN2, tf32 tensor ----------------
// Block: image n, 8 output rows (192 px), 64 couts. K = 16 chunks x (8 cin x 9 taps).
// 8 warps, 4(M) x 2(N); warp tile m48 x n32; mma m16n8k8.
// Weights staged as float2(hi,lo), row stride 68 float2 -> conflict-free LDS.64
// (bank-pair = 4*qc + qr, distinct per half-warp phase).
__global__ __launch_bounds__(256) void k3_conv2_mma(
    const float* __restrict__ cb, const float* __restrict__ bg,
    const float* __restrict__ bb, const float* __restrict__ bm,
    const float* __restrict__ bv)
{
    __shared__ float sA[8 * 260];        // 8 cins x 10 rows x 26 cols (8320 B)
    __shared__ float2 sB[9 * 8 * 68];    // [tap*8+ci][cout64] (hi,lo)  (39168 B)
    __shared__ float sSc[64], sSh[64];

    int n = blockIdx.x;
    int y0g = blockIdx.y;              // 0..2  -> rows y0g*8 .. +7
    int coutbase = blockIdx.z * 64;    // 0 or 64
    int tid = threadIdx.x;
    int lane = tid & 31, warp = tid >> 5;
    int wm = warp & 3, wn = warp >> 2; // 4 x 2 warp grid
    int qr = lane >> 2, qc = lane & 3;

    if (tid < 64) {
        int oc = coutbase + tid;
        float sc = bg[oc] * rsqrtf(bv[oc] + 1e-5f);
        sSc[tid] = sc;
        sSh[tid] = (cb[oc] - bm[oc]) * sc + bb[oc];
    }

    int offr[3], offr8[3];
#pragma unroll
    for (int mf = 0; mf < 3; mf++) {
        int p = wm * 48 + mf * 16 + qr;
        offr[mf] = (p / 24) * 26 + (p % 24);
        int p8 = p + 8;
        offr8[mf] = (p8 / 24) * 26 + (p8 % 24);
    }

    float acc[3][4][4];
#pragma unroll
    for (int mf = 0; mf < 3; mf++)
#pragma unroll
        for (int nf = 0; nf < 4; nf++)
#pragma unroll
            for (int i = 0; i < 4; i++) acc[mf][nf][i] = 0.f;

    int y0 = y0g * 8;
    const float* pbase = g_p1 + n * 128 * 676 + y0 * 26;

    for (int cb8 = 0; cb8 < 128; cb8 += 8) {
        __syncthreads();
        // stage A: 8 planes, 10 rows x 26 cols each
        for (int i = tid; i < 2080; i += 256) {
            int ci = i / 260, r = i - ci * 260;
            sA[i] = pbase[(cb8 + ci) * 676 + r];
        }
        // stage B: pre-split interleaved weights (coalesced 8B along cout)
        for (int i = tid; i < 4608; i += 256) {
            int co = i & 63;
            int r = i >> 6;               // tap*8+ci
            int ci = r & 7, tap = r >> 3;
            sB[r * 68 + co] = g_w2hl[(tap * 128 + cb8 + ci) * 128 + coutbase + co];
        }
        __syncthreads();
#pragma unroll
        for (int tap = 0; tap < 9; tap++) {
            int toff = (tap / 3) * 26 + (tap % 3);
            uint32_t a[3][4];
#pragma unroll
            for (int mf = 0; mf < 3; mf++) {
                a[mf][0] = __float_as_uint(sA[qc * 260 + offr[mf] + toff]);
                a[mf][1] = __float_as_uint(sA[qc * 260 + offr8[mf] + toff]);
                a[mf][2] = __float_as_uint(sA[(qc + 4) * 260 + offr[mf] + toff]);
                a[mf][3] = __float_as_uint(sA[(qc + 4) * 260 + offr8[mf] + toff]);
            }
#pragma unroll
            for (int nf = 0; nf < 4; nf++) {
                int ncol = wn * 32 + nf * 8 + qr;
                float2 b0 = sB[(tap * 8 + qc) * 68 + ncol];
                float2 b1 = sB[(tap * 8 + qc + 4) * 68 + ncol];
                uint32_t bh0 = __float_as_uint(b0.x);
                uint32_t bh1 = __float_as_uint(b1.x);
                uint32_t bl0 = __float_as_uint(b0.y);
                uint32_t bl1 = __float_as_uint(b1.y);
#pragma unroll
                for (int mf = 0; mf < 3; mf++) {
                    mma_tf32(acc[mf][nf], a[mf], bh0, bh1);
                    mma_tf32(acc[mf][nf], a[mf], bl0, bl1);
                }
            }
        }
    }

    // epilogue: BN + scatter to g_c2 [n][cout][576]
    float* op = g_c2 + (n * 128 + coutbase) * 576 + y0g * 192;
#pragma unroll
    for (int mf = 0; mf < 3; mf++) {
        int p = wm * 48 + mf * 16 + qr;
#pragma unroll
        for (int nf = 0; nf < 4; nf++) {
            int L = wn * 32 + nf * 8 + qc * 2;
            float sc0 = sSc[L], sh0 = sSh[L];
            float sc1 = sSc[L + 1], sh1 = sSh[L + 1];
            op[L * 576 + p]           = acc[mf][nf][0] * sc0 + sh0;
            op[(L + 1) * 576 + p]     = acc[mf][nf][1] * sc1 + sh1;
            op[L * 576 + p + 8]       = acc[mf][nf][2] * sc0 + sh0;
            op[(L + 1) * 576 + p + 8] = acc[mf][nf][3] * sc1 + sh1;
        }
    }
}

// ---------------- K4: IF2 + 2x2 maxpool + flatten ----------------
__global__ __launch_bounds__(256) void k4_if2_pool()
{
    int idx = blockIdx.x * 256 + threadIdx.x;  // 589,824 exact
    int ox = idx % 12;
    int t1 = idx / 12;
    int oy = t1 % 12;
    int t2 = t1 / 12;
    int c = t2 & 127;
    int b = t2 >> 7;
    float v0 = 0.f, v1 = 0.f, v2 = 0.f, v3 = 0.f;
    int fo = c * 144 + oy * 12 + ox;
#pragma unroll
    for (int t = 0; t < 8; t++) {
        const float* cp = g_c2 + ((t * 32 + b) * 128 + c) * 576 + (2 * oy) * 24 + 2 * ox;
        v0 += cp[0]; v1 += cp[1]; v2 += cp[24]; v3 += cp[25];
        float s0 = v0 >= 1.f ? 1.f : 0.f; v0 = v0 >= 1.f ? 0.f : v0;
        float s1 = v1 >= 1.f ? 1.f : 0.f; v1 = v1 >= 1.f ? 0.f : v1;
        float s2 = v2 >= 1.f ? 1.f : 0.f; v2 = v2 >= 1.f ? 0.f : v2;
        float s3 = v3 >= 1.f ? 1.f : 0.f; v3 = v3 >= 1.f ? 0.f : v3;
        g_f[(t * 32 + b) * 18432 + fo] = fmaxf(fmaxf(s0, s1), fmaxf(s2, s3));
    }
}

// ---------------- K5: fc1 GEMM, tf32 mma, split-K=8 ----------------
__global__ __launch_bounds__(256) void k5_fc1_mma(const float* __restrict__ w1)
{
    __shared__ float sA[16 * 264];   // [k][m], stride 264 (8 mod 32 -> conflict-free)
    __shared__ float sBh[16 * 72];   // [k][n], stride 72 (8 mod 32)
    __shared__ float sBl[16 * 72];
    int n0 = blockIdx.x * 64;
    int z = blockIdx.y;
    int tid = threadIdx.x;
    int lane = tid & 31, warp = tid >> 5;
    int wm = warp & 3, wn = warp >> 2;
    int qr = lane >> 2, qc = lane & 3;

    float acc[4][4][4];
#pragma unroll
    for (int mf = 0; mf < 4; mf++)
#pragma unroll
        for (int nf = 0; nf < 4; nf++)
#pragma unroll
            for (int i = 0; i < 4; i++) acc[mf][nf][i] = 0.f;

    int kbase = z * 2304;
    for (int kc = 0; kc < 144; kc++) {
        int k0 = kbase + kc * 16;
        __syncthreads();
        for (int v = tid; v < 1024; v += 256) {
            int m = v >> 2;
            int kq = (v & 3) * 4;
            float4 a = *(const float4*)(g_f + m * 18432 + k0 + kq);
            sA[(kq + 0) * 264 + m] = a.x;
            sA[(kq + 1) * 264 + m] = a.y;
            sA[(kq + 2) * 264 + m] = a.z;
            sA[(kq + 3) * 264 + m] = a.w;
        }
        {
            int nr = tid >> 2;
            int kq = (tid & 3) * 4;
            float4 b = *(const float4*)(w1 + (n0 + nr) * 18432 + k0 + kq);
            float bx[4] = {b.x, b.y, b.z, b.w};
#pragma unroll
            for (int i = 0; i < 4; i++) {
                uint32_t hb = f2tf32(bx[i]);
                float hf = __uint_as_float(hb);
                sBh[(kq + i) * 72 + nr] = hf;
                sBl[(kq + i) * 72 + nr] = __uint_as_float(f2tf32(bx[i] - hf));
            }
        }
        __syncthreads();
#pragma unroll
        for (int ks = 0; ks < 2; ks++) {
            uint32_t a[4][4];
#pragma unroll
            for (int mf = 0; mf < 4; mf++) {
                int m = wm * 64 + mf * 16 + qr;
                a[mf][0] = __float_as_uint(sA[(ks * 8 + qc) * 264 + m]);
                a[mf][1] = __float_as_uint(sA[(ks * 8 + qc) * 264 + m + 8]);
                a[mf][2] = __float_as_uint(sA[(ks * 8 + qc + 4) * 264 + m]);
                a[mf][3] = __float_as_uint(sA[(ks * 8 + qc + 4) * 264 + m + 8]);
            }
#pragma unroll
            for (int nf = 0; nf < 4; nf++) {
                int nn = wn * 32 + nf * 8 + qr;
                uint32_t bh0 = __float_as_uint(sBh[(ks * 8 + qc) * 72 + nn]);
                uint32_t bh1 = __float_as_uint(sBh[(ks * 8 + qc + 4) * 72 + nn]);
                uint32_t bl0 = __float_as_uint(sBl[(ks * 8 + qc) * 72 + nn]);
                uint32_t bl1 = __float_as_uint(sBl[(ks * 8 + qc + 4) * 72 + nn]);
#pragma unroll
                for (int mf = 0; mf < 4; mf++) {
                    mma_tf32(acc[mf][nf], a[mf], bh0, bh1);
                    mma_tf32(acc[mf][nf], a[mf], bl0, bl1);
                }
            }
        }
    }

    float* op = g_y1p + z * 294912;
#pragma unroll
    for (int mf = 0; mf < 4; mf++) {
        int m = wm * 64 + mf * 16 + qr;
#pragma unroll
        for (int nf = 0; nf < 4; nf++) {
            int nn = n0 + wn * 32 + nf * 8 + qc * 2;
            op[m * 1152 + nn]           = acc[mf][nf][0];
            op[m * 1152 + nn + 1]       = acc[mf][nf][1];
            op[(m + 8) * 1152 + nn]     = acc[mf][nf][2];
            op[(m + 8) * 1152 + nn + 1] = acc[mf][nf][3];
        }
    }
}

// ---------------- K6: reduce split-K(8) + bias + LIF1 ----------------
__global__ __launch_bounds__(256) void k6_lif1(const float* __restrict__ bias)
{
    int idx = blockIdx.x * 256 + threadIdx.x;  // 36,864 exact
    int o = idx % 1152, b = idx / 1152;
    float bi = bias[o];
    float v = 0.f;
#pragma unroll
    for (int t = 0; t < 8; t++) {
        int row = (t * 32 + b) * 1152 + o;
        float xx = bi;
#pragma unroll
        for (int z = 0; z < 8; z++) xx += g_y1p[z * 294912 + row];
        v += (xx - v) * 0.5f;
        float s = v >= 1.f ? 1.f : 0.f;
        g_l1[row] = s;
        v = v >= 1.f ? 0.f : v;
    }
}

// ---------------- K7: fc2 ----------------
__global__ __launch_bounds__(128) void k7_fc2(const float* __restrict__ w,
                                              const float* __restrict__ bias)
{
    __shared__ float row[1152];
    int r = blockIdx.x, o = threadIdx.x;
    for (int i = o; i < 1152; i += 128) row[i] = g_l1[r * 1152 + i];
    __syncthreads();
    const float4* wp = (const float4*)(w + o * 1152);
    float acc = 0.f;
#pragma unroll 4
    for (int k = 0; k < 288; k++) {
        float4 wv = wp[k];
        acc += row[4 * k] * wv.x + row[4 * k + 1] * wv.y
             + row[4 * k + 2] * wv.z + row[4 * k + 3] * wv.w;
    }
    g_y2[r * 128 + o] = acc + bias[o];
}

// ---------------- K8: LIF2 ----------------
__global__ __launch_bounds__(256) void k8_lif2()
{
    int idx = blockIdx.x * 256 + threadIdx.x;  // 4096 exact
    int o = idx & 127, b = idx >> 7;
    float v = 0.f;
#pragma unroll
    for (int t = 0; t < 8; t++) {
        int row = (t * 32 + b) * 128 + o;
        float xx = g_y2[row];
        v += (xx - v) * 0.5f;
        float s = v >= 1.f ? 1.f : 0.f;
        g_l2[row] = s;
        v = v >= 1.f ? 0.f : v;
    }
}

// ---------------- K9: fc3 + LIF3 + mean over T ----------------
__global__ __launch_bounds__(256) void k9_fc3(const float* __restrict__ w,
                                              const float* __restrict__ bias,
                                              float* __restrict__ out)
{
    int idx = threadIdx.x;
    if (idx >= 224) return;
    int o = idx % 7, b = idx / 7;
    const float4* wp = (const float4*)(w + o * 128);
    float v = 0.f, accm = 0.f;
    float bi = bias[o];
    for (int t = 0; t < 8; t++) {
        const float4* lp = (const float4*)(g_l2 + (t * 32 + b) * 128);
        float y = 0.f;
#pragma unroll
        for (int k = 0; k < 32; k++) {
            float4 a = lp[k], ww = wp[k];
            y += a.x * ww.x + a.y * ww.y + a.z * ww.z + a.w * ww.w;
        }
        y += bi;
        v += (y - v) * 0.5f;
        float s = v >= 1.f ? 1.f : 0.f;
        accm += s;
        v = v >= 1.f ? 0.f : v;
    }
    out[b * 7 + o] = accm * 0.125f;
}

// ---------------- launch ----------------
extern "C" void kernel_launch(void* const* d_in, const int* in_sizes, int n_in,
                              void* d_out, int out_size)
{
    const float* x       = (const float*)d_in[0];
    const float* conv1_w = (const float*)d_in[1];
    const float* conv1_b = (const float*)d_in[2];
    const float* bn1_g   = (const float*)d_in[3];
    const float* bn1_b   = (const float*)d_in[4];
    const float* bn1_m   = (const float*)d_in[5];
    const float* bn1_v   = (const float*)d_in[6];
    const float* conv2_w = (const float*)d_in[7];
    const float* conv2_b = (const float*)d_in[8];
    const float* bn2_g   = (const float*)d_in[9];
    const float* bn2_b   = (const float*)d_in[10];
    const float* bn2_m   = (const float*)d_in[11];
    const float* bn2_v   = (const float*)d_in[12];
    const float* fc1_w   = (const float*)d_in[13];
    const float* fc1_b   = (const float*)d_in[14];
    const float* fc2_w   = (const float*)d_in[15];
    const float* fc2_b   = (const float*)d_in[16];
    const float* fc3_w   = (const float*)d_in[17];
    const float* fc3_b   = (const float*)d_in[18];

    // encourage max smem carveout so 2 CTAs of k3 (2x47KB) can be resident
    static bool attr_done = false;
    if (!attr_done) {
        cudaFuncSetAttribute(k3_conv2_mma,
                             cudaFuncAttributePreferredSharedMemoryCarveout, 100);
        cudaFuncSetAttribute(k5_fc1_mma,
                             cudaFuncAttributePreferredSharedMemoryCarveout, 100);
        attr_done = true;
    }

    // zero padded p1 borders (interior overwritten by K2)
    void* p1ptr = nullptr;
    cudaGetSymbolAddress(&p1ptr, g_p1);
    cudaMemsetAsync(p1ptr, 0, sizeof(g_p1));

    k0_split_w2<<<576, 256>>>(conv2_w);
    k1_conv1bn<<<32 * 128, 256>>>(x, conv1_w, conv1_b, bn1_g, bn1_b, bn1_m, bn1_v);
    k2_if_pool<<<9216, 256>>>();
    dim3 g3(NTB, 3, 2);
    k3_conv2_mma<<<g3, 256>>>(conv2_b, bn2_g, bn2_b, bn2_m, bn2_v);
    k4_if2_pool<<<2304, 256>>>();
    dim3 g5(18, 8);
    k5_fc1_mma<<<g5, 256>>>(fc1_w);
    k6_lif1<<<144, 256>>>(fc1_b);
    k7_fc2<<<NTB, 128>>>(fc2_w, fc2_b);
    k8_lif2<<<16, 256>>>();
    k9_fc3<<<1, 256>>>(fc3_w, fc3_b, (float*)d_out);
}

// round 5
// speedup vs baseline: 2.1753x; 1.1918x over previous
#include <cuda_runtime.h>
#include <cuda_pipeline.h>
#include <cstdint>

// SJCSNN spiking CNN forward, T=8, B=32, out [32,7] f32.
// conv2 AND fc1 on tensor pipe: tf32 mma.sync, 2-term weight split
// (spike activations are {0,1} -> exact in tf32; weight residual ~2^-21).
// R5: k3 uses cp.async double-buffered staging pipeline.

#define NTB 256  // T*B

// ---- scratch (device globals; no allocations) ----
__device__ float g_h[32 * 128 * 48 * 48];                      // conv1+bn1 output
__device__ __align__(16) float g_p1[NTB * 128 * 26 * 26];      // IF1+pool spikes, PADDED 26x26
__device__ float g_c2[NTB * 128 * 24 * 24];                    // conv2+bn2 output
__device__ __align__(16) float g_f[NTB * 18432];               // IF2+pool spikes, flattened
__device__ float g_y1p[8 * NTB * 1152];                        // fc1 split-K partials (8)
__device__ float g_l1[NTB * 1152];                             // LIF1 spikes
__device__ float g_y2[NTB * 128];                              // fc2 output
__device__ float g_l2[NTB * 128];                              // LIF2 spikes
__device__ __align__(16) float2 g_w2hl[9 * 128 * 128];         // conv2 W (hi,lo), [tap][cin][cout]

// ---------------- tf32 mma helpers ----------------
__device__ __forceinline__ uint32_t f2tf32(float f) {
    uint32_t r;
    asm("cvt.rna.tf32.f32 %0, %1;" : "=r"(r) : "f"(f));
    return r;
}
__device__ __forceinline__ void mma_tf32(float c[4], const uint32_t a[4],
                                         uint32_t b0, uint32_t b1) {
    asm volatile(
        "mma.sync.aligned.m16n8k8.row.col.f32.tf32.tf32.f32 "
        "{%0,%1,%2,%3}, {%4,%5,%6,%7}, {%8,%9}, {%0,%1,%2,%3};"
        : "+f"(c[0]), "+f"(c[1]), "+f"(c[2]), "+f"(c[3])
        : "r"(a[0]), "r"(a[1]), "r"(a[2]), "r"(a[3]), "r"(b0), "r"(b1));
}

// ---------------- K0: precompute conv2 weight split (interleaved) ----------------
__global__ __launch_bounds__(256) void k0_split_w2(const float* __restrict__ w2)
{
    int i = blockIdx.x * 256 + threadIdx.x;  // 147456 exact
    int co = i / 1152;
    int rem = i - co * 1152;
    int ci = rem / 9, tap = rem - ci * 9;
    float w = w2[i];
    uint32_t hb = f2tf32(w);
    float hf = __uint_as_float(hb);
    uint32_t lb = f2tf32(w - hf);
    g_w2hl[(tap * 128 + ci) * 128 + co] = make_float2(hf, __uint_as_float(lb));
}

// ---------------- K1: conv1 (1->128, 3x3 SAME) + BN1 ----------------
__global__ __launch_bounds__(256) void k1_conv1bn(
    const float* __restrict__ x, const float* __restrict__ w,
    const float* __restrict__ cb, const float* __restrict__ bg,
    const float* __restrict__ bb, const float* __restrict__ bm,
    const float* __restrict__ bv)
{
    __shared__ float s[2500];  // 50*50 padded
    int b = blockIdx.x >> 7, c = blockIdx.x & 127;
    int tid = threadIdx.x;
    for (int i = tid; i < 2500; i += 256) s[i] = 0.0f;
    __syncthreads();
    const float* xp = x + b * 2304;
    for (int i = tid; i < 2304; i += 256) {
        int r = i / 48, q = i - r * 48;
        s[(r + 1) * 50 + q + 1] = xp[i];
    }
    __syncthreads();
    float wr[9];
#pragma unroll
    for (int k = 0; k < 9; k++) wr[k] = w[c * 9 + k];
    float sc = bg[c] * rsqrtf(bv[c] + 1e-5f);
    float sh = (cb[c] - bm[c]) * sc + bb[c];
    float* hp = g_h + (b * 128 + c) * 2304;
    for (int p = tid; p < 2304; p += 256) {
        int y = p / 48, xx = p - y * 48;
        const float* sp = s + y * 50 + xx;
        float a = sp[0] * wr[0] + sp[1] * wr[1] + sp[2] * wr[2]
                + sp[50] * wr[3] + sp[51] * wr[4] + sp[52] * wr[5]
                + sp[100] * wr[6] + sp[101] * wr[7] + sp[102] * wr[8];
        hp[p] = a * sc + sh;
    }
}

// ---------------- K2: IF1 + 2x2 maxpool ----------------
__global__ __launch_bounds__(256) void k2_if_pool()
{
    int idx = blockIdx.x * 256 + threadIdx.x;  // 2,359,296 exact
    int ox = idx % 24;
    int t1 = idx / 24;
    int oy = t1 % 24;
    int t2 = t1 / 24;
    int c = t2 & 127;
    int b = t2 >> 7;
    const float* hp = g_h + (b * 128 + c) * 2304 + (2 * oy) * 48 + 2 * ox;
    float h0 = hp[0], h1 = hp[1], h2 = hp[48], h3 = hp[49];
    float v0 = 0.f, v1 = 0.f, v2 = 0.f, v3 = 0.f;
    int pin = c * 676 + (oy + 1) * 26 + ox + 1;
#pragma unroll
    for (int t = 0; t < 8; t++) {
        v0 += h0; v1 += h1; v2 += h2; v3 += h3;
        float s0 = v0 >= 1.f ? 1.f : 0.f; v0 = v0 >= 1.f ? 0.f : v0;
        float s1 = v1 >= 1.f ? 1.f : 0.f; v1 = v1 >= 1.f ? 0.f : v1;
        float s2 = v2 >= 1.f ? 1.f : 0.f; v2 = v2 >= 1.f ? 0.f : v2;
        float s3 = v3 >= 1.f ? 1.f : 0.f; v3 = v3 >= 1.f ? 0.f : v3;
        float mx = fmaxf(fmaxf(s0, s1), fmaxf(s2, s3));
        g_p1[(t * 32 + b) * 128 * 676 + pin] = mx;
    }
}

// ---------------- K3: conv2 + BN2, tf32 mma, cp.async double-buffered ----------------
// Block: image n, 8 output rows (192 px), 64 couts. 16 chunks of (8 cin x 9 taps).
// 8 warps 4(M)x2(N); warp tile m48 x n32; mma m16n8k8, pre-split interleaved weights.
// Dynamic smem: sA 2x2080 f, sB 2x4896 float2 (stride 68 -> conflict-free), + BN.
__global__ __launch_bounds__(256) void k3_conv2_mma(
    const float* __restrict__ cb, const float* __restrict__ bg,
    const float* __restrict__ bb, const float* __restrict__ bm,
    const float* __restrict__ bv)
{
    extern __shared__ float dyn[];
    float* sA0 = dyn;                          // 2 x 2080 floats
    float2* sB0 = (float2*)(dyn + 4160);       // 2 x 4896 float2
    float* sSc = dyn + 4160 + 19584;           // 64
    float* sSh = sSc + 64;                     // 64

    int n = blockIdx.x;
    int y0g = blockIdx.y;              // 0..2  -> rows y0g*8 .. +7
    int coutbase = blockIdx.z * 64;    // 0 or 64
    int tid = threadIdx.x;
    int lane = tid & 31, warp = tid >> 5;
    int wm = warp & 3, wn = warp >> 2; // 4 x 2 warp grid
    int qr = lane >> 2, qc = lane & 3;

    if (tid < 64) {
        int oc = coutbase + tid;
        float sc = bg[oc] * rsqrtf(bv[oc] + 1e-5f);
        sSc[tid] = sc;
        sSh[tid] = (cb[oc] - bm[oc]) * sc + bb[oc];
    }

    int offr[3], offr8[3];
#pragma unroll
    for (int mf = 0; mf < 3; mf++) {
        int p = wm * 48 + mf * 16 + qr;
        offr[mf] = (p / 24) * 26 + (p % 24);
        int p8 = p + 8;
        offr8[mf] = (p8 / 24) * 26 + (p8 % 24);
    }

    float acc[3][4][4];
#pragma unroll
    for (int mf = 0; mf < 3; mf++)
#pragma unroll
        for (int nf = 0; nf < 4; nf++)
#pragma unroll
            for (int i = 0; i < 4; i++) acc[mf][nf][i] = 0.f;

    int y0 = y0g * 8;
    const float* pbase = g_p1 + n * 128 * 676 + y0 * 26;

    // ---- async staging of one chunk (8 cins) into buffer buf ----
    auto issue = [&](int chunk, int buf) {
        float* sAb = sA0 + buf * 2080;
        float2* sBb = sB0 + buf * 4896;
        int cb8 = chunk * 8;
        // A: 8 planes x 260 contiguous floats = 520 x 16B
        for (int i = tid; i < 520; i += 256) {
            int ci = i / 65, q = i - ci * 65;
            __pipeline_memcpy_async(sAb + ci * 260 + q * 4,
                                    pbase + (cb8 + ci) * 676 + q * 4, 16);
        }
        // B: 72 rows x 64 couts of float2 (coalesced 8B)
        for (int i = tid; i < 4608; i += 256) {
            int co = i & 63;
            int r = i >> 6;               // tap*8+ci
            int ci = r & 7, tap = r >> 3;
            __pipeline_memcpy_async(sBb + r * 68 + co,
                                    g_w2hl + (tap * 128 + cb8 + ci) * 128 + coutbase + co,
                                    8);
        }
        __pipeline_commit();
    };

    issue(0, 0);
    for (int c = 0; c < 16; c++) {
        if (c < 15) {
            issue(c + 1, (c + 1) & 1);
            __pipeline_wait_prior(1);
        } else {
            __pipeline_wait_prior(0);
        }
        __syncthreads();
        const float* sAb = sA0 + (c & 1) * 2080;
        const float2* sBb = sB0 + (c & 1) * 4896;
#pragma unroll
        for (int tap = 0; tap < 9; tap++) {
            int toff = (tap / 3) * 26 + (tap % 3);
            uint32_t a[3][4];
#pragma unroll
            for (int mf = 0; mf < 3; mf++) {
                a[mf][0] = __float_as_uint(sAb[qc * 260 + offr[mf] + toff]);
                a[mf][1] = __float_as_uint(sAb[qc * 260 + offr8[mf] + toff]);
                a[mf][2] = __float_as_uint(sAb[(qc + 4) * 260 + offr[mf] + toff]);
                a[mf][3] = __float_as_uint(sAb[(qc + 4) * 260 + offr8[mf] + toff]);
            }
#pragma unroll
            for (int nf = 0; nf < 4; nf++) {
                int ncol = wn * 32 + nf * 8 + qr;
                float2 b0 = sBb[(tap * 8 + qc) * 68 + ncol];
                float2 b1 = sBb[(tap * 8 + qc + 4) * 68 + ncol];
                uint32_t bh0 = __float_as_uint(b0.x);
                uint32_t bh1 = __float_as_uint(b1.x);
                uint32_t bl0 = __float_as_uint(b0.y);
                uint32_t bl1 = __float_as_uint(b1.y);
#pragma unroll
                for (int mf = 0; mf < 3; mf++) {
                    mma_tf32(acc[mf][nf], a[mf], bh0, bh1);
                    mma_tf32(acc[mf][nf], a[mf], bl0, bl1);
                }
            }
        }
        __syncthreads();
    }

    // epilogue: BN + scatter to g_c2 [n][cout][576]
    float* op = g_c2 + (n * 128 + coutbase) * 576 + y0g * 192;
#pragma unroll
    for (int mf = 0; mf < 3; mf++) {
        int p = wm * 48 + mf * 16 + qr;
#pragma unroll
        for (int nf = 0; nf < 4; nf++) {
            int L = wn * 32 + nf * 8 + qc * 2;
            float sc0 = sSc[L], sh0 = sSh[L];
            float sc1 = sSc[L + 1], sh1 = sSh[L + 1];
            op[L * 576 + p]           = acc[mf][nf][0] * sc0 + sh0;
            op[(L + 1) * 576 + p]     = acc[mf][nf][1] * sc1 + sh1;
            op[L * 576 + p + 8]       = acc[mf][nf][2] * sc0 + sh0;
            op[(L + 1) * 576 + p + 8] = acc[mf][nf][3] * sc1 + sh1;
        }
    }
}

// ---------------- K4: IF2 + 2x2 maxpool + flatten ----------------
__global__ __launch_bounds__(256) void k4_if2_pool()
{
    int idx = blockIdx.x * 256 + threadIdx.x;  // 589,824 exact
    int ox = idx % 12;
    int t1 = idx / 12;
    int oy = t1 % 12;
    int t2 = t1 / 12;
    int c = t2 & 127;
    int b = t2 >> 7;
    float v0 = 0.f, v1 = 0.f, v2 = 0.f, v3 = 0.f;
    int fo = c * 144 + oy * 12 + ox;
#pragma unroll
    for (int t = 0; t < 8; t++) {
        const float* cp = g_c2 + ((t * 32 + b) * 128 + c) * 576 + (2 * oy) * 24 + 2 * ox;
        v0 += cp[0]; v1 += cp[1]; v2 += cp[24]; v3 += cp[25];
        float s0 = v0 >= 1.f ? 1.f : 0.f; v0 = v0 >= 1.f ? 0.f : v0;
        float s1 = v1 >= 1.f ? 1.f : 0.f; v1 = v1 >= 1.f ? 0.f : v1;
        float s2 = v2 >= 1.f ? 1.f : 0.f; v2 = v2 >= 1.f ? 0.f : v2;
        float s3 = v3 >= 1.f ? 1.f : 0.f; v3 = v3 >= 1.f ? 0.f : v3;
        g_f[(t * 32 + b) * 18432 + fo] = fmaxf(fmaxf(s0, s1), fmaxf(s2, s3));
    }
}

// ---------------- K5: fc1 GEMM, tf32 mma, split-K=8 ----------------
__global__ __launch_bounds__(256) void k5_fc1_mma(const float* __restrict__ w1)
{
    __shared__ float sA[16 * 264];   // [k][m], stride 264 (8 mod 32 -> conflict-free)
    __shared__ float sBh[16 * 72];   // [k][n], stride 72 (8 mod 32)
    __shared__ float sBl[16 * 72];
    int n0 = blockIdx.x * 64;
    int z = blockIdx.y;
    int tid = threadIdx.x;
    int lane = tid & 31, warp = tid >> 5;
    int wm = warp & 3, wn = warp >> 2;
    int qr = lane >> 2, qc = lane & 3;

    float acc[4][4][4];
#pragma unroll
    for (int mf = 0; mf < 4; mf++)
#pragma unroll
        for (int nf = 0; nf < 4; nf++)
#pragma unroll
            for (int i = 0; i < 4; i++) acc[mf][nf][i] = 0.f;

    int kbase = z * 2304;
    for (int kc = 0; kc < 144; kc++) {
        int k0 = kbase + kc * 16;
        __syncthreads();
        for (int v = tid; v < 1024; v += 256) {
            int m = v >> 2;
            int kq = (v & 3) * 4;
            float4 a = *(const float4*)(g_f + m * 18432 + k0 + kq);
            sA[(kq + 0) * 264 + m] = a.x;
            sA[(kq + 1) * 264 + m] = a.y;
            sA[(kq + 2) * 264 + m] = a.z;
            sA[(kq + 3) * 264 + m] = a.w;
        }
        {
            int nr = tid >> 2;
            int kq = (tid & 3) * 4;
            float4 b = *(const float4*)(w1 + (n0 + nr) * 18432 + k0 + kq);
            float bx[4] = {b.x, b.y, b.z, b.w};
#pragma unroll
            for (int i = 0; i < 4; i++) {
                uint32_t hb = f2tf32(bx[i]);
                float hf = __uint_as_float(hb);
                sBh[(kq + i) * 72 + nr] = hf;
                sBl[(kq + i) * 72 + nr] = __uint_as_float(f2tf32(bx[i] - hf));
            }
        }
        __syncthreads();
#pragma unroll
        for (int ks = 0; ks < 2; ks++) {
            uint32_t a[4][4];
#pragma unroll
            for (int mf = 0; mf < 4; mf++) {
                int m = wm * 64 + mf * 16 + qr;
                a[mf][0] = __float_as_uint(sA[(ks * 8 + qc) * 264 + m]);
                a[mf][1] = __float_as_uint(sA[(ks * 8 + qc) * 264 + m + 8]);
                a[mf][2] = __float_as_uint(sA[(ks * 8 + qc + 4) * 264 + m]);
                a[mf][3] = __float_as_uint(sA[(ks * 8 + qc + 4) * 264 + m + 8]);
            }
#pragma unroll
            for (int nf = 0; nf < 4; nf++) {
                int nn = wn * 32 + nf * 8 + qr;
                uint32_t bh0 = __float_as_uint(sBh[(ks * 8 + qc) * 72 + nn]);
                uint32_t bh1 = __float_as_uint(sBh[(ks * 8 + qc + 4) * 72 + nn]);
                uint32_t bl0 = __float_as_uint(sBl[(ks * 8 + qc) * 72 + nn]);
                uint32_t bl1 = __float_as_uint(sBl[(ks * 8 + qc + 4) * 72 + nn]);
#pragma unroll
                for (int mf = 0; mf < 4; mf++) {
                    mma_tf32(acc[mf][nf], a[mf], bh0, bh1);
                    mma_tf32(acc[mf][nf], a[mf], bl0, bl1);
                }
            }
        }
    }

    float* op = g_y1p + z * 294912;
#pragma unroll
    for (int mf = 0; mf < 4; mf++) {
        int m = wm * 64 + mf * 16 + qr;
#pragma unroll
        for (int nf = 0; nf < 4; nf++) {
            int nn = n0 + wn * 32 + nf * 8 + qc * 2;
            op[m * 1152 + nn]           = acc[mf][nf][0];
            op[m * 1152 + nn + 1]       = acc[mf][nf][1];
            op[(m + 8) * 1152 + nn]     = acc[mf][nf][2];
            op[(m + 8) * 1152 + nn + 1] = acc[mf][nf][3];
        }
    }
}

// ---------------- K6: reduce split-K(8) + bias + LIF1 ----------------
__global__ __launch_bounds__(256) void k6_lif1(const float* __restrict__ bias)
{
    int idx = blockIdx.x * 256 + threadIdx.x;  // 36,864 exact
    int o = idx % 1152, b = idx / 1152;
    float bi = bias[o];
    float v = 0.f;
#pragma unroll
    for (int t = 0; t < 8; t++) {
        int row = (t * 32 + b) * 1152 + o;
        float xx = bi;
#pragma unroll
        for (int z = 0; z < 8; z++) xx += g_y1p[z * 294912 + row];
        v += (xx - v) * 0.5f;
        float s = v >= 1.f ? 1.f : 0.f;
        g_l1[row] = s;
        v = v >= 1.f ? 0.f : v;
    }
}

// ---------------- K7: fc2 ----------------
__global__ __launch_bounds__(128) void k7_fc2(const float* __restrict__ w,
                                              const float* __restrict__ bias)
{
    __shared__ float row[1152];
    int r = blockIdx.x, o = threadIdx.x;
    for (int i = o; i < 1152; i += 128) row[i] = g_l1[r * 1152 + i];
    __syncthreads();
    const float4* wp = (const float4*)(w + o * 1152);
    float acc = 0.f;
#pragma unroll 4
    for (int k = 0; k < 288; k++) {
        float4 wv = wp[k];
        acc += row[4 * k] * wv.x + row[4 * k + 1] * wv.y
             + row[4 * k + 2] * wv.z + row[4 * k + 3] * wv.w;
    }
    g_y2[r * 128 + o] = acc + bias[o];
}

// ---------------- K8: LIF2 ----------------
__global__ __launch_bounds__(256) void k8_lif2()
{
    int idx = blockIdx.x * 256 + threadIdx.x;  // 4096 exact
    int o = idx & 127, b = idx >> 7;
    float v = 0.f;
#pragma unroll
    for (int t = 0; t < 8; t++) {
        int row = (t * 32 + b) * 128 + o;
        float xx = g_y2[row];
        v += (xx - v) * 0.5f;
        float s = v >= 1.f ? 1.f : 0.f;
        g_l2[row] = s;
        v = v >= 1.f ? 0.f : v;
    }
}

// ---------------- K9: fc3 + LIF3 + mean over T ----------------
__global__ __launch_bounds__(256) void k9_fc3(const float* __restrict__ w,
                                              const float* __restrict__ bias,
                                              float* __restrict__ out)
{
    int idx = threadIdx.x;
    if (idx >= 224) return;
    int o = idx % 7, b = idx / 7;
    const float4* wp = (const float4*)(w + o * 128);
    float v = 0.f, accm = 0.f;
    float bi = bias[o];
    for (int t = 0; t < 8; t++) {
        const float4* lp = (const float4*)(g_l2 + (t * 32 + b) * 128);
        float y = 0.f;
#pragma unroll
        for (int k = 0; k < 32; k++) {
            float4 a = lp[k], ww = wp[k];
            y += a.x * ww.x + a.y * ww.y + a.z * ww.z + a.w * ww.w;
        }
        y += bi;
        v += (y - v) * 0.5f;
        float s = v >= 1.f ? 1.f : 0.f;
        accm += s;
        v = v >= 1.f ? 0.f : v;
    }
    out[b * 7 + o] = accm * 0.125f;
}

// ---------------- launch ----------------
#define K3_SMEM (4160 * 4 + 4896 * 2 * 8 + 128 * 4)  // 95488 B

extern "C" void kernel_launch(void* const* d_in, const int* in_sizes, int n_in,
                              void* d_out, int out_size)
{
    const float* x       = (const float*)d_in[0];
    const float* conv1_w = (const float*)d_in[1];
    const float* conv1_b = (const float*)d_in[2];
    const float* bn1_g   = (const float*)d_in[3];
    const float* bn1_b   = (const float*)d_in[4];
    const float* bn1_m   = (const float*)d_in[5];
    const float* bn1_v   = (const float*)d_in[6];
    const float* conv2_w = (const float*)d_in[7];
    const float* conv2_b = (const float*)d_in[8];
    const float* bn2_g   = (const float*)d_in[9];
    const float* bn2_b   = (const float*)d_in[10];
    const float* bn2_m   = (const float*)d_in[11];
    const float* bn2_v   = (const float*)d_in[12];
    const float* fc1_w   = (const float*)d_in[13];
    const float* fc1_b   = (const float*)d_in[14];
    const float* fc2_w   = (const float*)d_in[15];
    const float* fc2_b   = (const float*)d_in[16];
    const float* fc3_w   = (const float*)d_in[17];
    const float* fc3_b   = (const float*)d_in[18];

    static bool attr_done = false;
    if (!attr_done) {
        cudaFuncSetAttribute(k3_conv2_mma,
                             cudaFuncAttributeMaxDynamicSharedMemorySize, K3_SMEM);
        cudaFuncSetAttribute(k3_conv2_mma,
                             cudaFuncAttributePreferredSharedMemoryCarveout, 100);
        cudaFuncSetAttribute(k5_fc1_mma,
                             cudaFuncAttributePreferredSharedMemoryCarveout, 100);
        attr_done = true;
    }

    // zero padded p1 borders (interior overwritten by K2)
    void* p1ptr = nullptr;
    cudaGetSymbolAddress(&p1ptr, g_p1);
    cudaMemsetAsync(p1ptr, 0, sizeof(g_p1));

    k0_split_w2<<<576, 256>>>(conv2_w);
    k1_conv1bn<<<32 * 128, 256>>>(x, conv1_w, conv1_b, bn1_g, bn1_b, bn1_m, bn1_v);
    k2_if_pool<<<9216, 256>>>();
    dim3 g3(NTB, 3, 2);
    k3_conv2_mma<<<g3, 256, K3_SMEM>>>(conv2_b, bn2_g, bn2_b, bn2_m, bn2_v);
    k4_if2_pool<<<2304, 256>>>();
    dim3 g5(18, 8);
    k5_fc1_mma<<<g5, 256>>>(fc1_w);
    k6_lif1<<<144, 256>>>(fc1_b);
    k7_fc2<<<NTB, 128>>>(fc2_w, fc2_b);
    k8_lif2<<<16, 256>>>();
    k9_fc3<<<1, 256>>>(fc3_w, fc3_b, (float*)d_out);
}

// round 6
// speedup vs baseline: 2.8826x; 1.3252x over previous
#include <cuda_runtime.h>
#include <cuda_pipeline.h>
#include <cstdint>

// SJCSNN spiking CNN forward, T=8, B=32, out [32,7] f32.
// conv2 AND fc1 on tensor pipe: tf32 mma.sync, 2-term weight split
// (spike activations are {0,1} -> exact in tf32; weight residual ~2^-21).
// R5: k3 cp.async double-buffered. R6: k5 cp.async double-buffered,
// hi/lo split moved to registers.

#define NTB 256  // T*B

// ---- scratch (device globals; no allocations) ----
__device__ float g_h[32 * 128 * 48 * 48];                      // conv1+bn1 output
__device__ __align__(16) float g_p1[NTB * 128 * 26 * 26];      // IF1+pool spikes, PADDED 26x26
__device__ float g_c2[NTB * 128 * 24 * 24];                    // conv2+bn2 output
__device__ __align__(16) float g_f[NTB * 18432];               // IF2+pool spikes, flattened
__device__ float g_y1p[8 * NTB * 1152];                        // fc1 split-K partials (8)
__device__ float g_l1[NTB * 1152];                             // LIF1 spikes
__device__ float g_y2[NTB * 128];                              // fc2 output
__device__ float g_l2[NTB * 128];                              // LIF2 spikes
__device__ __align__(16) float2 g_w2hl[9 * 128 * 128];         // conv2 W (hi,lo), [tap][cin][cout]

// ---------------- tf32 mma helpers ----------------
__device__ __forceinline__ uint32_t f2tf32(float f) {
    uint32_t r;
    asm("cvt.rna.tf32.f32 %0, %1;" : "=r"(r) : "f"(f));
    return r;
}
__device__ __forceinline__ void mma_tf32(float c[4], const uint32_t a[4],
                                         uint32_t b0, uint32_t b1) {
    asm volatile(
        "mma.sync.aligned.m16n8k8.row.col.f32.tf32.tf32.f32 "
        "{%0,%1,%2,%3}, {%4,%5,%6,%7}, {%8,%9}, {%0,%1,%2,%3};"
        : "+f"(c[0]), "+f"(c[1]), "+f"(c[2]), "+f"(c[3])
        : "r"(a[0]), "r"(a[1]), "r"(a[2]), "r"(a[3]), "r"(b0), "r"(b1));
}

// ---------------- K0: precompute conv2 weight split (interleaved) ----------------
__global__ __launch_bounds__(256) void k0_split_w2(const float* __restrict__ w2)
{
    int i = blockIdx.x * 256 + threadIdx.x;  // 147456 exact
    int co = i / 1152;
    int rem = i - co * 1152;
    int ci = rem / 9, tap = rem - ci * 9;
    float w = w2[i];
    uint32_t hb = f2tf32(w);
    float hf = __uint_as_float(hb);
    uint32_t lb = f2tf32(w - hf);
    g_w2hl[(tap * 128 + ci) * 128 + co] = make_float2(hf, __uint_as_float(lb));
}

// ---------------- K1: conv1 (1->128, 3x3 SAME) + BN1 ----------------
__global__ __launch_bounds__(256) void k1_conv1bn(
    const float* __restrict__ x, const float* __restrict__ w,
    const float* __restrict__ cb, const float* __restrict__ bg,
    const float* __restrict__ bb, const float* __restrict__ bm,
    const float* __restrict__ bv)
{
    __shared__ float s[2500];  // 50*50 padded
    int b = blockIdx.x >> 7, c = blockIdx.x & 127;
    int tid = threadIdx.x;
    for (int i = tid; i < 2500; i += 256) s[i] = 0.0f;
    __syncthreads();
    const float* xp = x + b * 2304;
    for (int i = tid; i < 2304; i += 256) {
        int r = i / 48, q = i - r * 48;
        s[(r + 1) * 50 + q + 1] = xp[i];
    }
    __syncthreads();
    float wr[9];
#pragma unroll
    for (int k = 0; k < 9; k++) wr[k] = w[c * 9 + k];
    float sc = bg[c] * rsqrtf(bv[c] + 1e-5f);
    float sh = (cb[c] - bm[c]) * sc + bb[c];
    float* hp = g_h + (b * 128 + c) * 2304;
    for (int p = tid; p < 2304; p += 256) {
        int y = p / 48, xx = p - y * 48;
        const float* sp = s + y * 50 + xx;
        float a = sp[0] * wr[0] + sp[1] * wr[1] + sp[2] * wr[2]
                + sp[50] * wr[3] + sp[51] * wr[4] + sp[52] * wr[5]
                + sp[100] * wr[6] + sp[101] * wr[7] + sp[102] * wr[8];
        hp[p] = a * sc + sh;
    }
}

// ---------------- K2: IF1 + 2x2 maxpool ----------------
__global__ __launch_bounds__(256) void k2_if_pool()
{
    int idx = blockIdx.x * 256 + threadIdx.x;  // 2,359,296 exact
    int ox = idx % 24;
    int t1 = idx / 24;
    int oy = t1 % 24;
    int t2 = t1 / 24;
    int c = t2 & 127;
    int b = t2 >> 7;
    const float* hp = g_h + (b * 128 + c) * 2304 + (2 * oy) * 48 + 2 * ox;
    float h0 = hp[0], h1 = hp[1], h2 = hp[48], h3 = hp[49];
    float v0 = 0.f, v1 = 0.f, v2 = 0.f, v3 = 0.f;
    int pin = c * 676 + (oy + 1) * 26 + ox + 1;
#pragma unroll
    for (int t = 0; t < 8; t++) {
        v0 += h0; v1 += h1; v2 += h2; v3 += h3;
        float s0 = v0 >= 1.f ? 1.f : 0.f; v0 = v0 >= 1.f ? 0.f : v0;
        float s1 = v1 >= 1.f ? 1.f : 0.f; v1 = v1 >= 1.f ? 0.f : v1;
        float s2 = v2 >= 1.f ? 1.f : 0.f; v2 = v2 >= 1.f ? 0.f : v2;
        float s3 = v3 >= 1.f ? 1.f : 0.f; v3 = v3 >= 1.f ? 0.f : v3;
        float mx = fmaxf(fmaxf(s0, s1), fmaxf(s2, s3));
        g_p1[(t * 32 + b) * 128 * 676 + pin] = mx;
    }
}

// ---------------- K3: conv2 + BN2, tf32 mma, cp.async double-buffered ----------------
__global__ __launch_bounds__(256) void k3_conv2_mma(
    const float* __restrict__ cb, const float* __restrict__ bg,
    const float* __restrict__ bb, const float* __restrict__ bm,
    const float* __restrict__ bv)
{
    extern __shared__ float dyn[];
    float* sA0 = dyn;                          // 2 x 2080 floats
    float2* sB0 = (float2*)(dyn + 4160);       // 2 x 4896 float2
    float* sSc = dyn + 4160 + 19584;           // 64
    float* sSh = sSc + 64;                     // 64

    int n = blockIdx.x;
    int y0g = blockIdx.y;              // 0..2  -> rows y0g*8 .. +7
    int coutbase = blockIdx.z * 64;    // 0 or 64
    int tid = threadIdx.x;
    int lane = tid & 31, warp = tid >> 5;
    int wm = warp & 3, wn = warp >> 2; // 4 x 2 warp grid
    int qr = lane >> 2, qc = lane & 3;

    if (tid < 64) {
        int oc = coutbase + tid;
        float sc = bg[oc] * rsqrtf(bv[oc] + 1e-5f);
        sSc[tid] = sc;
        sSh[tid] = (cb[oc] - bm[oc]) * sc + bb[oc];
    }

    int offr[3], offr8[3];
#pragma unroll
    for (int mf = 0; mf < 3; mf++) {
        int p = wm * 48 + mf * 16 + qr;
        offr[mf] = (p / 24) * 26 + (p % 24);
        int p8 = p + 8;
        offr8[mf] = (p8 / 24) * 26 + (p8 % 24);
    }

    float acc[3][4][4];
#pragma unroll
    for (int mf = 0; mf < 3; mf++)
#pragma unroll
        for (int nf = 0; nf < 4; nf++)
#pragma unroll
            for (int i = 0; i < 4; i++) acc[mf][nf][i] = 0.f;

    int y0 = y0g * 8;
    const float* pbase = g_p1 + n * 128 * 676 + y0 * 26;

    auto issue = [&](int chunk, int buf) {
        float* sAb = sA0 + buf * 2080;
        float2* sBb = sB0 + buf * 4896;
        int cb8 = chunk * 8;
        for (int i = tid; i < 520; i += 256) {
            int ci = i / 65, q = i - ci * 65;
            __pipeline_memcpy_async(sAb + ci * 260 + q * 4,
                                    pbase + (cb8 + ci) * 676 + q * 4, 16);
        }
        for (int i = tid; i < 4608; i += 256) {
            int co = i & 63;
            int r = i >> 6;               // tap*8+ci
            int ci = r & 7, tap = r >> 3;
            __pipeline_memcpy_async(sBb + r * 68 + co,
                                    g_w2hl + (tap * 128 + cb8 + ci) * 128 + coutbase + co,
                                    8);
        }
        __pipeline_commit();
    };

    issue(0, 0);
    for (int c = 0; c < 16; c++) {
        if (c < 15) {
            issue(c + 1, (c + 1) & 1);
            __pipeline_wait_prior(1);
        } else {
            __pipeline_wait_prior(0);
        }
        __syncthreads();
        const float* sAb = sA0 + (c & 1) * 2080;
        const float2* sBb = sB0 + (c & 1) * 4896;
#pragma unroll
        for (int tap = 0; tap < 9; tap++) {
            int toff = (tap / 3) * 26 + (tap % 3);
            uint32_t a[3][4];
#pragma unroll
            for (int mf = 0; mf < 3; mf++) {
                a[mf][0] = __float_as_uint(sAb[qc * 260 + offr[mf] + toff]);
                a[mf][1] = __float_as_uint(sAb[qc * 260 + offr8[mf] + toff]);
                a[mf][2] = __float_as_uint(sAb[(qc + 4) * 260 + offr[mf] + toff]);
                a[mf][3] = __float_as_uint(sAb[(qc + 4) * 260 + offr8[mf] + toff]);
            }
#pragma unroll
            for (int nf = 0; nf < 4; nf++) {
                int ncol = wn * 32 + nf * 8 + qr;
                float2 b0 = sBb[(tap * 8 + qc) * 68 + ncol];
                float2 b1 = sBb[(tap * 8 + qc + 4) * 68 + ncol];
                uint32_t bh0 = __float_as_uint(b0.x);
                uint32_t bh1 = __float_as_uint(b1.x);
                uint32_t bl0 = __float_as_uint(b0.y);
                uint32_t bl1 = __float_as_uint(b1.y);
#pragma unroll
                for (int mf = 0; mf < 3; mf++) {
                    mma_tf32(acc[mf][nf], a[mf], bh0, bh1);
                    mma_tf32(acc[mf][nf], a[mf], bl0, bl1);
                }
            }
        }
        __syncthreads();
    }

    float* op = g_c2 + (n * 128 + coutbase) * 576 + y0g * 192;
#pragma unroll
    for (int mf = 0; mf < 3; mf++) {
        int p = wm * 48 + mf * 16 + qr;
#pragma unroll
        for (int nf = 0; nf < 4; nf++) {
            int L = wn * 32 + nf * 8 + qc * 2;
            float sc0 = sSc[L], sh0 = sSh[L];
            float sc1 = sSc[L + 1], sh1 = sSh[L + 1];
            op[L * 576 + p]           = acc[mf][nf][0] * sc0 + sh0;
            op[(L + 1) * 576 + p]     = acc[mf][nf][1] * sc1 + sh1;
            op[L * 576 + p + 8]       = acc[mf][nf][2] * sc0 + sh0;
            op[(L + 1) * 576 + p + 8] = acc[mf][nf][3] * sc1 + sh1;
        }
    }
}

// ---------------- K4: IF2 + 2x2 maxpool + flatten ----------------
__global__ __launch_bounds__(256) void k4_if2_pool()
{
    int idx = blockIdx.x * 256 + threadIdx.x;  // 589,824 exact
    int ox = idx % 12;
    int t1 = idx / 12;
    int oy = t1 % 12;
    int t2 = t1 / 12;
    int c = t2 & 127;
    int b = t2 >> 7;
    float v0 = 0.f, v1 = 0.f, v2 = 0.f, v3 = 0.f;
    int fo = c * 144 + oy * 12 + ox;
#pragma unroll
    for (int t = 0; t < 8; t++) {
        const float* cp = g_c2 + ((t * 32 + b) * 128 + c) * 576 + (2 * oy) * 24 + 2 * ox;
        v0 += cp[0]; v1 += cp[1]; v2 += cp[24]; v3 += cp[25];
        float s0 = v0 >= 1.f ? 1.f : 0.f; v0 = v0 >= 1.f ? 0.f : v0;
        float s1 = v1 >= 1.f ? 1.f : 0.f; v1 = v1 >= 1.f ? 0.f : v1;
        float s2 = v2 >= 1.f ? 1.f : 0.f; v2 = v2 >= 1.f ? 0.f : v2;
        float s3 = v3 >= 1.f ? 1.f : 0.f; v3 = v3 >= 1.f ? 0.f : v3;
        g_f[(t * 32 + b) * 18432 + fo] = fmaxf(fmaxf(s0, s1), fmaxf(s2, s3));
    }
}

// ---------------- K5: fc1 GEMM, tf32 mma, split-K=8, cp.async pipelined ----------------
// C[256,1152] = F[256,18432] * W1[1152,18432]^T. BM=256, BN=64, BK=16.
// 8 warps 4(M)x2(N). Raw fp32 tiles staged async ([m][k] / [n][k], stride 20 ->
// conflict-free); hi/lo tf32 split done in registers at fragment load.
__global__ __launch_bounds__(256) void k5_fc1_mma(const float* __restrict__ w1)
{
    extern __shared__ float dyn5[];
    float* sA0 = dyn5;                 // 2 x 256*20 floats
    float* sB0 = dyn5 + 2 * 5120;      // 2 x 64*20 floats

    int n0 = blockIdx.x * 64;
    int z = blockIdx.y;
    int tid = threadIdx.x;
    int lane = tid & 31, warp = tid >> 5;
    int wm = warp & 3, wn = warp >> 2;
    int qr = lane >> 2, qc = lane & 3;

    float acc[4][4][4];
#pragma unroll
    for (int mf = 0; mf < 4; mf++)
#pragma unroll
        for (int nf = 0; nf < 4; nf++)
#pragma unroll
            for (int i = 0; i < 4; i++) acc[mf][nf][i] = 0.f;

    int kbase = z * 2304;

    auto issue = [&](int kc, int buf) {
        int k0 = kbase + kc * 16;
        float* sAb = sA0 + buf * 5120;
        float* sBb = sB0 + buf * 1280;
        // A: 256 rows x 16 k = 1024 x 16B ops
        for (int v = tid; v < 1024; v += 256) {
            int m = v >> 2;
            int kq = (v & 3) * 4;
            __pipeline_memcpy_async(sAb + m * 20 + kq,
                                    g_f + m * 18432 + k0 + kq, 16);
        }
        // B: 64 rows x 16 k = 256 x 16B ops
        if (tid < 256) {
            int nr = tid >> 2;
            int kq = (tid & 3) * 4;
            __pipeline_memcpy_async(sBb + nr * 20 + kq,
                                    w1 + (n0 + nr) * 18432 + k0 + kq, 16);
        }
        __pipeline_commit();
    };

    issue(0, 0);
    for (int kc = 0; kc < 144; kc++) {
        if (kc < 143) {
            issue(kc + 1, (kc + 1) & 1);
            __pipeline_wait_prior(1);
        } else {
            __pipeline_wait_prior(0);
        }
        __syncthreads();
        const float* sAb = sA0 + (kc & 1) * 5120;
        const float* sBb = sB0 + (kc & 1) * 1280;
#pragma unroll
        for (int ks = 0; ks < 2; ks++) {
            int kk = ks * 8 + qc;
            uint32_t a[4][4];
#pragma unroll
            for (int mf = 0; mf < 4; mf++) {
                int m = wm * 64 + mf * 16 + qr;
                a[mf][0] = __float_as_uint(sAb[m * 20 + kk]);
                a[mf][1] = __float_as_uint(sAb[(m + 8) * 20 + kk]);
                a[mf][2] = __float_as_uint(sAb[m * 20 + kk + 4]);
                a[mf][3] = __float_as_uint(sAb[(m + 8) * 20 + kk + 4]);
            }
#pragma unroll
            for (int nf = 0; nf < 4; nf++) {
                int nn = wn * 32 + nf * 8 + qr;
                float b0 = sBb[nn * 20 + kk];
                float b1 = sBb[nn * 20 + kk + 4];
                uint32_t bh0 = f2tf32(b0);
                uint32_t bh1 = f2tf32(b1);
                uint32_t bl0 = f2tf32(b0 - __uint_as_float(bh0));
                uint32_t bl1 = f2tf32(b1 - __uint_as_float(bh1));
#pragma unroll
                for (int mf = 0; mf < 4; mf++) {
                    mma_tf32(acc[mf][nf], a[mf], bh0, bh1);
                    mma_tf32(acc[mf][nf], a[mf], bl0, bl1);
                }
            }
        }
        __syncthreads();
    }

    float* op = g_y1p + z * 294912;
#pragma unroll
    for (int mf = 0; mf < 4; mf++) {
        int m = wm * 64 + mf * 16 + qr;
#pragma unroll
        for (int nf = 0; nf < 4; nf++) {
            int nn = n0 + wn * 32 + nf * 8 + qc * 2;
            op[m * 1152 + nn]           = acc[mf][nf][0];
            op[m * 1152 + nn + 1]       = acc[mf][nf][1];
            op[(m + 8) * 1152 + nn]     = acc[mf][nf][2];
            op[(m + 8) * 1152 + nn + 1] = acc[mf][nf][3];
        }
    }
}

// ---------------- K6: reduce split-K(8) + bias + LIF1 ----------------
__global__ __launch_bounds__(256) void k6_lif1(const float* __restrict__ bias)
{
    int idx = blockIdx.x * 256 + threadIdx.x;  // 36,864 exact
    int o = idx % 1152, b = idx / 1152;
    float bi = bias[o];
    float v = 0.f;
#pragma unroll
    for (int t = 0; t < 8; t++) {
        int row = (t * 32 + b) * 1152 + o;
        float xx = bi;
#pragma unroll
        for (int z = 0; z < 8; z++) xx += g_y1p[z * 294912 + row];
        v += (xx - v) * 0.5f;
        float s = v >= 1.f ? 1.f : 0.f;
        g_l1[row] = s;
        v = v >= 1.f ? 0.f : v;
    }
}

// ---------------- K7: fc2 ----------------
__global__ __launch_bounds__(128) void k7_fc2(const float* __restrict__ w,
                                              const float* __restrict__ bias)
{
    __shared__ float row[1152];
    int r = blockIdx.x, o = threadIdx.x;
    for (int i = o; i < 1152; i += 128) row[i] = g_l1[r * 1152 + i];
    __syncthreads();
    const float4* wp = (const float4*)(w + o * 1152);
    float acc = 0.f;
#pragma unroll 4
    for (int k = 0; k < 288; k++) {
        float4 wv = wp[k];
        acc += row[4 * k] * wv.x + row[4 * k + 1] * wv.y
             + row[4 * k + 2] * wv.z + row[4 * k + 3] * wv.w;
    }
    g_y2[r * 128 + o] = acc + bias[o];
}

// ---------------- K8: LIF2 ----------------
__global__ __launch_bounds__(256) void k8_lif2()
{
    int idx = blockIdx.x * 256 + threadIdx.x;  // 4096 exact
    int o = idx & 127, b = idx >> 7;
    float v = 0.f;
#pragma unroll
    for (int t = 0; t < 8; t++) {
        int row = (t * 32 + b) * 128 + o;
        float xx = g_y2[row];
        v += (xx - v) * 0.5f;
        float s = v >= 1.f ? 1.f : 0.f;
        g_l2[row] = s;
        v = v >= 1.f ? 0.f : v;
    }
}

// ---------------- K9: fc3 + LIF3 + mean over T ----------------
__global__ __launch_bounds__(256) void k9_fc3(const float* __restrict__ w,
                                              const float* __restrict__ bias,
                                              float* __restrict__ out)
{
    int idx = threadIdx.x;
    if (idx >= 224) return;
    int o = idx % 7, b = idx / 7;
    const float4* wp = (const float4*)(w + o * 128);
    float v = 0.f, accm = 0.f;
    float bi = bias[o];
    for (int t = 0; t < 8; t++) {
        const float4* lp = (const float4*)(g_l2 + (t * 32 + b) * 128);
        float y = 0.f;
#pragma unroll
        for (int k = 0; k < 32; k++) {
            float4 a = lp[k], ww = wp[k];
            y += a.x * ww.x + a.y * ww.y + a.z * ww.z + a.w * ww.w;
        }
        y += bi;
        v += (y - v) * 0.5f;
        float s = v >= 1.f ? 1.f : 0.f;
        accm += s;
        v = v >= 1.f ? 0.f : v;
    }
    out[b * 7 + o] = accm * 0.125f;
}

// ---------------- launch ----------------
#define K3_SMEM (4160 * 4 + 4896 * 2 * 8 + 128 * 4)  // 95488 B
#define K5_SMEM ((2 * 5120 + 2 * 1280) * 4)          // 51200 B

extern "C" void kernel_launch(void* const* d_in, const int* in_sizes, int n_in,
                              void* d_out, int out_size)
{
    const float* x       = (const float*)d_in[0];
    const float* conv1_w = (const float*)d_in[1];
    const float* conv1_b = (const float*)d_in[2];
    const float* bn1_g   = (const float*)d_in[3];
    const float* bn1_b   = (const float*)d_in[4];
    const float* bn1_m   = (const float*)d_in[5];
    const float* bn1_v   = (const float*)d_in[6];
    const float* conv2_w = (const float*)d_in[7];
    const float* conv2_b = (const float*)d_in[8];
    const float* bn2_g   = (const float*)d_in[9];
    const float* bn2_b   = (const float*)d_in[10];
    const float* bn2_m   = (const float*)d_in[11];
    const float* bn2_v   = (const float*)d_in[12];
    const float* fc1_w   = (const float*)d_in[13];
    const float* fc1_b   = (const float*)d_in[14];
    const float* fc2_w   = (const float*)d_in[15];
    const float* fc2_b   = (const float*)d_in[16];
    const float* fc3_w   = (const float*)d_in[17];
    const float* fc3_b   = (const float*)d_in[18];

    static bool attr_done = false;
    if (!attr_done) {
        cudaFuncSetAttribute(k3_conv2_mma,
                             cudaFuncAttributeMaxDynamicSharedMemorySize, K3_SMEM);
        cudaFuncSetAttribute(k3_conv2_mma,
                             cudaFuncAttributePreferredSharedMemoryCarveout, 100);
        cudaFuncSetAttribute(k5_fc1_mma,
                             cudaFuncAttributeMaxDynamicSharedMemorySize, K5_SMEM);
        cudaFuncSetAttribute(k5_fc1_mma,
                             cudaFuncAttributePreferredSharedMemoryCarveout, 100);
        attr_done = true;
    }

    // zero padded p1 borders (interior overwritten by K2)
    void* p1ptr = nullptr;
    cudaGetSymbolAddress(&p1ptr, g_p1);
    cudaMemsetAsync(p1ptr, 0, sizeof(g_p1));

    k0_split_w2<<<576, 256>>>(conv2_w);
    k1_conv1bn<<<32 * 128, 256>>>(x, conv1_w, conv1_b, bn1_g, bn1_b, bn1_m, bn1_v);
    k2_if_pool<<<9216, 256>>>();
    dim3 g3(NTB, 3, 2);
    k3_conv2_mma<<<g3, 256, K3_SMEM>>>(conv2_b, bn2_g, bn2_b, bn2_m, bn2_v);
    k4_if2_pool<<<2304, 256>>>();
    dim3 g5(18, 8);
    k5_fc1_mma<<<g5, 256, K5_SMEM>>>(fc1_w);
    k6_lif1<<<144, 256>>>(fc1_b);
    k7_fc2<<<NTB, 128>>>(fc2_w, fc2_b);
    k8_lif2<<<16, 256>>>();
    k9_fc3<<<1, 256>>>(fc3_w, fc3_b, (float*)d_out);
}

// round 7
// speedup vs baseline: 4.2681x; 1.4806x over previous
#include <cuda_runtime.h>
#include <cuda_pipeline.h>
#include <cuda_fp16.h>
#include <cstdint>

// SJCSNN spiking CNN forward, T=8, B=32, out [32,7] f32.
// conv2: fp16 mma.m16n8k16, scaled 2-term weight split, single accumulator
//   (spikes {0,1} exact in fp16; lo-term uses A=2^-11 via bit-mask trick).
// fc1: tf32 mma 2-split, cp.async pipelined (unchanged from R6).

#define NTB 256  // T*B

// ---- scratch (device globals; no allocations) ----
__device__ float g_h[32 * 128 * 48 * 48];                      // conv1+bn1 output
__device__ __align__(16) uint32_t g_p1h[NTB * 64 * 676];       // IF1+pool spikes, fp16 pair-packed, PADDED 26x26
__device__ float g_c2[NTB * 128 * 24 * 24];                    // conv2+bn2 output
__device__ __align__(16) float g_f[NTB * 18432];               // IF2+pool spikes, flattened (fp32, for fc1)
__device__ float g_y1p[8 * NTB * 1152];                        // fc1 split-K partials (8)
__device__ float g_l1[NTB * 1152];                             // LIF1 spikes
__device__ float g_y2[NTB * 128];                              // fc2 output
__device__ float g_l2[NTB * 128];                              // LIF2 spikes
// conv2 weights fp16 split: [tap(9)][cinpair(64)][cout(128)][hi,lo] as half2 words
__device__ __align__(16) uint32_t g_w2p[9 * 64 * 128 * 2];

// ---------------- mma helpers ----------------
__device__ __forceinline__ uint32_t f2tf32(float f) {
    uint32_t r;
    asm("cvt.rna.tf32.f32 %0, %1;" : "=r"(r) : "f"(f));
    return r;
}
__device__ __forceinline__ void mma_tf32(float c[4], const uint32_t a[4],
                                         uint32_t b0, uint32_t b1) {
    asm volatile(
        "mma.sync.aligned.m16n8k8.row.col.f32.tf32.tf32.f32 "
        "{%0,%1,%2,%3}, {%4,%5,%6,%7}, {%8,%9}, {%0,%1,%2,%3};"
        : "+f"(c[0]), "+f"(c[1]), "+f"(c[2]), "+f"(c[3])
        : "r"(a[0]), "r"(a[1]), "r"(a[2]), "r"(a[3]), "r"(b0), "r"(b1));
}
__device__ __forceinline__ void mma_f16(float c[4], const uint32_t a[4],
                                        uint32_t b0, uint32_t b1) {
    asm volatile(
        "mma.sync.aligned.m16n8k16.row.col.f32.f16.f16.f32 "
        "{%0,%1,%2,%3}, {%4,%5,%6,%7}, {%8,%9}, {%0,%1,%2,%3};"
        : "+f"(c[0]), "+f"(c[1]), "+f"(c[2]), "+f"(c[3])
        : "r"(a[0]), "r"(a[1]), "r"(a[2]), "r"(a[3]), "r"(b0), "r"(b1));
}

// ---------------- K0: conv2 weight fp16 split, pair-packed ----------------
// out word layout: [(tap*64 + p)*128 + co]*2 + {0:hi, 1:lo}
// word = half2( w[cin=2p], w[cin=2p+1] )  (low half = even cin)
__global__ __launch_bounds__(256) void k0_split_w2(const float* __restrict__ w2)
{
    int i = blockIdx.x * 256 + threadIdx.x;  // 73728 exact
    int co = i & 127;
    int r = i >> 7;              // tap*64 + p
    int p = r & 63, tap = r >> 6;
    int c0 = 2 * p, c1 = c0 + 1;
    float w0 = w2[co * 1152 + c0 * 9 + tap];
    float w1 = w2[co * 1152 + c1 * 9 + tap];
    __half h0 = __float2half_rn(w0);
    __half h1 = __float2half_rn(w1);
    __half l0 = __float2half_rn((w0 - __half2float(h0)) * 2048.0f);
    __half l1 = __float2half_rn((w1 - __half2float(h1)) * 2048.0f);
    uint32_t whi = (uint32_t)__half_as_ushort(h0) | ((uint32_t)__half_as_ushort(h1) << 16);
    uint32_t wlo = (uint32_t)__half_as_ushort(l0) | ((uint32_t)__half_as_ushort(l1) << 16);
    g_w2p[(r * 128 + co) * 2]     = whi;
    g_w2p[(r * 128 + co) * 2 + 1] = wlo;
}

// ---------------- K1: conv1 (1->128, 3x3 SAME) + BN1 ----------------
__global__ __launch_bounds__(256) void k1_conv1bn(
    const float* __restrict__ x, const float* __restrict__ w,
    const float* __restrict__ cb, const float* __restrict__ bg,
    const float* __restrict__ bb, const float* __restrict__ bm,
    const float* __restrict__ bv)
{
    __shared__ float s[2500];  // 50*50 padded
    int b = blockIdx.x >> 7, c = blockIdx.x & 127;
    int tid = threadIdx.x;
    for (int i = tid; i < 2500; i += 256) s[i] = 0.0f;
    __syncthreads();
    const float* xp = x + b * 2304;
    for (int i = tid; i < 2304; i += 256) {
        int r = i / 48, q = i - r * 48;
        s[(r + 1) * 50 + q + 1] = xp[i];
    }
    __syncthreads();
    float wr[9];
#pragma unroll
    for (int k = 0; k < 9; k++) wr[k] = w[c * 9 + k];
    float sc = bg[c] * rsqrtf(bv[c] + 1e-5f);
    float sh = (cb[c] - bm[c]) * sc + bb[c];
    float* hp = g_h + (b * 128 + c) * 2304;
    for (int p = tid; p < 2304; p += 256) {
        int y = p / 48, xx = p - y * 48;
        const float* sp = s + y * 50 + xx;
        float a = sp[0] * wr[0] + sp[1] * wr[1] + sp[2] * wr[2]
                + sp[50] * wr[3] + sp[51] * wr[4] + sp[52] * wr[5]
                + sp[100] * wr[6] + sp[101] * wr[7] + sp[102] * wr[8];
        hp[p] = a * sc + sh;
    }
}

// ---------------- K2: IF1 + 2x2 maxpool, fp16 channel-pair packed output ----------------
// thread per (b, cpair, oy, ox); writes half2(spikepool[2cp], spikepool[2cp+1])
__global__ __launch_bounds__(256) void k2_if_pool()
{
    int idx = blockIdx.x * 256 + threadIdx.x;  // 1,179,648 exact
    int ox = idx % 24;
    int t1 = idx / 24;
    int oy = t1 % 24;
    int t2 = t1 / 24;
    int pair = t2 & 63;
    int b = t2 >> 6;
    const float* h0p = g_h + (b * 128 + 2 * pair) * 2304 + (2 * oy) * 48 + 2 * ox;
    const float* h1p = h0p + 2304;
    float a0 = h0p[0], a1 = h0p[1], a2 = h0p[48], a3 = h0p[49];
    float c0 = h1p[0], c1 = h1p[1], c2 = h1p[48], c3 = h1p[49];
    float va0 = 0.f, va1 = 0.f, va2 = 0.f, va3 = 0.f;
    float vc0 = 0.f, vc1 = 0.f, vc2 = 0.f, vc3 = 0.f;
    int pin = pair * 676 + (oy + 1) * 26 + ox + 1;
#pragma unroll
    for (int t = 0; t < 8; t++) {
        va0 += a0; va1 += a1; va2 += a2; va3 += a3;
        vc0 += c0; vc1 += c1; vc2 += c2; vc3 += c3;
        bool sa0 = va0 >= 1.f, sa1 = va1 >= 1.f, sa2 = va2 >= 1.f, sa3 = va3 >= 1.f;
        bool sc0 = vc0 >= 1.f, sc1 = vc1 >= 1.f, sc2 = vc2 >= 1.f, sc3 = vc3 >= 1.f;
        va0 = sa0 ? 0.f : va0; va1 = sa1 ? 0.f : va1;
        va2 = sa2 ? 0.f : va2; va3 = sa3 ? 0.f : va3;
        vc0 = sc0 ? 0.f : vc0; vc1 = sc1 ? 0.f : vc1;
        vc2 = sc2 ? 0.f : vc2; vc3 = sc3 ? 0.f : vc3;
        bool m0 = sa0 | sa1 | sa2 | sa3;
        bool m1 = sc0 | sc1 | sc2 | sc3;
        uint32_t word = (m0 ? 0x3C00u : 0u) | (m1 ? 0x3C000000u : 0u);
        g_p1h[(t * 32 + b) * 64 * 676 + pin] = word;
    }
}

// ---------------- K3: conv2 + BN2, fp16 mma m16n8k16, cp.async double-buffered --------
// Block: image n, 8 output rows (192 px), 64 couts. 8 chunks of (8 cin-pairs x 9 taps).
// 8 warps 4(M)x2(N); warp tile m48 x n32. Scaled 2-split, single fp32 accumulator:
//   hi-mma: A = spikes(1.0), B = w_hi ; lo-mma: A = spikes*2^-11 (mask), B = (w-hi)*2^11.
// B smem: [tap*8+p][cout][hi,lo] interleaved, row stride 136 words -> conflict-free LDS.64.
__global__ __launch_bounds__(256, 2) void k3_conv2_mma(
    const float* __restrict__ cb, const float* __restrict__ bg,
    const float* __restrict__ bb, const float* __restrict__ bm,
    const float* __restrict__ bv)
{
    extern __shared__ uint32_t dyn[];
    uint32_t* sA0 = dyn;                       // 2 x 2080 words (8 pair-planes x 260)
    uint32_t* sB0 = dyn + 4160;                // 2 x 9792 words (72 rows x 136)
    float* sSc = (float*)(dyn + 4160 + 19584); // 64
    float* sSh = sSc + 64;                     // 64

    int n = blockIdx.x;
    int y0g = blockIdx.y;              // 0..2  -> rows y0g*8 .. +7
    int coutbase = blockIdx.z * 64;    // 0 or 64
    int tid = threadIdx.x;
    int lane = tid & 31, warp = tid >> 5;
    int wm = warp & 3, wn = warp >> 2; // 4 x 2 warp grid
    int qr = lane >> 2, qc = lane & 3;

    if (tid < 64) {
        int oc = coutbase + tid;
        float sc = bg[oc] * rsqrtf(bv[oc] + 1e-5f);
        sSc[tid] = sc;
        sSh[tid] = (cb[oc] - bm[oc]) * sc + bb[oc];
    }

    int offr[3], offr8[3];
#pragma unroll
    for (int mf = 0; mf < 3; mf++) {
        int p = wm * 48 + mf * 16 + qr;
        offr[mf] = (p / 24) * 26 + (p % 24);
        int p8 = p + 8;
        offr8[mf] = (p8 / 24) * 26 + (p8 % 24);
    }

    float acc[3][4][4];
#pragma unroll
    for (int mf = 0; mf < 3; mf++)
#pragma unroll
        for (int nf = 0; nf < 4; nf++)
#pragma unroll
            for (int i = 0; i < 4; i++) acc[mf][nf][i] = 0.f;

    int y0 = y0g * 8;
    const uint32_t* pbase = g_p1h + n * 64 * 676 + y0 * 26;

    // stage one chunk (8 cin-pairs = 16 cins) into buffer buf
    auto issue = [&](int chunk, int buf) {
        uint32_t* sAb = sA0 + buf * 2080;
        uint32_t* sBb = sB0 + buf * 9792;
        int pb = chunk * 8;  // base cin-pair
        // A: 8 pair-planes x 260 words = 520 x 16B
        for (int i = tid; i < 520; i += 256) {
            int ci = i / 65, q = i - ci * 65;
            __pipeline_memcpy_async(sAb + ci * 260 + q * 4,
                                    pbase + (pb + ci) * 676 + q * 4, 16);
        }
        // B: 72 rows x 64 couts x (hi,lo) 8B each
        for (int i = tid; i < 4608; i += 256) {
            int co = i & 63;
            int r = i >> 6;               // tap*8 + pi
            int pi = r & 7, tap = r >> 3;
            __pipeline_memcpy_async(sBb + r * 136 + co * 2,
                                    g_w2p + ((tap * 64 + pb + pi) * 128 + coutbase + co) * 2,
                                    8);
        }
        __pipeline_commit();
    };

    issue(0, 0);
    for (int c = 0; c < 8; c++) {
        if (c < 7) {
            issue(c + 1, (c + 1) & 1);
            __pipeline_wait_prior(1);
        } else {
            __pipeline_wait_prior(0);
        }
        __syncthreads();
        const uint32_t* sAb = sA0 + (c & 1) * 2080;
        const uint32_t* sBb = sB0 + (c & 1) * 9792;
#pragma unroll
        for (int tap = 0; tap < 9; tap++) {
            int toff = (tap / 3) * 26 + (tap % 3);
            uint32_t ah[3][4], al[3][4];
#pragma unroll
            for (int mf = 0; mf < 3; mf++) {
                ah[mf][0] = sAb[qc * 260 + offr[mf] + toff];
                ah[mf][1] = sAb[qc * 260 + offr8[mf] + toff];
                ah[mf][2] = sAb[(qc + 4) * 260 + offr[mf] + toff];
                ah[mf][3] = sAb[(qc + 4) * 260 + offr8[mf] + toff];
#pragma unroll
                for (int j = 0; j < 4; j++) al[mf][j] = ah[mf][j] & 0x10001000u;
            }
#pragma unroll
            for (int nf = 0; nf < 4; nf++) {
                int ncol = wn * 32 + nf * 8 + qr;
                uint2 b0 = *(const uint2*)(sBb + (tap * 8 + qc) * 136 + ncol * 2);
                uint2 b1 = *(const uint2*)(sBb + (tap * 8 + qc + 4) * 136 + ncol * 2);
#pragma unroll
                for (int mf = 0; mf < 3; mf++) {
                    mma_f16(acc[mf][nf], ah[mf], b0.x, b1.x);
                    mma_f16(acc[mf][nf], al[mf], b0.y, b1.y);
                }
            }
        }
        __syncthreads();
    }

    // epilogue: BN + scatter to g_c2 [n][cout][576]
    float* op = g_c2 + (n * 128 + coutbase) * 576 + y0g * 192;
#pragma unroll
    for (int mf = 0; mf < 3; mf++) {
        int p = wm * 48 + mf * 16 + qr;
#pragma unroll
        for (int nf = 0; nf < 4; nf++) {
            int L = wn * 32 + nf * 8 + qc * 2;
            float sc0 = sSc[L], sh0 = sSh[L];
            float sc1 = sSc[L + 1], sh1 = sSh[L + 1];
            op[L * 576 + p]           = acc[mf][nf][0] * sc0 + sh0;
            op[(L + 1) * 576 + p]     = acc[mf][nf][1] * sc1 + sh1;
            op[L * 576 + p + 8]       = acc[mf][nf][2] * sc0 + sh0;
            op[(L + 1) * 576 + p + 8] = acc[mf][nf][3] * sc1 + sh1;
        }
    }
}

// ---------------- K4: IF2 + 2x2 maxpool + flatten ----------------
__global__ __launch_bounds__(256) void k4_if2_pool()
{
    int idx = blockIdx.x * 256 + threadIdx.x;  // 589,824 exact
    int ox = idx % 12;
    int t1 = idx / 12;
    int oy = t1 % 12;
    int t2 = t1 / 12;
    int c = t2 & 127;
    int b = t2 >> 7;
    float v0 = 0.f, v1 = 0.f, v2 = 0.f, v3 = 0.f;
    int fo = c * 144 + oy * 12 + ox;
#pragma unroll
    for (int t = 0; t < 8; t++) {
        const float* cp = g_c2 + ((t * 32 + b) * 128 + c) * 576 + (2 * oy) * 24 + 2 * ox;
        v0 += cp[0]; v1 += cp[1]; v2 += cp[24]; v3 += cp[25];
        float s0 = v0 >= 1.f ? 1.f : 0.f; v0 = v0 >= 1.f ? 0.f : v0;
        float s1 = v1 >= 1.f ? 1.f : 0.f; v1 = v1 >= 1.f ? 0.f : v1;
        float s2 = v2 >= 1.f ? 1.f : 0.f; v2 = v2 >= 1.f ? 0.f : v2;
        float s3 = v3 >= 1.f ? 1.f : 0.f; v3 = v3 >= 1.f ? 0.f : v3;
        g_f[(t * 32 + b) * 18432 + fo] = fmaxf(fmaxf(s0, s1), fmaxf(s2, s3));
    }
}

// ---------------- K5: fc1 GEMM, tf32 mma, split-K=8, cp.async pipelined ----------------
__global__ __launch_bounds__(256) void k5_fc1_mma(const float* __restrict__ w1)
{
    extern __shared__ float dyn5[];
    float* sA0 = dyn5;                 // 2 x 256*20 floats
    float* sB0 = dyn5 + 2 * 5120;      // 2 x 64*20 floats

    int n0 = blockIdx.x * 64;
    int z = blockIdx.y;
    int tid = threadIdx.x;
    int lane = tid & 31, warp = tid >> 5;
    int wm = warp & 3, wn = warp >> 2;
    int qr = lane >> 2, qc = lane & 3;

    float acc[4][4][4];
#pragma unroll
    for (int mf = 0; mf < 4; mf++)
#pragma unroll
        for (int nf = 0; nf < 4; nf++)
#pragma unroll
            for (int i = 0; i < 4; i++) acc[mf][nf][i] = 0.f;

    int kbase = z * 2304;

    auto issue = [&](int kc, int buf) {
        int k0 = kbase + kc * 16;
        float* sAb = sA0 + buf * 5120;
        float* sBb = sB0 + buf * 1280;
        for (int v = tid; v < 1024; v += 256) {
            int m = v >> 2;
            int kq = (v & 3) * 4;
            __pipeline_memcpy_async(sAb + m * 20 + kq,
                                    g_f + m * 18432 + k0 + kq, 16);
        }
        if (tid < 256) {
            int nr = tid >> 2;
            int kq = (tid & 3) * 4;
            __pipeline_memcpy_async(sBb + nr * 20 + kq,
                                    w1 + (n0 + nr) * 18432 + k0 + kq, 16);
        }
        __pipeline_commit();
    };

    issue(0, 0);
    for (int kc = 0; kc < 144; kc++) {
        if (kc < 143) {
            issue(kc + 1, (kc + 1) & 1);
            __pipeline_wait_prior(1);
        } else {
            __pipeline_wait_prior(0);
        }
        __syncthreads();
        const float* sAb = sA0 + (kc & 1) * 5120;
        const float* sBb = sB0 + (kc & 1) * 1280;
#pragma unroll
        for (int ks = 0; ks < 2; ks++) {
            int kk = ks * 8 + qc;
            uint32_t a[4][4];
#pragma unroll
            for (int mf = 0; mf < 4; mf++) {
                int m = wm * 64 + mf * 16 + qr;
                a[mf][0] = __float_as_uint(sAb[m * 20 + kk]);
                a[mf][1] = __float_as_uint(sAb[(m + 8) * 20 + kk]);
                a[mf][2] = __float_as_uint(sAb[m * 20 + kk + 4]);
                a[mf][3] = __float_as_uint(sAb[(m + 8) * 20 + kk + 4]);
            }
#pragma unroll
            for (int nf = 0; nf < 4; nf++) {
                int nn = wn * 32 + nf * 8 + qr;
                float b0 = sBb[nn * 20 + kk];
                float b1 = sBb[nn * 20 + kk + 4];
                uint32_t bh0 = f2tf32(b0);
                uint32_t bh1 = f2tf32(b1);
                uint32_t bl0 = f2tf32(b0 - __uint_as_float(bh0));
                uint32_t bl1 = f2tf32(b1 - __uint_as_float(bh1));
#pragma unroll
                for (int mf = 0; mf < 4; mf++) {
                    mma_tf32(acc[mf][nf], a[mf], bh0, bh1);
                    mma_tf32(acc[mf][nf], a[mf], bl0, bl1);
                }
            }
        }
        __syncthreads();
    }

    float* op = g_y1p + z * 294912;
#pragma unroll
    for (int mf = 0; mf < 4; mf++) {
        int m = wm * 64 + mf * 16 + qr;
#pragma unroll
        for (int nf = 0; nf < 4; nf++) {
            int nn = n0 + wn * 32 + nf * 8 + qc * 2;
            op[m * 1152 + nn]           = acc[mf][nf][0];
            op[m * 1152 + nn + 1]       = acc[mf][nf][1];
            op[(m + 8) * 1152 + nn]     = acc[mf][nf][2];
            op[(m + 8) * 1152 + nn + 1] = acc[mf][nf][3];
        }
    }
}

// ---------------- K6: reduce split-K(8) + bias + LIF1 ----------------
__global__ __launch_bounds__(256) void k6_lif1(const float* __restrict__ bias)
{
    int idx = blockIdx.x * 256 + threadIdx.x;  // 36,864 exact
    int o = idx % 1152, b = idx / 1152;
    float bi = bias[o];
    float v = 0.f;
#pragma unroll
    for (int t = 0; t < 8; t++) {
        int row = (t * 32 + b) * 1152 + o;
        float xx = bi;
#pragma unroll
        for (int z = 0; z < 8; z++) xx += g_y1p[z * 294912 + row];
        v += (xx - v) * 0.5f;
        float s = v >= 1.f ? 1.f : 0.f;
        g_l1[row] = s;
        v = v >= 1.f ? 0.f : v;
    }
}

// ---------------- K7: fc2 ----------------
__global__ __launch_bounds__(128) void k7_fc2(const float* __restrict__ w,
                                              const float* __restrict__ bias)
{
    __shared__ float row[1152];
    int r = blockIdx.x, o = threadIdx.x;
    for (int i = o; i < 1152; i += 128) row[i] = g_l1[r * 1152 + i];
    __syncthreads();
    const float4* wp = (const float4*)(w + o * 1152);
    float acc = 0.f;
#pragma unroll 4
    for (int k = 0; k < 288; k++) {
        float4 wv = wp[k];
        acc += row[4 * k] * wv.x + row[4 * k + 1] * wv.y
             + row[4 * k + 2] * wv.z + row[4 * k + 3] * wv.w;
    }
    g_y2[r * 128 + o] = acc + bias[o];
}

// ---------------- K8: LIF2 ----------------
__global__ __launch_bounds__(256) void k8_lif2()
{
    int idx = blockIdx.x * 256 + threadIdx.x;  // 4096 exact
    int o = idx & 127, b = idx >> 7;
    float v = 0.f;
#pragma unroll
    for (int t = 0; t < 8; t++) {
        int row = (t * 32 + b) * 128 + o;
        float xx = g_y2[row];
        v += (xx - v) * 0.5f;
        float s = v >= 1.f ? 1.f : 0.f;
        g_l2[row] = s;
        v = v >= 1.f ? 0.f : v;
    }
}

// ---------------- K9: fc3 + LIF3 + mean over T ----------------
__global__ __launch_bounds__(256) void k9_fc3(const float* __restrict__ w,
                                              const float* __restrict__ bias,
                                              float* __restrict__ out)
{
    int idx = threadIdx.x;
    if (idx >= 224) return;
    int o = idx % 7, b = idx / 7;
    const float4* wp = (const float4*)(w + o * 128);
    float v = 0.f, accm = 0.f;
    float bi = bias[o];
    for (int t = 0; t < 8; t++) {
        const float4* lp = (const float4*)(g_l2 + (t * 32 + b) * 128);
        float y = 0.f;
#pragma unroll
        for (int k = 0; k < 32; k++) {
            float4 a = lp[k], ww = wp[k];
            y += a.x * ww.x + a.y * ww.y + a.z * ww.z + a.w * ww.w;
        }
        y += bi;
        v += (y - v) * 0.5f;
        float s = v >= 1.f ? 1.f : 0.f;
        accm += s;
        v = v >= 1.f ? 0.f : v;
    }
    out[b * 7 + o] = accm * 0.125f;
}

// ---------------- launch ----------------
#define K3_SMEM ((4160 + 19584 + 128) * 4)   // 95488 B
#define K5_SMEM ((2 * 5120 + 2 * 1280) * 4)  // 51200 B

extern "C" void kernel_launch(void* const* d_in, const int* in_sizes, int n_in,
                              void* d_out, int out_size)
{
    const float* x       = (const float*)d_in[0];
    const float* conv1_w = (const float*)d_in[1];
    const float* conv1_b = (const float*)d_in[2];
    const float* bn1_g   = (const float*)d_in[3];
    const float* bn1_b   = (const float*)d_in[4];
    const float* bn1_m   = (const float*)d_in[5];
    const float* bn1_v   = (const float*)d_in[6];
    const float* conv2_w = (const float*)d_in[7];
    const float* conv2_b = (const float*)d_in[8];
    const float* bn2_g   = (const float*)d_in[9];
    const float* bn2_b   = (const float*)d_in[10];
    const float* bn2_m   = (const float*)d_in[11];
    const float* bn2_v   = (const float*)d_in[12];
    const float* fc1_w   = (const float*)d_in[13];
    const float* fc1_b   = (const float*)d_in[14];
    const float* fc2_w   = (const float*)d_in[15];
    const float* fc2_b   = (const float*)d_in[16];
    const float* fc3_w   = (const float*)d_in[17];
    const float* fc3_b   = (const float*)d_in[18];

    static bool attr_done = false;
    if (!attr_done) {
        cudaFuncSetAttribute(k3_conv2_mma,
                             cudaFuncAttributeMaxDynamicSharedMemorySize, K3_SMEM);
        cudaFuncSetAttribute(k3_conv2_mma,
                             cudaFuncAttributePreferredSharedMemoryCarveout, 100);
        cudaFuncSetAttribute(k5_fc1_mma,
                             cudaFuncAttributeMaxDynamicSharedMemorySize, K5_SMEM);
        cudaFuncSetAttribute(k5_fc1_mma,
                             cudaFuncAttributePreferredSharedMemoryCarveout, 100);
        attr_done = true;
    }

    // zero padded p1 borders (interior overwritten by K2); fp16 zero == 0x0000
    void* p1ptr = nullptr;
    cudaGetSymbolAddress(&p1ptr, g_p1h);
    cudaMemsetAsync(p1ptr, 0, sizeof(g_p1h));

    k0_split_w2<<<288, 256>>>(conv2_w);
    k1_conv1bn<<<32 * 128, 256>>>(x, conv1_w, conv1_b, bn1_g, bn1_b, bn1_m, bn1_v);
    k2_if_pool<<<4608, 256>>>();
    dim3 g3(NTB, 3, 2);
    k3_conv2_mma<<<g3, 256, K3_SMEM>>>(conv2_b, bn2_g, bn2_b, bn2_m, bn2_v);
    k4_if2_pool<<<2304, 256>>>();
    dim3 g5(18, 8);
    k5_fc1_mma<<<g5, 256, K5_SMEM>>>(fc1_w);
    k6_lif1<<<144, 256>>>(fc1_b);
    k7_fc2<<<NTB, 128>>>(fc2_w, fc2_b);
    k8_lif2<<<16, 256>>>();
    k9_fc3<<<1, 256>>>(fc3_w, fc3_b, (float*)d_out);
}

// round 8
// speedup vs baseline: 4.8060x; 1.1261x over previous
#include <cuda_runtime.h>
#include <cuda_pipeline.h>
#include <cuda_fp16.h>
#include <cstdint>

// SJCSNN spiking CNN forward, T=8, B=32, out [32,7] f32.
// conv2 AND fc1: fp16 mma.m16n8k16, scaled 2-term weight split, single fp32 acc
//   (spikes {0,1} exact in fp16; lo-term A = spikes*2^-11 via bit-mask trick,
//    lo-term B = (w - fp16(w)) * 2^11).

#define NTB 256  // T*B

// ---- scratch (device globals; no allocations) ----
__device__ __align__(16) uint32_t g_p1h[NTB * 64 * 676];   // IF1+pool spikes, fp16 pair-packed, PADDED 26x26
__device__ __align__(16) float g_c2[NTB * 128 * 24 * 24];  // conv2+bn2 output
__device__ __align__(16) uint32_t g_fh[NTB * 9216];        // IF2+pool spikes, fp16 pair-packed flat
__device__ float g_y1p[8 * NTB * 1152];                    // fc1 split-K partials (8)
__device__ float g_l1[NTB * 1152];                         // LIF1 spikes
__device__ float g_y2[NTB * 128];                          // fc2 output
__device__ float g_l2[NTB * 128];                          // LIF2 spikes
// conv2 weights fp16 split: [tap(9)][cinpair(64)][cout(128)][hi,lo] as half2 words
__device__ __align__(16) uint32_t g_w2p[9 * 64 * 128 * 2];

// ---------------- mma helper ----------------
__device__ __forceinline__ void mma_f16(float c[4], const uint32_t a[4],
                                        uint32_t b0, uint32_t b1) {
    asm volatile(
        "mma.sync.aligned.m16n8k16.row.col.f32.f16.f16.f32 "
        "{%0,%1,%2,%3}, {%4,%5,%6,%7}, {%8,%9}, {%0,%1,%2,%3};"
        : "+f"(c[0]), "+f"(c[1]), "+f"(c[2]), "+f"(c[3])
        : "r"(a[0]), "r"(a[1]), "r"(a[2]), "r"(a[3]), "r"(b0), "r"(b1));
}

// ---------------- K0: conv2 weight fp16 split, pair-packed ----------------
__global__ __launch_bounds__(256) void k0_split_w2(const float* __restrict__ w2)
{
    int i = blockIdx.x * 256 + threadIdx.x;  // 73728 exact
    int co = i & 127;
    int r = i >> 7;              // tap*64 + p
    int p = r & 63, tap = r >> 6;
    int c0 = 2 * p, c1 = c0 + 1;
    float w0 = w2[co * 1152 + c0 * 9 + tap];
    float w1 = w2[co * 1152 + c1 * 9 + tap];
    __half h0 = __float2half_rn(w0);
    __half h1 = __float2half_rn(w1);
    __half l0 = __float2half_rn((w0 - __half2float(h0)) * 2048.0f);
    __half l1 = __float2half_rn((w1 - __half2float(h1)) * 2048.0f);
    uint32_t whi = (uint32_t)__half_as_ushort(h0) | ((uint32_t)__half_as_ushort(h1) << 16);
    uint32_t wlo = (uint32_t)__half_as_ushort(l0) | ((uint32_t)__half_as_ushort(l1) << 16);
    g_w2p[(r * 128 + co) * 2]     = whi;
    g_w2p[(r * 128 + co) * 2 + 1] = wlo;
}

// ---------------- K12: conv1 (1->128) + BN1 + IF1 + 2x2 maxpool, fused ----------------
// block per (b, channel-pair); x plane in smem, both h planes in smem,
// then per pooled pixel the 8-step IF + pool + fp16 pair-pack.
__global__ __launch_bounds__(256) void k12_conv1_if_pool(
    const float* __restrict__ x, const float* __restrict__ w,
    const float* __restrict__ cb, const float* __restrict__ bg,
    const float* __restrict__ bb, const float* __restrict__ bm,
    const float* __restrict__ bv)
{
    __shared__ float sx[2500];       // 50x50 padded input
    __shared__ float sh[2][2304];    // h planes for the 2 channels
    int b = blockIdx.x >> 6, pair = blockIdx.x & 63;
    int tid = threadIdx.x;
    for (int i = tid; i < 2500; i += 256) sx[i] = 0.0f;
    __syncthreads();
    const float* xp = x + b * 2304;
    for (int i = tid; i < 2304; i += 256) {
        int r = i / 48, q = i - r * 48;
        sx[(r + 1) * 50 + q + 1] = xp[i];
    }
    __syncthreads();
#pragma unroll
    for (int half = 0; half < 2; half++) {
        int c = 2 * pair + half;
        float wr[9];
#pragma unroll
        for (int k = 0; k < 9; k++) wr[k] = w[c * 9 + k];
        float sc = bg[c] * rsqrtf(bv[c] + 1e-5f);
        float sf = (cb[c] - bm[c]) * sc + bb[c];
        for (int p = tid; p < 2304; p += 256) {
            int y = p / 48, xx = p - y * 48;
            const float* sp = sx + y * 50 + xx;
            float a = sp[0] * wr[0] + sp[1] * wr[1] + sp[2] * wr[2]
                    + sp[50] * wr[3] + sp[51] * wr[4] + sp[52] * wr[5]
                    + sp[100] * wr[6] + sp[101] * wr[7] + sp[102] * wr[8];
            sh[half][p] = a * sc + sf;
        }
    }
    __syncthreads();
    for (int p = tid; p < 576; p += 256) {
        int oy = p / 24, ox = p - oy * 24;
        int base = (2 * oy) * 48 + 2 * ox;
        float a0 = sh[0][base], a1 = sh[0][base + 1], a2 = sh[0][base + 48], a3 = sh[0][base + 49];
        float c0 = sh[1][base], c1 = sh[1][base + 1], c2 = sh[1][base + 48], c3 = sh[1][base + 49];
        float va0 = 0.f, va1 = 0.f, va2 = 0.f, va3 = 0.f;
        float vc0 = 0.f, vc1 = 0.f, vc2 = 0.f, vc3 = 0.f;
        int pin = pair * 676 + (oy + 1) * 26 + ox + 1;
#pragma unroll
        for (int t = 0; t < 8; t++) {
            va0 += a0; va1 += a1; va2 += a2; va3 += a3;
            vc0 += c0; vc1 += c1; vc2 += c2; vc3 += c3;
            bool sa0 = va0 >= 1.f, sa1 = va1 >= 1.f, sa2 = va2 >= 1.f, sa3 = va3 >= 1.f;
            bool sc0 = vc0 >= 1.f, sc1 = vc1 >= 1.f, sc2 = vc2 >= 1.f, sc3 = vc3 >= 1.f;
            va0 = sa0 ? 0.f : va0; va1 = sa1 ? 0.f : va1;
            va2 = sa2 ? 0.f : va2; va3 = sa3 ? 0.f : va3;
            vc0 = sc0 ? 0.f : vc0; vc1 = sc1 ? 0.f : vc1;
            vc2 = sc2 ? 0.f : vc2; vc3 = sc3 ? 0.f : vc3;
            bool m0 = sa0 | sa1 | sa2 | sa3;
            bool m1 = sc0 | sc1 | sc2 | sc3;
            uint32_t word = (m0 ? 0x3C00u : 0u) | (m1 ? 0x3C000000u : 0u);
            g_p1h[(t * 32 + b) * 64 * 676 + pin] = word;
        }
    }
}

// ---------------- K3: conv2 + BN2, fp16 mma m16n8k16, cp.async double-buffered --------
__global__ __launch_bounds__(256, 2) void k3_conv2_mma(
    const float* __restrict__ cb, const float* __restrict__ bg,
    const float* __restrict__ bb, const float* __restrict__ bm,
    const float* __restrict__ bv)
{
    extern __shared__ uint32_t dyn[];
    uint32_t* sA0 = dyn;                       // 2 x 2080 words (8 pair-planes x 260)
    uint32_t* sB0 = dyn + 4160;                // 2 x 9792 words (72 rows x 136)
    float* sSc = (float*)(dyn + 4160 + 19584); // 64
    float* sSh = sSc + 64;                     // 64

    int n = blockIdx.x;
    int y0g = blockIdx.y;              // 0..2  -> rows y0g*8 .. +7
    int coutbase = blockIdx.z * 64;    // 0 or 64
    int tid = threadIdx.x;
    int lane = tid & 31, warp = tid >> 5;
    int wm = warp & 3, wn = warp >> 2; // 4 x 2 warp grid
    int qr = lane >> 2, qc = lane & 3;

    if (tid < 64) {
        int oc = coutbase + tid;
        float sc = bg[oc] * rsqrtf(bv[oc] + 1e-5f);
        sSc[tid] = sc;
        sSh[tid] = (cb[oc] - bm[oc]) * sc + bb[oc];
    }

    int offr[3], offr8[3];
#pragma unroll
    for (int mf = 0; mf < 3; mf++) {
        int p = wm * 48 + mf * 16 + qr;
        offr[mf] = (p / 24) * 26 + (p % 24);
        int p8 = p + 8;
        offr8[mf] = (p8 / 24) * 26 + (p8 % 24);
    }

    float acc[3][4][4];
#pragma unroll
    for (int mf = 0; mf < 3; mf++)
#pragma unroll
        for (int nf = 0; nf < 4; nf++)
#pragma unroll
            for (int i = 0; i < 4; i++) acc[mf][nf][i] = 0.f;

    int y0 = y0g * 8;
    const uint32_t* pbase = g_p1h + n * 64 * 676 + y0 * 26;

    auto issue = [&](int chunk, int buf) {
        uint32_t* sAb = sA0 + buf * 2080;
        uint32_t* sBb = sB0 + buf * 9792;
        int pb = chunk * 8;  // base cin-pair
        for (int i = tid; i < 520; i += 256) {
            int ci = i / 65, q = i - ci * 65;
            __pipeline_memcpy_async(sAb + ci * 260 + q * 4,
                                    pbase + (pb + ci) * 676 + q * 4, 16);
        }
        for (int i = tid; i < 4608; i += 256) {
            int co = i & 63;
            int r = i >> 6;               // tap*8 + pi
            int pi = r & 7, tap = r >> 3;
            __pipeline_memcpy_async(sBb + r * 136 + co * 2,
                                    g_w2p + ((tap * 64 + pb + pi) * 128 + coutbase + co) * 2,
                                    8);
        }
        __pipeline_commit();
    };

    issue(0, 0);
    for (int c = 0; c < 8; c++) {
        if (c < 7) {
            issue(c + 1, (c + 1) & 1);
            __pipeline_wait_prior(1);
        } else {
            __pipeline_wait_prior(0);
        }
        __syncthreads();
        const uint32_t* sAb = sA0 + (c & 1) * 2080;
        const uint32_t* sBb = sB0 + (c & 1) * 9792;
#pragma unroll
        for (int tap = 0; tap < 9; tap++) {
            int toff = (tap / 3) * 26 + (tap % 3);
            uint32_t ah[3][4], al[3][4];
#pragma unroll
            for (int mf = 0; mf < 3; mf++) {
                ah[mf][0] = sAb[qc * 260 + offr[mf] + toff];
                ah[mf][1] = sAb[qc * 260 + offr8[mf] + toff];
                ah[mf][2] = sAb[(qc + 4) * 260 + offr[mf] + toff];
                ah[mf][3] = sAb[(qc + 4) * 260 + offr8[mf] + toff];
#pragma unroll
                for (int j = 0; j < 4; j++) al[mf][j] = ah[mf][j] & 0x10001000u;
            }
#pragma unroll
            for (int nf = 0; nf < 4; nf++) {
                int ncol = wn * 32 + nf * 8 + qr;
                uint2 b0 = *(const uint2*)(sBb + (tap * 8 + qc) * 136 + ncol * 2);
                uint2 b1 = *(const uint2*)(sBb + (tap * 8 + qc + 4) * 136 + ncol * 2);
#pragma unroll
                for (int mf = 0; mf < 3; mf++) {
                    mma_f16(acc[mf][nf], ah[mf], b0.x, b1.x);
                    mma_f16(acc[mf][nf], al[mf], b0.y, b1.y);
                }
            }
        }
        __syncthreads();
    }

    float* op = g_c2 + (n * 128 + coutbase) * 576 + y0g * 192;
#pragma unroll
    for (int mf = 0; mf < 3; mf++) {
        int p = wm * 48 + mf * 16 + qr;
#pragma unroll
        for (int nf = 0; nf < 4; nf++) {
            int L = wn * 32 + nf * 8 + qc * 2;
            float sc0 = sSc[L], sh0 = sSh[L];
            float sc1 = sSc[L + 1], sh1 = sSh[L + 1];
            op[L * 576 + p]           = acc[mf][nf][0] * sc0 + sh0;
            op[(L + 1) * 576 + p]     = acc[mf][nf][1] * sc1 + sh1;
            op[L * 576 + p + 8]       = acc[mf][nf][2] * sc0 + sh0;
            op[(L + 1) * 576 + p + 8] = acc[mf][nf][3] * sc1 + sh1;
        }
    }
}

// ---------------- K4: IF2 + 2x2 maxpool + flatten, fp16 pair-packed output ----------------
// thread per (b, c, oy, ox-pair); packs 2 adjacent pooled outputs into one half2 word
__global__ __launch_bounds__(256) void k4_if2_pool()
{
    int idx = blockIdx.x * 256 + threadIdx.x;  // 294,912 exact
    int oxp = idx % 6;
    int t1 = idx / 6;
    int oy = t1 % 12;
    int t2 = t1 / 12;
    int c = t2 & 127;
    int b = t2 >> 7;
    float va0 = 0.f, va1 = 0.f, va2 = 0.f, va3 = 0.f;
    float vc0 = 0.f, vc1 = 0.f, vc2 = 0.f, vc3 = 0.f;
    int fo = c * 72 + oy * 6 + oxp;
#pragma unroll
    for (int t = 0; t < 8; t++) {
        const float* cp = g_c2 + ((t * 32 + b) * 128 + c) * 576 + (2 * oy) * 24 + 4 * oxp;
        float4 r0 = *(const float4*)cp;
        float4 r1 = *(const float4*)(cp + 24);
        va0 += r0.x; va1 += r0.y; va2 += r1.x; va3 += r1.y;
        vc0 += r0.z; vc1 += r0.w; vc2 += r1.z; vc3 += r1.w;
        bool sa0 = va0 >= 1.f, sa1 = va1 >= 1.f, sa2 = va2 >= 1.f, sa3 = va3 >= 1.f;
        bool sc0 = vc0 >= 1.f, sc1 = vc1 >= 1.f, sc2 = vc2 >= 1.f, sc3 = vc3 >= 1.f;
        va0 = sa0 ? 0.f : va0; va1 = sa1 ? 0.f : va1;
        va2 = sa2 ? 0.f : va2; va3 = sa3 ? 0.f : va3;
        vc0 = sc0 ? 0.f : vc0; vc1 = sc1 ? 0.f : vc1;
        vc2 = sc2 ? 0.f : vc2; vc3 = sc3 ? 0.f : vc3;
        bool m0 = sa0 | sa1 | sa2 | sa3;
        bool m1 = sc0 | sc1 | sc2 | sc3;
        uint32_t word = (m0 ? 0x3C00u : 0u) | (m1 ? 0x3C000000u : 0u);
        g_fh[(t * 32 + b) * 9216 + fo] = word;
    }
}

// ---------------- K5: fc1 GEMM, fp16 mma m16n8k16, split-K=8, cp.async ----------------
// C[256,1152] = F[256,18432] * W1[1152,18432]^T. BM=256, BN=64, BK=16(=8 words).
// A: packed spikes, smem stride 12 words (conflict-free). B: raw fp32, stride 24
// (conflict-free float2 phases); fp16 hi/lo split in registers at fragment load.
__global__ __launch_bounds__(256) void k5_fc1_mma(const float* __restrict__ w1)
{
    extern __shared__ uint32_t dyn5[];
    uint32_t* sA0 = dyn5;                    // 2 x 256*12 words
    float* sB0 = (float*)(dyn5 + 2 * 3072);  // 2 x 64*24 floats

    int n0 = blockIdx.x * 64;
    int z = blockIdx.y;
    int tid = threadIdx.x;
    int lane = tid & 31, warp = tid >> 5;
    int wm = warp & 3, wn = warp >> 2;
    int qr = lane >> 2, qc = lane & 3;

    float acc[4][4][4];
#pragma unroll
    for (int mf = 0; mf < 4; mf++)
#pragma unroll
        for (int nf = 0; nf < 4; nf++)
#pragma unroll
            for (int i = 0; i < 4; i++) acc[mf][nf][i] = 0.f;

    int kbase = z * 2304;

    auto issue = [&](int kc, int buf) {
        int k0 = kbase + kc * 16;
        int kw = k0 >> 1;
        uint32_t* sAb = sA0 + buf * 3072;
        float* sBb = sB0 + buf * 1536;
        // A: 256 rows x 8 words = 512 x 16B ops
        for (int v = tid; v < 512; v += 256) {
            int m = v >> 1;
            int hq = (v & 1) * 4;
            __pipeline_memcpy_async(sAb + m * 12 + hq,
                                    g_fh + m * 9216 + kw + hq, 16);
        }
        // B: 64 rows x 16 floats = 256 x 16B ops
        {
            int nr = tid >> 2;
            int kq = (tid & 3) * 4;
            __pipeline_memcpy_async(sBb + nr * 24 + kq,
                                    w1 + (n0 + nr) * 18432 + k0 + kq, 16);
        }
        __pipeline_commit();
    };

    issue(0, 0);
    for (int kc = 0; kc < 144; kc++) {
        if (kc < 143) {
            issue(kc + 1, (kc + 1) & 1);
            __pipeline_wait_prior(1);
        } else {
            __pipeline_wait_prior(0);
        }
        __syncthreads();
        const uint32_t* sAb = sA0 + (kc & 1) * 3072;
        const float* sBb = sB0 + (kc & 1) * 1536;
        uint32_t ah[4][4], al[4][4];
#pragma unroll
        for (int mf = 0; mf < 4; mf++) {
            int m = wm * 64 + mf * 16 + qr;
            ah[mf][0] = sAb[m * 12 + qc];
            ah[mf][1] = sAb[(m + 8) * 12 + qc];
            ah[mf][2] = sAb[m * 12 + qc + 4];
            ah[mf][3] = sAb[(m + 8) * 12 + qc + 4];
#pragma unroll
            for (int j = 0; j < 4; j++) al[mf][j] = ah[mf][j] & 0x10001000u;
        }
#pragma unroll
        for (int nf = 0; nf < 4; nf++) {
            int nn = wn * 32 + nf * 8 + qr;
            float2 p0 = *(const float2*)(sBb + nn * 24 + 2 * qc);
            float2 p1 = *(const float2*)(sBb + nn * 24 + 2 * qc + 8);
            __half2 h0 = __float22half2_rn(p0);
            __half2 h1 = __float22half2_rn(p1);
            float2 h0f = __half22float2(h0);
            float2 h1f = __half22float2(h1);
            __half2 l0 = __float22half2_rn(
                make_float2((p0.x - h0f.x) * 2048.0f, (p0.y - h0f.y) * 2048.0f));
            __half2 l1 = __float22half2_rn(
                make_float2((p1.x - h1f.x) * 2048.0f, (p1.y - h1f.y) * 2048.0f));
            uint32_t bh0 = *(uint32_t*)&h0, bh1 = *(uint32_t*)&h1;
            uint32_t bl0 = *(uint32_t*)&l0, bl1 = *(uint32_t*)&l1;
#pragma unroll
            for (int mf = 0; mf < 4; mf++) {
                mma_f16(acc[mf][nf], ah[mf], bh0, bh1);
                mma_f16(acc[mf][nf], al[mf], bl0, bl1);
            }
        }
        __syncthreads();
    }

    float* op = g_y1p + z * 294912;
#pragma unroll
    for (int mf = 0; mf < 4; mf++) {
        int m = wm * 64 + mf * 16 + qr;
#pragma unroll
        for (int nf = 0; nf < 4; nf++) {
            int nn = n0 + wn * 32 + nf * 8 + qc * 2;
            op[m * 1152 + nn]           = acc[mf][nf][0];
            op[m * 1152 + nn + 1]       = acc[mf][nf][1];
            op[(m + 8) * 1152 + nn]     = acc[mf][nf][2];
            op[(m + 8) * 1152 + nn + 1] = acc[mf][nf][3];
        }
    }
}

// ---------------- K6: reduce split-K(8) + bias + LIF1 ----------------
__global__ __launch_bounds__(256) void k6_lif1(const float* __restrict__ bias)
{
    int idx = blockIdx.x * 256 + threadIdx.x;  // 36,864 exact
    int o = idx % 1152, b = idx / 1152;
    float bi = bias[o];
    float v = 0.f;
#pragma unroll
    for (int t = 0; t < 8; t++) {
        int row = (t * 32 + b) * 1152 + o;
        float xx = bi;
#pragma unroll
        for (int z = 0; z < 8; z++) xx += g_y1p[z * 294912 + row];
        v += (xx - v) * 0.5f;
        float s = v >= 1.f ? 1.f : 0.f;
        g_l1[row] = s;
        v = v >= 1.f ? 0.f : v;
    }
}

// ---------------- K7: fc2 ----------------
__global__ __launch_bounds__(128) void k7_fc2(const float* __restrict__ w,
                                              const float* __restrict__ bias)
{
    __shared__ float row[1152];
    int r = blockIdx.x, o = threadIdx.x;
    for (int i = o; i < 1152; i += 128) row[i] = g_l1[r * 1152 + i];
    __syncthreads();
    const float4* wp = (const float4*)(w + o * 1152);
    float acc = 0.f;
#pragma unroll 4
    for (int k = 0; k < 288; k++) {
        float4 wv = wp[k];
        acc += row[4 * k] * wv.x + row[4 * k + 1] * wv.y
             + row[4 * k + 2] * wv.z + row[4 * k + 3] * wv.w;
    }
    g_y2[r * 128 + o] = acc + bias[o];
}

// ---------------- K8: LIF2 ----------------
__global__ __launch_bounds__(256) void k8_lif2()
{
    int idx = blockIdx.x * 256 + threadIdx.x;  // 4096 exact
    int o = idx & 127, b = idx >> 7;
    float v = 0.f;
#pragma unroll
    for (int t = 0; t < 8; t++) {
        int row = (t * 32 + b) * 128 + o;
        float xx = g_y2[row];
        v += (xx - v) * 0.5f;
        float s = v >= 1.f ? 1.f : 0.f;
        g_l2[row] = s;
        v = v >= 1.f ? 0.f : v;
    }
}

// ---------------- K9: fc3 + LIF3 + mean over T ----------------
__global__ __launch_bounds__(256) void k9_fc3(const float* __restrict__ w,
                                              const float* __restrict__ bias,
                                              float* __restrict__ out)
{
    int idx = threadIdx.x;
    if (idx >= 224) return;
    int o = idx % 7, b = idx / 7;
    const float4* wp = (const float4*)(w + o * 128);
    float v = 0.f, accm = 0.f;
    float bi = bias[o];
    for (int t = 0; t < 8; t++) {
        const float4* lp = (const float4*)(g_l2 + (t * 32 + b) * 128);
        float y = 0.f;
#pragma unroll
        for (int k = 0; k < 32; k++) {
            float4 a = lp[k], ww = wp[k];
            y += a.x * ww.x + a.y * ww.y + a.z * ww.z + a.w * ww.w;
        }
        y += bi;
        v += (y - v) * 0.5f;
        float s = v >= 1.f ? 1.f : 0.f;
        accm += s;
        v = v >= 1.f ? 0.f : v;
    }
    out[b * 7 + o] = accm * 0.125f;
}

// ---------------- launch ----------------
#define K3_SMEM ((4160 + 19584 + 128) * 4)   // 95488 B
#define K5_SMEM ((2 * 3072 + 2 * 1536) * 4)  // 36864 B

extern "C" void kernel_launch(void* const* d_in, const int* in_sizes, int n_in,
                              void* d_out, int out_size)
{
    const float* x       = (const float*)d_in[0];
    const float* conv1_w = (const float*)d_in[1];
    const float* conv1_b = (const float*)d_in[2];
    const float* bn1_g   = (const float*)d_in[3];
    const float* bn1_b   = (const float*)d_in[4];
    const float* bn1_m   = (const float*)d_in[5];
    const float* bn1_v   = (const float*)d_in[6];
    const float* conv2_w = (const float*)d_in[7];
    const float* conv2_b = (const float*)d_in[8];
    const float* bn2_g   = (const float*)d_in[9];
    const float* bn2_b   = (const float*)d_in[10];
    const float* bn2_m   = (const float*)d_in[11];
    const float* bn2_v   = (const float*)d_in[12];
    const float* fc1_w   = (const float*)d_in[13];
    const float* fc1_b   = (const float*)d_in[14];
    const float* fc2_w   = (const float*)d_in[15];
    const float* fc2_b   = (const float*)d_in[16];
    const float* fc3_w   = (const float*)d_in[17];
    const float* fc3_b   = (const float*)d_in[18];

    static bool attr_done = false;
    if (!attr_done) {
        cudaFuncSetAttribute(k3_conv2_mma,
                             cudaFuncAttributeMaxDynamicSharedMemorySize, K3_SMEM);
        cudaFuncSetAttribute(k3_conv2_mma,
                             cudaFuncAttributePreferredSharedMemoryCarveout, 100);
        cudaFuncSetAttribute(k5_fc1_mma,
                             cudaFuncAttributeMaxDynamicSharedMemorySize, K5_SMEM);
        cudaFuncSetAttribute(k5_fc1_mma,
                             cudaFuncAttributePreferredSharedMemoryCarveout, 100);
        attr_done = true;
    }

    // zero padded p1 borders (interior overwritten by K12)
    void* p1ptr = nullptr;
    cudaGetSymbolAddress(&p1ptr, g_p1h);
    cudaMemsetAsync(p1ptr, 0, sizeof(g_p1h));

    k0_split_w2<<<288, 256>>>(conv2_w);
    k12_conv1_if_pool<<<2048, 256>>>(x, conv1_w, conv1_b, bn1_g, bn1_b, bn1_m, bn1_v);
    dim3 g3(NTB, 3, 2);
    k3_conv2_mma<<<g3, 256, K3_SMEM>>>(conv2_b, bn2_g, bn2_b, bn2_m, bn2_v);
    k4_if2_pool<<<1152, 256>>>();
    dim3 g5(18, 8);
    k5_fc1_mma<<<g5, 256, K5_SMEM>>>(fc1_w);
    k6_lif1<<<144, 256>>>(fc1_b);
    k7_fc2<<<NTB, 128>>>(fc2_w, fc2_b);
    k8_lif2<<<16, 256>>>();
    k9_fc3<<<1, 256>>>(fc3_w, fc3_b, (float*)d_out);
}

// round 9
// speedup vs baseline: 5.4014x; 1.1239x over previous
#include <cuda_runtime.h>
#include <cuda_pipeline.h>
#include <cuda_fp16.h>
#include <cstdint>

// SJCSNN spiking CNN forward, T=8, B=32, out [32,7] f32.
// conv2 AND fc1: fp16 mma.m16n8k16, scaled 2-term weight split, single fp32 acc
//   (spikes {0,1} exact in fp16; lo-term A = spikes*2^-11 via bit-mask trick,
//    lo-term B = (w - fp16(w)) * 2^11).
// R9: fc1 split-K=16 (2 CTAs/SM), fc2 blocked rows-in-smem, k3 16B B-staging.

#define NTB 256  // T*B

// ---- scratch (device globals; no allocations) ----
__device__ __align__(16) uint32_t g_p1h[NTB * 64 * 676];   // IF1+pool spikes, fp16 pair-packed, PADDED 26x26
__device__ __align__(16) float g_c2[NTB * 128 * 24 * 24];  // conv2+bn2 output
__device__ __align__(16) uint32_t g_fh[NTB * 9216];        // IF2+pool spikes, fp16 pair-packed flat
__device__ float g_y1p[16 * NTB * 1152];                   // fc1 split-K partials (16)
__device__ __align__(16) float g_l1[NTB * 1152];           // LIF1 spikes
__device__ float g_y2[NTB * 128];                          // fc2 output
__device__ float g_l2[NTB * 128];                          // LIF2 spikes
// conv2 weights fp16 split: [tap(9)][cinpair(64)][cout(128)][hi,lo] as half2 words
__device__ __align__(16) uint32_t g_w2p[9 * 64 * 128 * 2];

// ---------------- mma helper ----------------
__device__ __forceinline__ void mma_f16(float c[4], const uint32_t a[4],
                                        uint32_t b0, uint32_t b1) {
    asm volatile(
        "mma.sync.aligned.m16n8k16.row.col.f32.f16.f16.f32 "
        "{%0,%1,%2,%3}, {%4,%5,%6,%7}, {%8,%9}, {%0,%1,%2,%3};"
        : "+f"(c[0]), "+f"(c[1]), "+f"(c[2]), "+f"(c[3])
        : "r"(a[0]), "r"(a[1]), "r"(a[2]), "r"(a[3]), "r"(b0), "r"(b1));
}

// ---------------- K0: conv2 weight fp16 split, pair-packed ----------------
__global__ __launch_bounds__(256) void k0_split_w2(const float* __restrict__ w2)
{
    int i = blockIdx.x * 256 + threadIdx.x;  // 73728 exact
    int co = i & 127;
    int r = i >> 7;              // tap*64 + p
    int p = r & 63, tap = r >> 6;
    int c0 = 2 * p, c1 = c0 + 1;
    float w0 = w2[co * 1152 + c0 * 9 + tap];
    float w1 = w2[co * 1152 + c1 * 9 + tap];
    __half h0 = __float2half_rn(w0);
    __half h1 = __float2half_rn(w1);
    __half l0 = __float2half_rn((w0 - __half2float(h0)) * 2048.0f);
    __half l1 = __float2half_rn((w1 - __half2float(h1)) * 2048.0f);
    uint32_t whi = (uint32_t)__half_as_ushort(h0) | ((uint32_t)__half_as_ushort(h1) << 16);
    uint32_t wlo = (uint32_t)__half_as_ushort(l0) | ((uint32_t)__half_as_ushort(l1) << 16);
    g_w2p[(r * 128 + co) * 2]     = whi;
    g_w2p[(r * 128 + co) * 2 + 1] = wlo;
}

// ---------------- K12: conv1 (1->128) + BN1 + IF1 + 2x2 maxpool, fused ----------------
__global__ __launch_bounds__(256) void k12_conv1_if_pool(
    const float* __restrict__ x, const float* __restrict__ w,
    const float* __restrict__ cb, const float* __restrict__ bg,
    const float* __restrict__ bb, const float* __restrict__ bm,
    const float* __restrict__ bv)
{
    __shared__ float sx[2500];       // 50x50 padded input
    __shared__ float sh[2][2304];    // h planes for the 2 channels
    int b = blockIdx.x >> 6, pair = blockIdx.x & 63;
    int tid = threadIdx.x;
    for (int i = tid; i < 2500; i += 256) sx[i] = 0.0f;
    __syncthreads();
    const float* xp = x + b * 2304;
    for (int i = tid; i < 2304; i += 256) {
        int r = i / 48, q = i - r * 48;
        sx[(r + 1) * 50 + q + 1] = xp[i];
    }
    __syncthreads();
#pragma unroll
    for (int half = 0; half < 2; half++) {
        int c = 2 * pair + half;
        float wr[9];
#pragma unroll
        for (int k = 0; k < 9; k++) wr[k] = w[c * 9 + k];
        float sc = bg[c] * rsqrtf(bv[c] + 1e-5f);
        float sf = (cb[c] - bm[c]) * sc + bb[c];
        for (int p = tid; p < 2304; p += 256) {
            int y = p / 48, xx = p - y * 48;
            const float* sp = sx + y * 50 + xx;
            float a = sp[0] * wr[0] + sp[1] * wr[1] + sp[2] * wr[2]
                    + sp[50] * wr[3] + sp[51] * wr[4] + sp[52] * wr[5]
                    + sp[100] * wr[6] + sp[101] * wr[7] + sp[102] * wr[8];
            sh[half][p] = a * sc + sf;
        }
    }
    __syncthreads();
    for (int p = tid; p < 576; p += 256) {
        int oy = p / 24, ox = p - oy * 24;
        int base = (2 * oy) * 48 + 2 * ox;
        float a0 = sh[0][base], a1 = sh[0][base + 1], a2 = sh[0][base + 48], a3 = sh[0][base + 49];
        float c0 = sh[1][base], c1 = sh[1][base + 1], c2 = sh[1][base + 48], c3 = sh[1][base + 49];
        float va0 = 0.f, va1 = 0.f, va2 = 0.f, va3 = 0.f;
        float vc0 = 0.f, vc1 = 0.f, vc2 = 0.f, vc3 = 0.f;
        int pin = pair * 676 + (oy + 1) * 26 + ox + 1;
#pragma unroll
        for (int t = 0; t < 8; t++) {
            va0 += a0; va1 += a1; va2 += a2; va3 += a3;
            vc0 += c0; vc1 += c1; vc2 += c2; vc3 += c3;
            bool sa0 = va0 >= 1.f, sa1 = va1 >= 1.f, sa2 = va2 >= 1.f, sa3 = va3 >= 1.f;
            bool sc0 = vc0 >= 1.f, sc1 = vc1 >= 1.f, sc2 = vc2 >= 1.f, sc3 = vc3 >= 1.f;
            va0 = sa0 ? 0.f : va0; va1 = sa1 ? 0.f : va1;
            va2 = sa2 ? 0.f : va2; va3 = sa3 ? 0.f : va3;
            vc0 = sc0 ? 0.f : vc0; vc1 = sc1 ? 0.f : vc1;
            vc2 = sc2 ? 0.f : vc2; vc3 = sc3 ? 0.f : vc3;
            bool m0 = sa0 | sa1 | sa2 | sa3;
            bool m1 = sc0 | sc1 | sc2 | sc3;
            uint32_t word = (m0 ? 0x3C00u : 0u) | (m1 ? 0x3C000000u : 0u);
            g_p1h[(t * 32 + b) * 64 * 676 + pin] = word;
        }
    }
}

// ---------------- K3: conv2 + BN2, fp16 mma m16n8k16, cp.async double-buffered --------
__global__ __launch_bounds__(256, 2) void k3_conv2_mma(
    const float* __restrict__ cb, const float* __restrict__ bg,
    const float* __restrict__ bb, const float* __restrict__ bm,
    const float* __restrict__ bv)
{
    extern __shared__ uint32_t dyn[];
    uint32_t* sA0 = dyn;                       // 2 x 2080 words (8 pair-planes x 260)
    uint32_t* sB0 = dyn + 4160;                // 2 x 9792 words (72 rows x 136)
    float* sSc = (float*)(dyn + 4160 + 19584); // 64
    float* sSh = sSc + 64;                     // 64

    int n = blockIdx.x;
    int y0g = blockIdx.y;              // 0..2  -> rows y0g*8 .. +7
    int coutbase = blockIdx.z * 64;    // 0 or 64
    int tid = threadIdx.x;
    int lane = tid & 31, warp = tid >> 5;
    int wm = warp & 3, wn = warp >> 2; // 4 x 2 warp grid
    int qr = lane >> 2, qc = lane & 3;

    if (tid < 64) {
        int oc = coutbase + tid;
        float sc = bg[oc] * rsqrtf(bv[oc] + 1e-5f);
        sSc[tid] = sc;
        sSh[tid] = (cb[oc] - bm[oc]) * sc + bb[oc];
    }

    int offr[3], offr8[3];
#pragma unroll
    for (int mf = 0; mf < 3; mf++) {
        int p = wm * 48 + mf * 16 + qr;
        offr[mf] = (p / 24) * 26 + (p % 24);
        int p8 = p + 8;
        offr8[mf] = (p8 / 24) * 26 + (p8 % 24);
    }

    float acc[3][4][4];
#pragma unroll
    for (int mf = 0; mf < 3; mf++)
#pragma unroll
        for (int nf = 0; nf < 4; nf++)
#pragma unroll
            for (int i = 0; i < 4; i++) acc[mf][nf][i] = 0.f;

    int y0 = y0g * 8;
    const uint32_t* pbase = g_p1h + n * 64 * 676 + y0 * 26;

    auto issue = [&](int chunk, int buf) {
        uint32_t* sAb = sA0 + buf * 2080;
        uint32_t* sBb = sB0 + buf * 9792;
        int pb = chunk * 8;  // base cin-pair
        for (int i = tid; i < 520; i += 256) {
            int ci = i / 65, q = i - ci * 65;
            __pipeline_memcpy_async(sAb + ci * 260 + q * 4,
                                    pbase + (pb + ci) * 676 + q * 4, 16);
        }
        // B: 72 rows x 32 cout-pairs, 16B each (2 couts = 4 words)
        for (int i = tid; i < 2304; i += 256) {
            int cp2 = i & 31;
            int r = i >> 5;               // tap*8 + pi
            int pi = r & 7, tap = r >> 3;
            __pipeline_memcpy_async(sBb + r * 136 + cp2 * 4,
                                    g_w2p + ((tap * 64 + pb + pi) * 128 + coutbase + cp2 * 2) * 2,
                                    16);
        }
        __pipeline_commit();
    };

    issue(0, 0);
    for (int c = 0; c < 8; c++) {
        if (c < 7) {
            issue(c + 1, (c + 1) & 1);
            __pipeline_wait_prior(1);
        } else {
            __pipeline_wait_prior(0);
        }
        __syncthreads();
        const uint32_t* sAb = sA0 + (c & 1) * 2080;
        const uint32_t* sBb = sB0 + (c & 1) * 9792;
#pragma unroll
        for (int tap = 0; tap < 9; tap++) {
            int toff = (tap / 3) * 26 + (tap % 3);
            uint32_t ah[3][4], al[3][4];
#pragma unroll
            for (int mf = 0; mf < 3; mf++) {
                ah[mf][0] = sAb[qc * 260 + offr[mf] + toff];
                ah[mf][1] = sAb[qc * 260 + offr8[mf] + toff];
                ah[mf][2] = sAb[(qc + 4) * 260 + offr[mf] + toff];
                ah[mf][3] = sAb[(qc + 4) * 260 + offr8[mf] + toff];
#pragma unroll
                for (int j = 0; j < 4; j++) al[mf][j] = ah[mf][j] & 0x10001000u;
            }
#pragma unroll
            for (int nf = 0; nf < 4; nf++) {
                int ncol = wn * 32 + nf * 8 + qr;
                uint2 b0 = *(const uint2*)(sBb + (tap * 8 + qc) * 136 + ncol * 2);
                uint2 b1 = *(const uint2*)(sBb + (tap * 8 + qc + 4) * 136 + ncol * 2);
#pragma unroll
                for (int mf = 0; mf < 3; mf++) {
                    mma_f16(acc[mf][nf], ah[mf], b0.x, b1.x);
                    mma_f16(acc[mf][nf], al[mf], b0.y, b1.y);
                }
            }
        }
        __syncthreads();
    }

    float* op = g_c2 + (n * 128 + coutbase) * 576 + y0g * 192;
#pragma unroll
    for (int mf = 0; mf < 3; mf++) {
        int p = wm * 48 + mf * 16 + qr;
#pragma unroll
        for (int nf = 0; nf < 4; nf++) {
            int L = wn * 32 + nf * 8 + qc * 2;
            float sc0 = sSc[L], sh0 = sSh[L];
            float sc1 = sSc[L + 1], sh1 = sSh[L + 1];
            op[L * 576 + p]           = acc[mf][nf][0] * sc0 + sh0;
            op[(L + 1) * 576 + p]     = acc[mf][nf][1] * sc1 + sh1;
            op[L * 576 + p + 8]       = acc[mf][nf][2] * sc0 + sh0;
            op[(L + 1) * 576 + p + 8] = acc[mf][nf][3] * sc1 + sh1;
        }
    }
}

// ---------------- K4: IF2 + 2x2 maxpool + flatten, fp16 pair-packed output ----------------
__global__ __launch_bounds__(256) void k4_if2_pool()
{
    int idx = blockIdx.x * 256 + threadIdx.x;  // 294,912 exact
    int oxp = idx % 6;
    int t1 = idx / 6;
    int oy = t1 % 12;
    int t2 = t1 / 12;
    int c = t2 & 127;
    int b = t2 >> 7;
    float va0 = 0.f, va1 = 0.f, va2 = 0.f, va3 = 0.f;
    float vc0 = 0.f, vc1 = 0.f, vc2 = 0.f, vc3 = 0.f;
    int fo = c * 72 + oy * 6 + oxp;
#pragma unroll
    for (int t = 0; t < 8; t++) {
        const float* cp = g_c2 + ((t * 32 + b) * 128 + c) * 576 + (2 * oy) * 24 + 4 * oxp;
        float4 r0 = *(const float4*)cp;
        float4 r1 = *(const float4*)(cp + 24);
        va0 += r0.x; va1 += r0.y; va2 += r1.x; va3 += r1.y;
        vc0 += r0.z; vc1 += r0.w; vc2 += r1.z; vc3 += r1.w;
        bool sa0 = va0 >= 1.f, sa1 = va1 >= 1.f, sa2 = va2 >= 1.f, sa3 = va3 >= 1.f;
        bool sc0 = vc0 >= 1.f, sc1 = vc1 >= 1.f, sc2 = vc2 >= 1.f, sc3 = vc3 >= 1.f;
        va0 = sa0 ? 0.f : va0; va1 = sa1 ? 0.f : va1;
        va2 = sa2 ? 0.f : va2; va3 = sa3 ? 0.f : va3;
        vc0 = sc0 ? 0.f : vc0; vc1 = sc1 ? 0.f : vc1;
        vc2 = sc2 ? 0.f : vc2; vc3 = sc3 ? 0.f : vc3;
        bool m0 = sa0 | sa1 | sa2 | sa3;
        bool m1 = sc0 | sc1 | sc2 | sc3;
        uint32_t word = (m0 ? 0x3C00u : 0u) | (m1 ? 0x3C000000u : 0u);
        g_fh[(t * 32 + b) * 9216 + fo] = word;
    }
}

// ---------------- K5: fc1 GEMM, fp16 mma m16n8k16, split-K=16, cp.async ----------------
// C[256,1152] = F[256,18432] * W1[1152,18432]^T. BM=256, BN=64, BK=16(=8 words).
// grid (18, 16) = 288 blocks -> 2 CTAs/SM. fp16 hi/lo split in registers.
__global__ __launch_bounds__(256, 2) void k5_fc1_mma(const float* __restrict__ w1)
{
    extern __shared__ uint32_t dyn5[];
    uint32_t* sA0 = dyn5;                    // 2 x 256*12 words
    float* sB0 = (float*)(dyn5 + 2 * 3072);  // 2 x 64*24 floats

    int n0 = blockIdx.x * 64;
    int z = blockIdx.y;
    int tid = threadIdx.x;
    int lane = tid & 31, warp = tid >> 5;
    int wm = warp & 3, wn = warp >> 2;
    int qr = lane >> 2, qc = lane & 3;

    float acc[4][4][4];
#pragma unroll
    for (int mf = 0; mf < 4; mf++)
#pragma unroll
        for (int nf = 0; nf < 4; nf++)
#pragma unroll
            for (int i = 0; i < 4; i++) acc[mf][nf][i] = 0.f;

    int kbase = z * 1152;

    auto issue = [&](int kc, int buf) {
        int k0 = kbase + kc * 16;
        int kw = k0 >> 1;
        uint32_t* sAb = sA0 + buf * 3072;
        float* sBb = sB0 + buf * 1536;
        for (int v = tid; v < 512; v += 256) {
            int m = v >> 1;
            int hq = (v & 1) * 4;
            __pipeline_memcpy_async(sAb + m * 12 + hq,
                                    g_fh + m * 9216 + kw + hq, 16);
        }
        {
            int nr = tid >> 2;
            int kq = (tid & 3) * 4;
            __pipeline_memcpy_async(sBb + nr * 24 + kq,
                                    w1 + (n0 + nr) * 18432 + k0 + kq, 16);
        }
        __pipeline_commit();
    };

    issue(0, 0);
    for (int kc = 0; kc < 72; kc++) {
        if (kc < 71) {
            issue(kc + 1, (kc + 1) & 1);
            __pipeline_wait_prior(1);
        } else {
            __pipeline_wait_prior(0);
        }
        __syncthreads();
        const uint32_t* sAb = sA0 + (kc & 1) * 3072;
        const float* sBb = sB0 + (kc & 1) * 1536;
        uint32_t ah[4][4], al[4][4];
#pragma unroll
        for (int mf = 0; mf < 4; mf++) {
            int m = wm * 64 + mf * 16 + qr;
            ah[mf][0] = sAb[m * 12 + qc];
            ah[mf][1] = sAb[(m + 8) * 12 + qc];
            ah[mf][2] = sAb[m * 12 + qc + 4];
            ah[mf][3] = sAb[(m + 8) * 12 + qc + 4];
#pragma unroll
            for (int j = 0; j < 4; j++) al[mf][j] = ah[mf][j] & 0x10001000u;
        }
#pragma unroll
        for (int nf = 0; nf < 4; nf++) {
            int nn = wn * 32 + nf * 8 + qr;
            float2 p0 = *(const float2*)(sBb + nn * 24 + 2 * qc);
            float2 p1 = *(const float2*)(sBb + nn * 24 + 2 * qc + 8);
            __half2 h0 = __float22half2_rn(p0);
            __half2 h1 = __float22half2_rn(p1);
            float2 h0f = __half22float2(h0);
            float2 h1f = __half22float2(h1);
            __half2 l0 = __float22half2_rn(
                make_float2((p0.x - h0f.x) * 2048.0f, (p0.y - h0f.y) * 2048.0f));
            __half2 l1 = __float22half2_rn(
                make_float2((p1.x - h1f.x) * 2048.0f, (p1.y - h1f.y) * 2048.0f));
            uint32_t bh0 = *(uint32_t*)&h0, bh1 = *(uint32_t*)&h1;
            uint32_t bl0 = *(uint32_t*)&l0, bl1 = *(uint32_t*)&l1;
#pragma unroll
            for (int mf = 0; mf < 4; mf++) {
                mma_f16(acc[mf][nf], ah[mf], bh0, bh1);
                mma_f16(acc[mf][nf], al[mf], bl0, bl1);
            }
        }
        __syncthreads();
    }

    float* op = g_y1p + z * 294912;
#pragma unroll
    for (int mf = 0; mf < 4; mf++) {
        int m = wm * 64 + mf * 16 + qr;
#pragma unroll
        for (int nf = 0; nf < 4; nf++) {
            int nn = n0 + wn * 32 + nf * 8 + qc * 2;
            op[m * 1152 + nn]           = acc[mf][nf][0];
            op[m * 1152 + nn + 1]       = acc[mf][nf][1];
            op[(m + 8) * 1152 + nn]     = acc[mf][nf][2];
            op[(m + 8) * 1152 + nn + 1] = acc[mf][nf][3];
        }
    }
}

// ---------------- K6: reduce split-K(16) + bias + LIF1 ----------------
__global__ __launch_bounds__(256) void k6_lif1(const float* __restrict__ bias)
{
    int idx = blockIdx.x * 256 + threadIdx.x;  // 36,864 exact
    int o = idx % 1152, b = idx / 1152;
    float bi = bias[o];
    float v = 0.f;
#pragma unroll
    for (int t = 0; t < 8; t++) {
        int row = (t * 32 + b) * 1152 + o;
        float xx = bi;
#pragma unroll
        for (int z = 0; z < 16; z++) xx += g_y1p[z * 294912 + row];
        v += (xx - v) * 0.5f;
        float s = v >= 1.f ? 1.f : 0.f;
        g_l1[row] = s;
        v = v >= 1.f ? 0.f : v;
    }
}

// ---------------- K7: fc2, blocked (4 rows per block, rows in smem) ----------------
__global__ __launch_bounds__(128) void k7_fc2(const float* __restrict__ w,
                                              const float* __restrict__ bias)
{
    __shared__ float srow[4 * 1152];
    int r0 = blockIdx.x * 4;
    int o = threadIdx.x;
    for (int i = o; i < 4608; i += 128) srow[i] = g_l1[r0 * 1152 + i];
    __syncthreads();
    float a0 = 0.f, a1 = 0.f, a2 = 0.f, a3 = 0.f;
    const float4* wp = (const float4*)(w + o * 1152);
#pragma unroll 4
    for (int k = 0; k < 288; k++) {
        float4 wv = wp[k];
        float4 s0 = *(const float4*)&srow[4 * k];
        float4 s1 = *(const float4*)&srow[1152 + 4 * k];
        float4 s2 = *(const float4*)&srow[2304 + 4 * k];
        float4 s3 = *(const float4*)&srow[3456 + 4 * k];
        a0 += s0.x * wv.x + s0.y * wv.y + s0.z * wv.z + s0.w * wv.w;
        a1 += s1.x * wv.x + s1.y * wv.y + s1.z * wv.z + s1.w * wv.w;
        a2 += s2.x * wv.x + s2.y * wv.y + s2.z * wv.z + s2.w * wv.w;
        a3 += s3.x * wv.x + s3.y * wv.y + s3.z * wv.z + s3.w * wv.w;
    }
    float bi = bias[o];
    g_y2[(r0 + 0) * 128 + o] = a0 + bi;
    g_y2[(r0 + 1) * 128 + o] = a1 + bi;
    g_y2[(r0 + 2) * 128 + o] = a2 + bi;
    g_y2[(r0 + 3) * 128 + o] = a3 + bi;
}

// ---------------- K8: LIF2 ----------------
__global__ __launch_bounds__(256) void k8_lif2()
{
    int idx = blockIdx.x * 256 + threadIdx.x;  // 4096 exact
    int o = idx & 127, b = idx >> 7;
    float v = 0.f;
#pragma unroll
    for (int t = 0; t < 8; t++) {
        int row = (t * 32 + b) * 128 + o;
        float xx = g_y2[row];
        v += (xx - v) * 0.5f;
        float s = v >= 1.f ? 1.f : 0.f;
        g_l2[row] = s;
        v = v >= 1.f ? 0.f : v;
    }
}

// ---------------- K9: fc3 + LIF3 + mean over T ----------------
__global__ __launch_bounds__(256) void k9_fc3(const float* __restrict__ w,
                                              const float* __restrict__ bias,
                                              float* __restrict__ out)
{
    int idx = threadIdx.x;
    if (idx >= 224) return;
    int o = idx % 7, b = idx / 7;
    const float4* wp = (const float4*)(w + o * 128);
    float v = 0.f, accm = 0.f;
    float bi = bias[o];
    for (int t = 0; t < 8; t++) {
        const float4* lp = (const float4*)(g_l2 + (t * 32 + b) * 128);
        float y = 0.f;
#pragma unroll
        for (int k = 0; k < 32; k++) {
            float4 a = lp[k], ww = wp[k];
            y += a.x * ww.x + a.y * ww.y + a.z * ww.z + a.w * ww.w;
        }
        y += bi;
        v += (y - v) * 0.5f;
        float s = v >= 1.f ? 1.f : 0.f;
        accm += s;
        v = v >= 1.f ? 0.f : v;
    }
    out[b * 7 + o] = accm * 0.125f;
}

// ---------------- launch ----------------
#define K3_SMEM ((4160 + 19584 + 128) * 4)   // 95488 B
#define K5_SMEM ((2 * 3072 + 2 * 1536) * 4)  // 36864 B

extern "C" void kernel_launch(void* const* d_in, const int* in_sizes, int n_in,
                              void* d_out, int out_size)
{
    const float* x       = (const float*)d_in[0];
    const float* conv1_w = (const float*)d_in[1];
    const float* conv1_b = (const float*)d_in[2];
    const float* bn1_g   = (const float*)d_in[3];
    const float* bn1_b   = (const float*)d_in[4];
    const float* bn1_m   = (const float*)d_in[5];
    const float* bn1_v   = (const float*)d_in[6];
    const float* conv2_w = (const float*)d_in[7];
    const float* conv2_b = (const float*)d_in[8];
    const float* bn2_g   = (const float*)d_in[9];
    const float* bn2_b   = (const float*)d_in[10];
    const float* bn2_m   = (const float*)d_in[11];
    const float* bn2_v   = (const float*)d_in[12];
    const float* fc1_w   = (const float*)d_in[13];
    const float* fc1_b   = (const float*)d_in[14];
    const float* fc2_w   = (const float*)d_in[15];
    const float* fc2_b   = (const float*)d_in[16];
    const float* fc3_w   = (const float*)d_in[17];
    const float* fc3_b   = (const float*)d_in[18];

    static bool attr_done = false;
    if (!attr_done) {
        cudaFuncSetAttribute(k3_conv2_mma,
                             cudaFuncAttributeMaxDynamicSharedMemorySize, K3_SMEM);
        cudaFuncSetAttribute(k3_conv2_mma,
                             cudaFuncAttributePreferredSharedMemoryCarveout, 100);
        cudaFuncSetAttribute(k5_fc1_mma,
                             cudaFuncAttributeMaxDynamicSharedMemorySize, K5_SMEM);
        cudaFuncSetAttribute(k5_fc1_mma,
                             cudaFuncAttributePreferredSharedMemoryCarveout, 100);
        attr_done = true;
    }

    // zero padded p1 borders (interior overwritten by K12)
    void* p1ptr = nullptr;
    cudaGetSymbolAddress(&p1ptr, g_p1h);
    cudaMemsetAsync(p1ptr, 0, sizeof(g_p1h));

    k0_split_w2<<<288, 256>>>(conv2_w);
    k12_conv1_if_pool<<<2048, 256>>>(x, conv1_w, conv1_b, bn1_g, bn1_b, bn1_m, bn1_v);
    dim3 g3(NTB, 3, 2);
    k3_conv2_mma<<<g3, 256, K3_SMEM>>>(conv2_b, bn2_g, bn2_b, bn2_m, bn2_v);
    k4_if2_pool<<<1152, 256>>>();
    dim3 g5(18, 16);
    k5_fc1_mma<<<g5, 256, K5_SMEM>>>(fc1_w);
    k6_lif1<<<144, 256>>>(fc1_b);
    k7_fc2<<<64, 128>>>(fc2_w, fc2_b);
    k8_lif2<<<16, 256>>>();
    k9_fc3<<<1, 256>>>(fc3_w, fc3_b, (float*)d_out);
}